// round 6
// baseline (speedup 1.0000x reference)
#include <cuda_runtime.h>
#include <cuda_bf16.h>
#include <cstdint>
#include <math.h>

// Problem dims
#define BB 2
#define TT 2048
#define HIDN 1024
#define NH 8
#define DKK 128
#define NROWS (BB*TT)      // 4096
#define TCH 128
#define NCHUNK (TT/TCH)    // 16
#define NBH (BB*NH)        // 16

#define SMEM_SWZ(off) ((off) ^ (((off) >> 3) & 0x70))
typedef __nv_bfloat16 bf16;

// -------- fp32 scratch --------
__device__ float g_Q[NROWS*HIDN];
__device__ float g_EK[NROWS*HIDN];     // raw k (from projection)
__device__ float g_V[NROWS*HIDN];
__device__ float g_gate[NROWS*HIDN];
__device__ float g_O[NROWS*HIDN];
__device__ float g_Asum[NBH*NCHUNK*DKK];
__device__ float g_CcT[NBH*NCHUNK*DKK*DKK];   // per-chunk (V^T EK) = Cc^T [dv][dk]
__device__ float g_G1part[4*NROWS*128];       // split-K partials for Wg1
// -------- split-bf16 scratch --------
__device__ bf16 g_xhi[NROWS*HIDN],  g_xlo[NROWS*HIDN];
__device__ bf16 g_Wqhi[HIDN*HIDN],  g_Wqlo[HIDN*HIDN];
__device__ bf16 g_Wkhi[HIDN*HIDN],  g_Wklo[HIDN*HIDN];
__device__ bf16 g_Wvhi[HIDN*HIDN],  g_Wvlo[HIDN*HIDN];
__device__ bf16 g_Wohi[HIDN*HIDN],  g_Wolo[HIDN*HIDN];
__device__ bf16 g_Wg1hi[128*HIDN],  g_Wg1lo[128*HIDN];
__device__ bf16 g_Wg2hi[HIDN*128],  g_Wg2lo[HIDN*128];
__device__ bf16 g_G1hi[NROWS*128],  g_G1lo[NROWS*128];
__device__ bf16 g_Uhi[NROWS*HIDN],  g_Ulo[NROWS*HIDN];
__device__ bf16 g_EKhi[NROWS*HIDN], g_EKlo[NROWS*HIDN];   // exp(k), natural [t, dk]
__device__ bf16 g_EKThi[NBH*DKK*TT], g_EKTlo[NBH*DKK*TT]; // [bh][dk][t]
__device__ bf16 g_QHhi[NROWS*HIDN], g_QHlo[NROWS*HIDN];   // qhat, natural [t, dk]
__device__ bf16 g_VThi[NBH*DKK*TT], g_VTlo[NBH*DKK*TT];   // [bh][dv][t]
__device__ bf16 g_CcThi[NBH*NCHUNK*DKK*DKK], g_CcTlo[NBH*NCHUNK*DKK*DKK]; // excl prefix

// ================= helpers =================
__device__ __forceinline__ uint32_t smem_u32(const void* p) {
    uint32_t a;
    asm("{ .reg .u64 t; cvta.to.shared.u64 t, %1; cvt.u32.u64 %0, t; }" : "=r"(a) : "l"(p));
    return a;
}
__device__ __forceinline__ void ldsm4(uint32_t* r, uint32_t addr) {
    asm volatile("ldmatrix.sync.aligned.m8n8.x4.shared.b16 {%0,%1,%2,%3}, [%4];"
        : "=r"(r[0]), "=r"(r[1]), "=r"(r[2]), "=r"(r[3]) : "r"(addr));
}
__device__ __forceinline__ void mma_bf16(float* d, const uint32_t* a, const uint32_t* b) {
    asm volatile("mma.sync.aligned.m16n8k16.row.col.f32.bf16.bf16.f32 "
        "{%0,%1,%2,%3}, {%4,%5,%6,%7}, {%8,%9}, {%0,%1,%2,%3};"
        : "+f"(d[0]), "+f"(d[1]), "+f"(d[2]), "+f"(d[3])
        : "r"(a[0]), "r"(a[1]), "r"(a[2]), "r"(a[3]), "r"(b[0]), "r"(b[1]));
}
#define CP_ASYNC16(dst, src) \
    asm volatile("cp.async.cg.shared.global [%0], [%1], 16;" :: "r"(dst), "l"(src) : "memory")
#define CP_COMMIT() asm volatile("cp.async.commit_group;" ::: "memory")
#define CP_WAIT2()  asm volatile("cp.async.wait_group 2;" ::: "memory")
#define CP_WAIT0()  asm volatile("cp.async.wait_group 0;" ::: "memory")

__device__ __forceinline__ void split2(float v0, float v1, uint32_t& h, uint32_t& lo) {
    bf16 h0 = __float2bfloat16_rn(v0), h1 = __float2bfloat16_rn(v1);
    bf16 l0 = __float2bfloat16_rn(v0 - __bfloat162float(h0));
    bf16 l1 = __float2bfloat16_rn(v1 - __bfloat162float(h1));
    __nv_bfloat162 hp = __halves2bfloat162(h0, h1);
    __nv_bfloat162 lp = __halves2bfloat162(l0, l1);
    h = *(uint32_t*)&hp; lo = *(uint32_t*)&lp;
}
__device__ __forceinline__ void store_pair_split(bf16* Chi, bf16* Clo, size_t off,
                                                 float v0, float v1) {
    uint32_t h, lo; split2(v0, v1, h, lo);
    *(uint32_t*)(Chi + off) = h;
    *(uint32_t*)(Clo + off) = lo;
}

// shared 64-K-wide 3-term MMA block (validated fragment mappings)
__device__ __forceinline__ void mma_block64(float acc[2][8][4],
        uint32_t sAhi, uint32_t sAlo, uint32_t sBhi, uint32_t sBlo,
        int a_row, int a_kb, int b_row, int b_kb) {
#pragma unroll
    for (int ks = 0; ks < 4; ks++) {
        const int koff = ks * 32;
        uint32_t Ah[2][4], Al[2][4], Bh[4][4], Bl[4][4];
#pragma unroll
        for (int mf = 0; mf < 2; mf++) {
            uint32_t ro = SMEM_SWZ((uint32_t)((a_row + mf * 16) * 128 + koff + a_kb));
            ldsm4(Ah[mf], sAhi + ro);
            ldsm4(Al[mf], sAlo + ro);
        }
#pragma unroll
        for (int nf2 = 0; nf2 < 4; nf2++) {
            uint32_t ro = SMEM_SWZ((uint32_t)((b_row + nf2 * 16) * 128 + koff + b_kb));
            ldsm4(Bh[nf2], sBhi + ro);
            ldsm4(Bl[nf2], sBlo + ro);
        }
#pragma unroll
        for (int mf = 0; mf < 2; mf++)
#pragma unroll
            for (int nf = 0; nf < 8; nf++) {
                const int nf2 = nf >> 1, ho = (nf & 1) * 2;
                mma_bf16(acc[mf][nf], Ah[mf], &Bh[nf2][ho]);
                mma_bf16(acc[mf][nf], Ah[mf], &Bl[nf2][ho]);
                mma_bf16(acc[mf][nf], Al[mf], &Bh[nf2][ho]);
            }
    }
}

// ================ merged split conversion (all weights + x) ================
__global__ __launch_bounds__(256)
void convert_all(const float* __restrict__ x,  const float* __restrict__ Wq,
                 const float* __restrict__ Wk, const float* __restrict__ Wv,
                 const float* __restrict__ Wo, const float* __restrict__ Wg1,
                 const float* __restrict__ Wg2) {
    int bx = blockIdx.x;
    const float* src; bf16 *hi, *lo; int lb;
    if      (bx < 4096) { src = x;   hi = g_xhi;   lo = g_xlo;   lb = bx; }
    else if (bx < 5120) { src = Wq;  hi = g_Wqhi;  lo = g_Wqlo;  lb = bx - 4096; }
    else if (bx < 6144) { src = Wk;  hi = g_Wkhi;  lo = g_Wklo;  lb = bx - 5120; }
    else if (bx < 7168) { src = Wv;  hi = g_Wvhi;  lo = g_Wvlo;  lb = bx - 6144; }
    else if (bx < 8192) { src = Wo;  hi = g_Wohi;  lo = g_Wolo;  lb = bx - 7168; }
    else if (bx < 8320) { src = Wg1; hi = g_Wg1hi; lo = g_Wg1lo; lb = bx - 8192; }
    else                { src = Wg2; hi = g_Wg2hi; lo = g_Wg2lo; lb = bx - 8320; }
    int i = (lb * 256 + threadIdx.x) * 4;
    float4 v = *(const float4*)(src + i);
    uint32_t h0, l0, h1, l1;
    split2(v.x, v.y, h0, l0);
    split2(v.z, v.w, h1, l1);
    uint2 hu; hu.x = h0; hu.y = h1;
    uint2 lu; lu.x = l0; lu.y = l1;
    *(uint2*)(hi + i) = hu;
    *(uint2*)(lo + i) = lu;
}

// ============ cp.async tensor-core GEMM: C[M,N] = A[M,K] B[N,K]^T ============
#define TLA_HI 0
#define TLA_LO 16384
#define TLB_HI 32768
#define TLB_LO 49152
#define STG_STRIDE 65536
#define NSTAGE 3
#define GEMM_SMEM (NSTAGE*STG_STRIDE + 1024)

__device__ __forceinline__ void issue_stage(uint32_t sa,
        const bf16* __restrict__ Ahi, const bf16* __restrict__ Alo,
        const bf16* __restrict__ Bhi, const bf16* __restrict__ Blo,
        int rowA, int rowB, int Kstride, int k0, int tid) {
#pragma unroll
    for (int t = 0; t < 16; t++) {
        const int tile = t >> 2;
        int idx = t * 256 + tid;
        int r = (idx >> 3) & 127;
        int c16 = idx & 7;
        const bf16* base = (tile == 0) ? Ahi : (tile == 1) ? Alo : (tile == 2) ? Bhi : Blo;
        int rowg = ((tile < 2) ? rowA : rowB) + r;
        const void* src = base + (size_t)rowg * Kstride + k0 + c16 * 8;
        uint32_t dst = sa + tile * 16384 + SMEM_SWZ((uint32_t)(r * 128 + c16 * 16));
        CP_ASYNC16(dst, src);
    }
}

__device__ __forceinline__ void gemm_core(
        const bf16* __restrict__ Ahi, const bf16* __restrict__ Alo,
        const bf16* __restrict__ Bhi, const bf16* __restrict__ Blo,
        float* __restrict__ C, bf16* __restrict__ Chi, bf16* __restrict__ Clo,
        int N, int Kloop, int Kstride, int rowA, int rowB, int act, int outsplit) {
    extern __shared__ char dynsm[];
    char* tile = (char*)((((uintptr_t)dynsm) + 1023) & ~(uintptr_t)1023);
    const uint32_t sa0 = smem_u32(tile);
    const int tid = threadIdx.x;
    const int wid = tid >> 5, l = tid & 31;
    const int warp_m = wid >> 1, warp_n = wid & 1;

    float acc[2][8][4];
#pragma unroll
    for (int mf = 0; mf < 2; mf++)
#pragma unroll
        for (int nf = 0; nf < 8; nf++)
#pragma unroll
            for (int j = 0; j < 4; j++) acc[mf][nf][j] = 0.f;

    const int a_row = warp_m * 32 + (l & 15);
    const int a_kb  = (l >> 4) * 16;
    const int b_row = warp_n * 64 + (l & 7) + ((l >> 4) & 1) * 8;
    const int b_kb  = ((l >> 3) & 1) * 16;

    const int nk = Kloop >> 6;
#pragma unroll
    for (int s = 0; s < NSTAGE; s++) {
        if (s < nk) issue_stage(sa0 + s * STG_STRIDE, Ahi, Alo, Bhi, Blo, rowA, rowB, Kstride, s << 6, tid);
        CP_COMMIT();
    }
    int sidx = 0;
    for (int kb = 0; kb < nk; kb++) {
        CP_WAIT2();
        __syncthreads();
        const uint32_t st = sa0 + sidx * STG_STRIDE;
        mma_block64(acc, st + TLA_HI, st + TLA_LO, st + TLB_HI, st + TLB_LO,
                    a_row, a_kb, b_row, b_kb);
        __syncthreads();
        if (kb + NSTAGE < nk)
            issue_stage(sa0 + sidx * STG_STRIDE, Ahi, Alo, Bhi, Blo, rowA, rowB, Kstride, (kb + NSTAGE) << 6, tid);
        CP_COMMIT();
        sidx = (sidx + 1 == NSTAGE) ? 0 : sidx + 1;
    }

#pragma unroll
    for (int mf = 0; mf < 2; mf++)
#pragma unroll
        for (int nf = 0; nf < 8; nf++) {
            int r0 = rowA + warp_m * 32 + mf * 16 + (l >> 2);
            int cc = rowB + warp_n * 64 + nf * 8 + (l & 3) * 2;
            float v0 = acc[mf][nf][0], v1 = acc[mf][nf][1];
            float v2 = acc[mf][nf][2], v3 = acc[mf][nf][3];
            if (act) {
                v0 = v0 / (1.f + expf(-v0));
                v1 = v1 / (1.f + expf(-v1));
                v2 = v2 / (1.f + expf(-v2));
                v3 = v3 / (1.f + expf(-v3));
            }
            if (!outsplit) {
                *(float2*)(C + (size_t)r0 * N + cc)       = make_float2(v0, v1);
                *(float2*)(C + (size_t)(r0 + 8) * N + cc) = make_float2(v2, v3);
            } else {
                store_pair_split(Chi, Clo, (size_t)r0 * N + cc, v0, v1);
                store_pair_split(Chi, Clo, (size_t)(r0 + 8) * N + cc, v2, v3);
            }
        }
}

template<int ACT, int OSPLIT>
__global__ __launch_bounds__(256, 1)
void gemm_bf16(const bf16* Ahi, const bf16* Alo, const bf16* Bhi, const bf16* Blo,
               float* C, bf16* Chi, bf16* Clo, int N, int K) {
    gemm_core(Ahi, Alo, Bhi, Blo, C, Chi, Clo, N, K, K,
              blockIdx.y * 128, blockIdx.x * 128, ACT, OSPLIT);
}

// fused Q/K/V projection: grid (24, 32); which = bx>>3
__global__ __launch_bounds__(256, 1)
void gemm_qkv() {
    const int which = blockIdx.x >> 3;
    const int colb = blockIdx.x & 7;
    const bf16 *Bh, *Bl;
    float* C;
    if (which == 0)      { Bh = g_Wqhi; Bl = g_Wqlo; C = g_Q; }
    else if (which == 1) { Bh = g_Wkhi; Bl = g_Wklo; C = g_EK; }
    else                 { Bh = g_Wvhi; Bl = g_Wvlo; C = g_V; }
    gemm_core(g_xhi, g_xlo, Bh, Bl, C, nullptr, nullptr, HIDN, HIDN, HIDN,
              blockIdx.y * 128, colb * 128, which == 0, 0);
}

// split-K Wg1: grid (4, 32); each CTA does K range [bx*256, +256)
__global__ __launch_bounds__(256, 1)
void gemm_wg1_split() {
    const int ks = blockIdx.x;
    gemm_core(g_xhi + ks * 256, g_xlo + ks * 256,
              g_Wg1hi + ks * 256, g_Wg1lo + ks * 256,
              g_G1part + (size_t)ks * NROWS * 128, nullptr, nullptr,
              128, 256, HIDN, blockIdx.y * 128, 0, 0, 0);
}

__global__ __launch_bounds__(256)
void g1_reduce() {
    int i = (blockIdx.x * 256 + threadIdx.x) * 4;   // over NROWS*128
    const int S = NROWS * 128;
    float4 a = *(float4*)(g_G1part + i);
    float4 b = *(float4*)(g_G1part + S + i);
    float4 c = *(float4*)(g_G1part + 2*S + i);
    float4 d = *(float4*)(g_G1part + 3*S + i);
    float v0 = a.x + b.x + c.x + d.x;
    float v1 = a.y + b.y + c.y + d.y;
    float v2 = a.z + b.z + c.z + d.z;
    float v3 = a.w + b.w + c.w + d.w;
    uint32_t h0, l0, h1, l1;
    split2(v0, v1, h0, l0);
    split2(v2, v3, h1, l1);
    uint2 hu; hu.x = h0; hu.y = h1;
    uint2 lu; lu.x = l0; lu.y = l1;
    *(uint2*)(g_G1hi + i) = hu;
    *(uint2*)(g_G1lo + i) = lu;
}

// ================ transpose V -> split bf16 VT[bh][dv][t] ================
__global__ __launch_bounds__(256)
void transpose_v() {
    __shared__ float tile[32][33];
    const int ttile = blockIdx.x;            // 0..63
    const int dvt = blockIdx.y & 3, bh = blockIdx.y >> 2;
    const int b = bh >> 3, h = bh & 7;
    const int t0 = ttile * 32, dv0 = dvt * 32;
    const int lx = threadIdx.x & 31, ly = threadIdx.x >> 5;
#pragma unroll
    for (int i = 0; i < 4; i++) {
        int r = ly + i * 8;
        tile[r][lx] = g_V[(size_t)(b * TT + t0 + r) * HIDN + h * DKK + dv0 + lx];
    }
    __syncthreads();
#pragma unroll
    for (int i = 0; i < 4; i++) {
        int r = ly + i * 8;
        float v = tile[lx][r];
        bf16 hh = __float2bfloat16_rn(v);
        bf16 ll = __float2bfloat16_rn(v - __bfloat162float(hh));
        size_t oa = ((size_t)bh * DKK + dv0 + r) * TT + t0 + lx;
        g_VThi[oa] = hh;
        g_VTlo[oa] = ll;
    }
}

// ====== ek_prep: exp(k) -> split natural + split transposed + colsum ======
#define EKP_SMEM (128*136*4 + 256*4 + 64)
__global__ __launch_bounds__(256, 1)
void ek_prep() {
    extern __shared__ float sm[];
    float* red = sm + 128*136;
    const int c = blockIdx.x, bh = blockIdx.y;
    const int b = bh >> 3, h = bh & 7;
    const int base = b*TT + c*TCH;
    const int hoff = h*DKK;
    const int tid = threadIdx.x;
#pragma unroll
    for (int it = 0; it < 16; it++) {
        int idx = it * 256 + tid;
        int r = idx >> 5;
        int c4 = (idx & 31) << 2;
        size_t gi = (size_t)(base + r) * HIDN + hoff + c4;
        float4 kv = *(const float4*)(g_EK + gi);
        kv.x = expf(kv.x); kv.y = expf(kv.y); kv.z = expf(kv.z); kv.w = expf(kv.w);
        uint32_t h0, l0, h1, l1;
        split2(kv.x, kv.y, h0, l0);
        split2(kv.z, kv.w, h1, l1);
        uint2 hu; hu.x = h0; hu.y = h1;
        uint2 lu; lu.x = l0; lu.y = l1;
        *(uint2*)(g_EKhi + gi) = hu;
        *(uint2*)(g_EKlo + gi) = lu;
        sm[r*136 + c4 + 0] = kv.x; sm[r*136 + c4 + 1] = kv.y;
        sm[r*136 + c4 + 2] = kv.z; sm[r*136 + c4 + 3] = kv.w;
    }
    __syncthreads();
    {   // colsum over t
        int dk = tid & 127, half = tid >> 7;
        float s = 0.f;
#pragma unroll 8
        for (int t = half*64; t < half*64 + 64; t++) s += sm[t*136 + dk];
        red[tid] = s;
    }
    __syncthreads();
    if (tid < 128) g_Asum[(bh*NCHUNK + c)*DKK + tid] = red[tid] + red[tid + 128];
    // transposed write EKT[bh][dk][t]
#pragma unroll
    for (int it = 0; it < 16; it++) {
        int idx = it * 256 + tid;
        int dk = idx >> 5;
        int t4 = (idx & 31) << 2;
        float v0 = sm[(t4+0)*136 + dk], v1 = sm[(t4+1)*136 + dk];
        float v2 = sm[(t4+2)*136 + dk], v3 = sm[(t4+3)*136 + dk];
        uint32_t h0, l0, h1, l1;
        split2(v0, v1, h0, l0);
        split2(v2, v3, h1, l1);
        uint2 hu; hu.x = h0; hu.y = h1;
        uint2 lu; lu.x = l0; lu.y = l1;
        size_t oa = ((size_t)bh*DKK + dk)*TT + c*TCH + t4;
        *(uint2*)(g_EKThi + oa) = hu;
        *(uint2*)(g_EKTlo + oa) = lu;
    }
}

// generic 128x128 operand loader into hi/lo smem (two 16KB K-halves each)
__device__ __forceinline__ void load_op(uint32_t shi, uint32_t slo,
        const bf16* __restrict__ ghi, const bf16* __restrict__ glo,
        size_t rstride, int tid) {
#pragma unroll
    for (int t = 0; t < 8; t++) {
        int idx = t * 256 + tid;
        int r = idx >> 4;
        int c16 = idx & 15;
        uint32_t off = (uint32_t)((c16 >> 3) * 16384) + SMEM_SWZ((uint32_t)(r * 128 + (c16 & 7) * 16));
        CP_ASYNC16(shi + off, ghi + (size_t)r * rstride + c16 * 8);
        CP_ASYNC16(slo + off, glo + (size_t)r * rstride + c16 * 8);
    }
}

// ====== chunk_cct_tc: CcT[dv][dk] = sum_t VT[dv,t] * EKT[dk,t] (fp32 out) ======
#define CCT_SMEM (4*32768 + 1024)
__global__ __launch_bounds__(256, 1)
void chunk_cct_tc() {
    extern __shared__ char dynsm[];
    char* smb = (char*)((((uintptr_t)dynsm) + 1023) & ~(uintptr_t)1023);
    const uint32_t sa = smem_u32(smb);
    const int c = blockIdx.x, bh = blockIdx.y;
    const int tid = threadIdx.x, wid = tid >> 5, l = tid & 31;
    const int warp_m = wid >> 1, warp_n = wid & 1;
    const int a_row = warp_m * 32 + (l & 15);
    const int a_kb  = (l >> 4) * 16;
    const int b_row = warp_n * 64 + (l & 7) + ((l >> 4) & 1) * 8;
    const int b_kb  = ((l >> 3) & 1) * 16;
    const uint32_t AHI = sa, ALO = sa + 32768, BHI = sa + 65536, BLO = sa + 98304;

    size_t vb = (size_t)bh * DKK * TT + c * TCH;
    load_op(AHI, ALO, g_VThi + vb, g_VTlo + vb, TT, tid);
    load_op(BHI, BLO, g_EKThi + vb, g_EKTlo + vb, TT, tid);
    CP_COMMIT(); CP_WAIT0(); __syncthreads();

    float acc[2][8][4];
#pragma unroll
    for (int mf = 0; mf < 2; mf++)
#pragma unroll
        for (int nf = 0; nf < 8; nf++)
#pragma unroll
            for (int j = 0; j < 4; j++) acc[mf][nf][j] = 0.f;
#pragma unroll
    for (int kc = 0; kc < 2; kc++)
        mma_block64(acc, AHI + kc*16384, ALO + kc*16384, BHI + kc*16384, BLO + kc*16384,
                    a_row, a_kb, b_row, b_kb);

    size_t cb = (size_t)(bh*NCHUNK + c) * DKK * DKK;
#pragma unroll
    for (int mf = 0; mf < 2; mf++)
#pragma unroll
        for (int nf = 0; nf < 8; nf++) {
            int r0 = warp_m * 32 + mf * 16 + (l >> 2);
            int cc = warp_n * 64 + nf * 8 + (l & 3) * 2;
            *(float2*)(g_CcT + cb + (size_t)r0 * DKK + cc) = make_float2(acc[mf][nf][0], acc[mf][nf][1]);
            *(float2*)(g_CcT + cb + (size_t)(r0+8) * DKK + cc) = make_float2(acc[mf][nf][2], acc[mf][nf][3]);
        }
}

__global__ void scan_asum() {
    int bh = blockIdx.x, dk = threadIdx.x;
    float run = 0.f;
    for (int c = 0; c < NCHUNK; c++) {
        int i = (bh*NCHUNK + c)*DKK + dk;
        float v = g_Asum[i]; g_Asum[i] = run; run += v;
    }
}
// exclusive prefix of CcT across chunks -> split bf16
__global__ void scan_cc() {
    int bh = blockIdx.y;
    int idx = blockIdx.x*256 + threadIdx.x;
    float run = 0.f;
    for (int c = 0; c < NCHUNK; c++) {
        size_t p = ((size_t)(bh*NCHUNK + c))*(DKK*DKK) + idx;
        float v = g_CcT[p];
        bf16 hh = __float2bfloat16_rn(run);
        bf16 ll = __float2bfloat16_rn(run - __bfloat162float(hh));
        g_CcThi[p] = hh; g_CcTlo[p] = ll;
        run += v;
    }
}

// Qhat = silu(q)/A_t * scale -> split bf16 (EK reconstructed from hi+lo)
__global__ void compute_qhat() {
    const int c = blockIdx.x, bh = blockIdx.y;
    const int b = bh >> 3, h = bh & 7;
    const int base = b*TT + c*TCH;
    const int dk = threadIdx.x;
    const float scale = 0.08838834764831845f;
    float run = g_Asum[(bh*NCHUNK + c)*DKK + dk];
    for (int t = 0; t < TCH; t++) {
        size_t gi = (size_t)(base + t)*HIDN + h*DKK + dk;
        run += __bfloat162float(g_EKhi[gi]) + __bfloat162float(g_EKlo[gi]);
        float qh = g_Q[gi] / run * scale;
        bf16 hh = __float2bfloat16_rn(qh);
        bf16 ll = __float2bfloat16_rn(qh - __bfloat162float(hh));
        g_QHhi[gi] = hh; g_QHlo[gi] = ll;
    }
}

// ====== chunk_out (tensor core): O = tril(QH EK^T) V + QH Cc ======
#define CO2_SMEM (6*32768 + 1024)
__global__ __launch_bounds__(256, 1)
void chunk_out_tc() {
    extern __shared__ char dynsm[];
    char* smb = (char*)((((uintptr_t)dynsm) + 1023) & ~(uintptr_t)1023);
    const uint32_t sa = smem_u32(smb);
    const int c = blockIdx.x, bh = blockIdx.y;
    const int b = bh >> 3, h = bh & 7;
    const int tbase = b*TT + c*TCH;
    const int hoff = h*DKK;
    const int tid = threadIdx.x, wid = tid >> 5, l = tid & 31;
    const int warp_m = wid >> 1, warp_n = wid & 1;
    const int a_row = warp_m * 32 + (l & 15);
    const int a_kb  = (l >> 4) * 16;
    const int b_row = warp_n * 64 + (l & 7) + ((l >> 4) & 1) * 8;
    const int b_kb  = ((l >> 3) & 1) * 16;

    const uint32_t QHI = sa, QLO = sa + 32768;
    const uint32_t BHI = sa + 65536, BLO = sa + 98304;
    const uint32_t PHI = sa + 131072, PLO = sa + 163840;
    char* Pc_hi = smb + 131072;
    char* Pc_lo = smb + 163840;

    load_op(QHI, QLO, g_QHhi + (size_t)tbase*HIDN + hoff, g_QHlo + (size_t)tbase*HIDN + hoff, HIDN, tid);
    load_op(BHI, BLO, g_EKhi + (size_t)tbase*HIDN + hoff, g_EKlo + (size_t)tbase*HIDN + hoff, HIDN, tid);
    CP_COMMIT(); CP_WAIT0(); __syncthreads();

    float acc[2][8][4];
#pragma unroll
    for (int mf = 0; mf < 2; mf++)
#pragma unroll
        for (int nf = 0; nf < 8; nf++)
#pragma unroll
            for (int j = 0; j < 4; j++) acc[mf][nf][j] = 0.f;

    // stage 1: P = QH * EK^T
#pragma unroll
    for (int kc = 0; kc < 2; kc++)
        mma_block64(acc, QHI + kc*16384, QLO + kc*16384, BHI + kc*16384, BLO + kc*16384,
                    a_row, a_kb, b_row, b_kb);
    __syncthreads();

    load_op(BHI, BLO, g_CcThi + (size_t)(bh*NCHUNK + c)*(DKK*DKK),
                       g_CcTlo + (size_t)(bh*NCHUNK + c)*(DKK*DKK), DKK, tid);
    CP_COMMIT();

    // causal mask + store P to smem (split bf16)
#pragma unroll
    for (int mf = 0; mf < 2; mf++)
#pragma unroll
        for (int nf = 0; nf < 8; nf++) {
            int r0 = warp_m * 32 + mf * 16 + (l >> 2);
            int cc = warp_n * 64 + nf * 8 + (l & 3) * 2;
            float v0 = (cc     <= r0) ? acc[mf][nf][0] : 0.f;
            float v1 = (cc + 1 <= r0) ? acc[mf][nf][1] : 0.f;
            float v2 = (cc     <= r0 + 8) ? acc[mf][nf][2] : 0.f;
            float v3 = (cc + 1 <= r0 + 8) ? acc[mf][nf][3] : 0.f;
            uint32_t ch = (uint32_t)((cc >> 6) * 16384);
            uint32_t o0 = ch + SMEM_SWZ((uint32_t)(r0 * 128 + (cc & 63) * 2));
            uint32_t o1 = ch + SMEM_SWZ((uint32_t)((r0 + 8) * 128 + (cc & 63) * 2));
            uint32_t hh, ll;
            split2(v0, v1, hh, ll);
            *(uint32_t*)(Pc_hi + o0) = hh; *(uint32_t*)(Pc_lo + o0) = ll;
            split2(v2, v3, hh, ll);
            *(uint32_t*)(Pc_hi + o1) = hh; *(uint32_t*)(Pc_lo + o1) = ll;
        }
    CP_WAIT0(); __syncthreads();

    // stage 2b: O = QH * CcT^T
#pragma unroll
    for (int mf = 0; mf < 2; mf++)
#pragma unroll
        for (int nf = 0; nf < 8; nf++)
#pragma unroll
            for (int j = 0; j < 4; j++) acc[mf][nf][j] = 0.f;
#pragma unroll
    for (int kc = 0; kc < 2; kc++)
        mma_block64(acc, QHI + kc*16384, QLO + kc*16384, BHI + kc*16384, BLO + kc*16384,
                    a_row, a_kb, b_row, b_kb);
    __syncthreads();

    load_op(QHI, QLO, g_VThi + (size_t)bh*DKK*TT + c*TCH,
                       g_VTlo + (size_t)bh*DKK*TT + c*TCH, TT, tid);
    CP_COMMIT(); CP_WAIT0(); __syncthreads();

    // stage 2a: O += P * VT^T
#pragma unroll
    for (int kc = 0; kc < 2; kc++)
        mma_block64(acc, PHI + kc*16384, PLO + kc*16384, QHI + kc*16384, QLO + kc*16384,
                    a_row, a_kb, b_row, b_kb);

#pragma unroll
    for (int mf = 0; mf < 2; mf++)
#pragma unroll
        for (int nf = 0; nf < 8; nf++) {
            int r0 = warp_m * 32 + mf * 16 + (l >> 2);
            int cc = warp_n * 64 + nf * 8 + (l & 3) * 2;
            *(float2*)(g_O + (size_t)(tbase + r0) * HIDN + hoff + cc) =
                make_float2(acc[mf][nf][0], acc[mf][nf][1]);
            *(float2*)(g_O + (size_t)(tbase + r0 + 8) * HIDN + hoff + cc) =
                make_float2(acc[mf][nf][2], acc[mf][nf][3]);
        }
}

// epilogue: RMSNorm(o) * w * gate * sigmoid(gate) -> split bf16 U
__global__ __launch_bounds__(256)
void epilogue_k(const float* __restrict__ gnw) {
    __shared__ float red[256];
    const int n = blockIdx.x, tid = threadIdx.x;
    float4 ov = *((const float4*)(g_O + (size_t)n*HIDN) + tid);
    float ss = ov.x*ov.x + ov.y*ov.y + ov.z*ov.z + ov.w*ov.w;
    red[tid] = ss;
    __syncthreads();
    for (int s = 128; s > 0; s >>= 1) {
        if (tid < s) red[tid] += red[tid + s];
        __syncthreads();
    }
    float rms = rsqrtf(red[0] * (1.f/HIDN) + 1e-5f);
    float4 gv = *((const float4*)(g_gate + (size_t)n*HIDN) + tid);
    float4 wv = *((const float4*)gnw + tid);
    float4 u;
    u.x = ov.x*rms*wv.x * gv.x / (1.f + expf(-gv.x));
    u.y = ov.y*rms*wv.y * gv.y / (1.f + expf(-gv.y));
    u.z = ov.z*rms*wv.z * gv.z / (1.f + expf(-gv.z));
    u.w = ov.w*rms*wv.w * gv.w / (1.f + expf(-gv.w));
    size_t off = (size_t)n*HIDN + tid*4;
    store_pair_split(g_Uhi, g_Ulo, off, u.x, u.y);
    store_pair_split(g_Uhi, g_Ulo, off + 2, u.z, u.w);
}

extern "C" void kernel_launch(void* const* d_in, const int* in_sizes, int n_in,
                              void* d_out, int out_size) {
    const float* x   = (const float*)d_in[0];
    const float* Wq  = (const float*)d_in[1];
    const float* Wk  = (const float*)d_in[2];
    const float* Wv  = (const float*)d_in[3];
    const float* Wg1 = (const float*)d_in[4];
    const float* Wg2 = (const float*)d_in[5];
    const float* gnw = (const float*)d_in[6];
    const float* Wo  = (const float*)d_in[7];
    float* out = (float*)d_out;

    bf16 *woh,*wol,*w1h,*w1l,*w2h,*w2l,*g1h,*g1l,*uh,*ul;
    float* gate;
    cudaGetSymbolAddress((void**)&woh, g_Wohi); cudaGetSymbolAddress((void**)&wol, g_Wolo);
    cudaGetSymbolAddress((void**)&w1h, g_Wg1hi); cudaGetSymbolAddress((void**)&w1l, g_Wg1lo);
    cudaGetSymbolAddress((void**)&w2h, g_Wg2hi); cudaGetSymbolAddress((void**)&w2l, g_Wg2lo);
    cudaGetSymbolAddress((void**)&g1h, g_G1hi); cudaGetSymbolAddress((void**)&g1l, g_G1lo);
    cudaGetSymbolAddress((void**)&uh, g_Uhi);   cudaGetSymbolAddress((void**)&ul, g_Ulo);
    cudaGetSymbolAddress((void**)&gate, g_gate);

    cudaFuncSetAttribute(gemm_qkv, cudaFuncAttributeMaxDynamicSharedMemorySize, GEMM_SMEM);
    cudaFuncSetAttribute(gemm_wg1_split, cudaFuncAttributeMaxDynamicSharedMemorySize, GEMM_SMEM);
    cudaFuncSetAttribute(gemm_bf16<0,0>, cudaFuncAttributeMaxDynamicSharedMemorySize, GEMM_SMEM);
    cudaFuncSetAttribute(chunk_out_tc, cudaFuncAttributeMaxDynamicSharedMemorySize, CO2_SMEM);
    cudaFuncSetAttribute(chunk_cct_tc, cudaFuncAttributeMaxDynamicSharedMemorySize, CCT_SMEM);
    cudaFuncSetAttribute(ek_prep, cudaFuncAttributeMaxDynamicSharedMemorySize, EKP_SMEM);

    dim3 blk(256);
    convert_all<<<8448, blk>>>(x, Wq, Wk, Wv, Wo, Wg1, Wg2);
    gemm_qkv<<<dim3(24,32), blk, GEMM_SMEM>>>();
    gemm_wg1_split<<<dim3(4,32), blk, GEMM_SMEM>>>();
    g1_reduce<<<NROWS*128/1024, blk>>>();
    gemm_bf16<0,0><<<dim3(8,32), blk, GEMM_SMEM>>>(g1h, g1l, w2h, w2l, gate, nullptr, nullptr, HIDN, 128);
    transpose_v<<<dim3(64, 4*NBH), blk>>>();
    ek_prep<<<dim3(NCHUNK, NBH), blk, EKP_SMEM>>>();
    chunk_cct_tc<<<dim3(NCHUNK, NBH), blk, CCT_SMEM>>>();
    scan_asum<<<NBH, DKK>>>();
    scan_cc<<<dim3(64, NBH), 256>>>();
    compute_qhat<<<dim3(NCHUNK, NBH), DKK>>>();
    chunk_out_tc<<<dim3(NCHUNK, NBH), blk, CO2_SMEM>>>();
    epilogue_k<<<NROWS, blk>>>(gnw);
    gemm_bf16<0,0><<<dim3(8,32), blk, GEMM_SMEM>>>(uh, ul, woh, wol, out, nullptr, nullptr, HIDN, HIDN);
}

// round 7
// speedup vs baseline: 1.4100x; 1.4100x over previous
#include <cuda_runtime.h>
#include <cuda_bf16.h>
#include <cstdint>
#include <math.h>

// Problem dims
#define BB 2
#define TT 2048
#define HIDN 1024
#define NH 8
#define DKK 128
#define NROWS (BB*TT)      // 4096
#define TCH 128
#define NCHUNK (TT/TCH)    // 16
#define NBH (BB*NH)        // 16

#define SMEM_SWZ(off) ((off) ^ (((off) >> 3) & 0x70))
typedef __nv_bfloat16 bf16;

// -------- fp32 scratch --------
__device__ float g_Q[NROWS*HIDN];
__device__ float g_EK[NROWS*HIDN];     // raw k, then exp(k) in place
__device__ float g_V[NROWS*HIDN];
__device__ float g_gate[NROWS*HIDN];
__device__ float g_O[NROWS*HIDN];
__device__ float g_Asum[NBH*NCHUNK*DKK];
__device__ float g_CcT[NBH*NCHUNK*DKK*DKK];   // per-chunk (V^T EK) = Cc^T [dv][dk]
__device__ float g_G1part[4*NROWS*128];       // split-K partials for Wg1
// -------- split-bf16 scratch --------
__device__ bf16 g_xhi[NROWS*HIDN],  g_xlo[NROWS*HIDN];
__device__ bf16 g_Wqhi[HIDN*HIDN],  g_Wqlo[HIDN*HIDN];
__device__ bf16 g_Wkhi[HIDN*HIDN],  g_Wklo[HIDN*HIDN];
__device__ bf16 g_Wvhi[HIDN*HIDN],  g_Wvlo[HIDN*HIDN];
__device__ bf16 g_Wohi[HIDN*HIDN],  g_Wolo[HIDN*HIDN];
__device__ bf16 g_Wg1hi[128*HIDN],  g_Wg1lo[128*HIDN];
__device__ bf16 g_Wg2hi[HIDN*128],  g_Wg2lo[HIDN*128];
__device__ bf16 g_G1hi[NROWS*128],  g_G1lo[NROWS*128];
__device__ bf16 g_Uhi[NROWS*HIDN],  g_Ulo[NROWS*HIDN];
__device__ bf16 g_EKhi[NROWS*HIDN], g_EKlo[NROWS*HIDN];   // exp(k), natural [t, dk]
__device__ bf16 g_QHhi[NROWS*HIDN], g_QHlo[NROWS*HIDN];   // qhat, natural [t, dk]
__device__ bf16 g_VThi[NBH*DKK*TT], g_VTlo[NBH*DKK*TT];   // [bh][dv][t]
__device__ bf16 g_CcThi[NBH*NCHUNK*DKK*DKK], g_CcTlo[NBH*NCHUNK*DKK*DKK]; // excl prefix

// ================= helpers =================
__device__ __forceinline__ uint32_t smem_u32(const void* p) {
    uint32_t a;
    asm("{ .reg .u64 t; cvta.to.shared.u64 t, %1; cvt.u32.u64 %0, t; }" : "=r"(a) : "l"(p));
    return a;
}
__device__ __forceinline__ void ldsm4(uint32_t* r, uint32_t addr) {
    asm volatile("ldmatrix.sync.aligned.m8n8.x4.shared.b16 {%0,%1,%2,%3}, [%4];"
        : "=r"(r[0]), "=r"(r[1]), "=r"(r[2]), "=r"(r[3]) : "r"(addr));
}
__device__ __forceinline__ void mma_bf16(float* d, const uint32_t* a, const uint32_t* b) {
    asm volatile("mma.sync.aligned.m16n8k16.row.col.f32.bf16.bf16.f32 "
        "{%0,%1,%2,%3}, {%4,%5,%6,%7}, {%8,%9}, {%0,%1,%2,%3};"
        : "+f"(d[0]), "+f"(d[1]), "+f"(d[2]), "+f"(d[3])
        : "r"(a[0]), "r"(a[1]), "r"(a[2]), "r"(a[3]), "r"(b[0]), "r"(b[1]));
}
#define CP_ASYNC16(dst, src) \
    asm volatile("cp.async.cg.shared.global [%0], [%1], 16;" :: "r"(dst), "l"(src) : "memory")
#define CP_COMMIT() asm volatile("cp.async.commit_group;" ::: "memory")
#define CP_WAIT2()  asm volatile("cp.async.wait_group 2;" ::: "memory")
#define CP_WAIT0()  asm volatile("cp.async.wait_group 0;" ::: "memory")

__device__ __forceinline__ void split2(float v0, float v1, uint32_t& h, uint32_t& lo) {
    bf16 h0 = __float2bfloat16_rn(v0), h1 = __float2bfloat16_rn(v1);
    bf16 l0 = __float2bfloat16_rn(v0 - __bfloat162float(h0));
    bf16 l1 = __float2bfloat16_rn(v1 - __bfloat162float(h1));
    __nv_bfloat162 hp = __halves2bfloat162(h0, h1);
    __nv_bfloat162 lp = __halves2bfloat162(l0, l1);
    h = *(uint32_t*)&hp; lo = *(uint32_t*)&lp;
}
__device__ __forceinline__ void store_pair_split(bf16* Chi, bf16* Clo, size_t off,
                                                 float v0, float v1) {
    uint32_t h, lo; split2(v0, v1, h, lo);
    *(uint32_t*)(Chi + off) = h;
    *(uint32_t*)(Clo + off) = lo;
}

// shared 64-K-wide 3-term MMA block (validated fragment mappings)
__device__ __forceinline__ void mma_block64(float acc[2][8][4],
        uint32_t sAhi, uint32_t sAlo, uint32_t sBhi, uint32_t sBlo,
        int a_row, int a_kb, int b_row, int b_kb) {
#pragma unroll
    for (int ks = 0; ks < 4; ks++) {
        const int koff = ks * 32;
        uint32_t Ah[2][4], Al[2][4], Bh[4][4], Bl[4][4];
#pragma unroll
        for (int mf = 0; mf < 2; mf++) {
            uint32_t ro = SMEM_SWZ((uint32_t)((a_row + mf * 16) * 128 + koff + a_kb));
            ldsm4(Ah[mf], sAhi + ro);
            ldsm4(Al[mf], sAlo + ro);
        }
#pragma unroll
        for (int nf2 = 0; nf2 < 4; nf2++) {
            uint32_t ro = SMEM_SWZ((uint32_t)((b_row + nf2 * 16) * 128 + koff + b_kb));
            ldsm4(Bh[nf2], sBhi + ro);
            ldsm4(Bl[nf2], sBlo + ro);
        }
#pragma unroll
        for (int mf = 0; mf < 2; mf++)
#pragma unroll
            for (int nf = 0; nf < 8; nf++) {
                const int nf2 = nf >> 1, ho = (nf & 1) * 2;
                mma_bf16(acc[mf][nf], Ah[mf], &Bh[nf2][ho]);
                mma_bf16(acc[mf][nf], Ah[mf], &Bl[nf2][ho]);
                mma_bf16(acc[mf][nf], Al[mf], &Bh[nf2][ho]);
            }
    }
}

// ================ split conversion (fp32 -> hi/lo bf16) ================
__global__ __launch_bounds__(256)
void convert_split(const float* __restrict__ src, bf16* __restrict__ hi,
                   bf16* __restrict__ lo, int n) {
    int i = (blockIdx.x * 256 + threadIdx.x) * 4;
    if (i >= n) return;
    float4 v = *(const float4*)(src + i);
    uint32_t h0, l0, h1, l1;
    split2(v.x, v.y, h0, l0);
    split2(v.z, v.w, h1, l1);
    uint2 hu; hu.x = h0; hu.y = h1;
    uint2 lu; lu.x = l0; lu.y = l1;
    *(uint2*)(hi + i) = hu;
    *(uint2*)(lo + i) = lu;
}

// ============ cp.async tensor-core GEMM: C[M,N] = A[M,K] B[N,K]^T ============
#define TLA_HI 0
#define TLA_LO 16384
#define TLB_HI 32768
#define TLB_LO 49152
#define STG_STRIDE 65536
#define NSTAGE 3
#define GEMM_SMEM (NSTAGE*STG_STRIDE + 1024)

__device__ __forceinline__ void issue_stage(uint32_t sa,
        const bf16* __restrict__ Ahi, const bf16* __restrict__ Alo,
        const bf16* __restrict__ Bhi, const bf16* __restrict__ Blo,
        int rowA, int rowB, int Kstride, int k0, int tid) {
#pragma unroll
    for (int t = 0; t < 16; t++) {
        const int tile = t >> 2;
        int idx = t * 256 + tid;
        int r = (idx >> 3) & 127;
        int c16 = idx & 7;
        const bf16* base = (tile == 0) ? Ahi : (tile == 1) ? Alo : (tile == 2) ? Bhi : Blo;
        int rowg = ((tile < 2) ? rowA : rowB) + r;
        const void* src = base + (size_t)rowg * Kstride + k0 + c16 * 8;
        uint32_t dst = sa + tile * 16384 + SMEM_SWZ((uint32_t)(r * 128 + c16 * 16));
        CP_ASYNC16(dst, src);
    }
}

__device__ __forceinline__ void gemm_core(
        const bf16* __restrict__ Ahi, const bf16* __restrict__ Alo,
        const bf16* __restrict__ Bhi, const bf16* __restrict__ Blo,
        float* __restrict__ C, bf16* __restrict__ Chi, bf16* __restrict__ Clo,
        int N, int Kloop, int Kstride, int rowA, int rowB, int act, int outsplit) {
    extern __shared__ char dynsm[];
    char* tile = (char*)((((uintptr_t)dynsm) + 1023) & ~(uintptr_t)1023);
    const uint32_t sa0 = smem_u32(tile);
    const int tid = threadIdx.x;
    const int wid = tid >> 5, l = tid & 31;
    const int warp_m = wid >> 1, warp_n = wid & 1;

    float acc[2][8][4];
#pragma unroll
    for (int mf = 0; mf < 2; mf++)
#pragma unroll
        for (int nf = 0; nf < 8; nf++)
#pragma unroll
            for (int j = 0; j < 4; j++) acc[mf][nf][j] = 0.f;

    const int a_row = warp_m * 32 + (l & 15);
    const int a_kb  = (l >> 4) * 16;
    const int b_row = warp_n * 64 + (l & 7) + ((l >> 4) & 1) * 8;
    const int b_kb  = ((l >> 3) & 1) * 16;

    const int nk = Kloop >> 6;
#pragma unroll
    for (int s = 0; s < NSTAGE; s++) {
        if (s < nk) issue_stage(sa0 + s * STG_STRIDE, Ahi, Alo, Bhi, Blo, rowA, rowB, Kstride, s << 6, tid);
        CP_COMMIT();
    }
    int sidx = 0;
    for (int kb = 0; kb < nk; kb++) {
        CP_WAIT2();
        __syncthreads();
        const uint32_t st = sa0 + sidx * STG_STRIDE;
        mma_block64(acc, st + TLA_HI, st + TLA_LO, st + TLB_HI, st + TLB_LO,
                    a_row, a_kb, b_row, b_kb);
        __syncthreads();
        if (kb + NSTAGE < nk)
            issue_stage(sa0 + sidx * STG_STRIDE, Ahi, Alo, Bhi, Blo, rowA, rowB, Kstride, (kb + NSTAGE) << 6, tid);
        CP_COMMIT();
        sidx = (sidx + 1 == NSTAGE) ? 0 : sidx + 1;
    }

#pragma unroll
    for (int mf = 0; mf < 2; mf++)
#pragma unroll
        for (int nf = 0; nf < 8; nf++) {
            int r0 = rowA + warp_m * 32 + mf * 16 + (l >> 2);
            int cc = rowB + warp_n * 64 + nf * 8 + (l & 3) * 2;
            float v0 = acc[mf][nf][0], v1 = acc[mf][nf][1];
            float v2 = acc[mf][nf][2], v3 = acc[mf][nf][3];
            if (act) {
                v0 = v0 / (1.f + expf(-v0));
                v1 = v1 / (1.f + expf(-v1));
                v2 = v2 / (1.f + expf(-v2));
                v3 = v3 / (1.f + expf(-v3));
            }
            if (!outsplit) {
                *(float2*)(C + (size_t)r0 * N + cc)       = make_float2(v0, v1);
                *(float2*)(C + (size_t)(r0 + 8) * N + cc) = make_float2(v2, v3);
            } else {
                store_pair_split(Chi, Clo, (size_t)r0 * N + cc, v0, v1);
                store_pair_split(Chi, Clo, (size_t)(r0 + 8) * N + cc, v2, v3);
            }
        }
}

template<int ACT, int OSPLIT>
__global__ __launch_bounds__(256, 1)
void gemm_bf16(const bf16* Ahi, const bf16* Alo, const bf16* Bhi, const bf16* Blo,
               float* C, bf16* Chi, bf16* Clo, int N, int K) {
    gemm_core(Ahi, Alo, Bhi, Blo, C, Chi, Clo, N, K, K,
              blockIdx.y * 128, blockIdx.x * 128, ACT, OSPLIT);
}

// fused Q/K/V projection: grid (24, 32); which = bx>>3
__global__ __launch_bounds__(256, 1)
void gemm_qkv() {
    const int which = blockIdx.x >> 3;
    const int colb = blockIdx.x & 7;
    const bf16 *Bh, *Bl;
    float* C;
    if (which == 0)      { Bh = g_Wqhi; Bl = g_Wqlo; C = g_Q; }
    else if (which == 1) { Bh = g_Wkhi; Bl = g_Wklo; C = g_EK; }
    else                 { Bh = g_Wvhi; Bl = g_Wvlo; C = g_V; }
    gemm_core(g_xhi, g_xlo, Bh, Bl, C, nullptr, nullptr, HIDN, HIDN, HIDN,
              blockIdx.y * 128, colb * 128, which == 0, 0);
}

// split-K Wg1: grid (4, 32); each CTA does K range [bx*256, +256)
__global__ __launch_bounds__(256, 1)
void gemm_wg1_split() {
    const int ks = blockIdx.x;
    gemm_core(g_xhi + ks * 256, g_xlo + ks * 256,
              g_Wg1hi + ks * 256, g_Wg1lo + ks * 256,
              g_G1part + (size_t)ks * NROWS * 128, nullptr, nullptr,
              128, 256, HIDN, blockIdx.y * 128, 0, 0, 0);
}

__global__ __launch_bounds__(256)
void g1_reduce() {
    int i = (blockIdx.x * 256 + threadIdx.x) * 4;   // over NROWS*128
    const int S = NROWS * 128;
    float4 a = *(float4*)(g_G1part + i);
    float4 b = *(float4*)(g_G1part + S + i);
    float4 c = *(float4*)(g_G1part + 2*S + i);
    float4 d = *(float4*)(g_G1part + 3*S + i);
    float v0 = a.x + b.x + c.x + d.x;
    float v1 = a.y + b.y + c.y + d.y;
    float v2 = a.z + b.z + c.z + d.z;
    float v3 = a.w + b.w + c.w + d.w;
    uint32_t h0, l0, h1, l1;
    split2(v0, v1, h0, l0);
    split2(v2, v3, h1, l1);
    uint2 hu; hu.x = h0; hu.y = h1;
    uint2 lu; lu.x = l0; lu.y = l1;
    *(uint2*)(g_G1hi + i) = hu;
    *(uint2*)(g_G1lo + i) = lu;
}

// ================ transpose V -> split bf16 VT[bh][dv][t] ================
__global__ __launch_bounds__(256)
void transpose_v() {
    __shared__ float tile[32][33];
    const int ttile = blockIdx.x;            // 0..63
    const int dvt = blockIdx.y & 3, bh = blockIdx.y >> 2;
    const int b = bh >> 3, h = bh & 7;
    const int t0 = ttile * 32, dv0 = dvt * 32;
    const int lx = threadIdx.x & 31, ly = threadIdx.x >> 5;
#pragma unroll
    for (int i = 0; i < 4; i++) {
        int r = ly + i * 8;
        tile[r][lx] = g_V[(size_t)(b * TT + t0 + r) * HIDN + h * DKK + dv0 + lx];
    }
    __syncthreads();
#pragma unroll
    for (int i = 0; i < 4; i++) {
        int r = ly + i * 8;
        float v = tile[lx][r];
        bf16 hh = __float2bfloat16_rn(v);
        bf16 ll = __float2bfloat16_rn(v - __bfloat162float(hh));
        size_t oa = ((size_t)bh * DKK + dv0 + r) * TT + t0 + lx;
        g_VThi[oa] = hh;
        g_VTlo[oa] = ll;
    }
}

// ================= attention kernels ==================
#define MICRO_FMA(Aptr, Bptr, kk) do {                                    \
    float4 a0 = *(const float4*)&(Aptr)[(kk)*132 + ty*4];                 \
    float4 a1 = *(const float4*)&(Aptr)[(kk)*132 + 64 + ty*4];            \
    float4 b0 = *(const float4*)&(Bptr)[(kk)*132 + tx*4];                 \
    float4 b1 = *(const float4*)&(Bptr)[(kk)*132 + 64 + tx*4];            \
    float av[8] = {a0.x,a0.y,a0.z,a0.w,a1.x,a1.y,a1.z,a1.w};              \
    float bv[8] = {b0.x,b0.y,b0.z,b0.w,b1.x,b1.y,b1.z,b1.w};              \
    _Pragma("unroll") for (int ii=0; ii<8; ii++)                          \
      _Pragma("unroll") for (int jj=0; jj<8; jj++)                        \
        acc[ii][jj] += av[ii]*bv[jj];                                     \
} while(0)

__device__ __forceinline__ int fragmap(int idx, int t4) {
    return (idx < 4) ? (t4*4 + idx) : (64 + t4*4 + idx - 4);
}

// exp(k) in place (+split bf16 out), per-chunk colsum, CcT = V^T EK (fp32)
__global__ __launch_bounds__(256)
void chunk_stats() {
    const int c = blockIdx.x, bh = blockIdx.y;
    const int b = bh >> 3, h = bh & 7;
    const int base = b*TT + c*TCH;
    const int hoff = h*DKK;
    __shared__ float EKs[8*132];
    __shared__ float Vs[8*132];
    __shared__ float red[8*128];
    const int tid = threadIdx.x;
    const int tx = tid & 15, ty = tid >> 4;
    const int trow = tid >> 5;
    const int col = (tid & 31) << 2;
    float acc[8][8];
#pragma unroll
    for (int i = 0; i < 8; i++)
#pragma unroll
        for (int j = 0; j < 8; j++) acc[i][j] = 0.f;
    float ps0 = 0.f, ps1 = 0.f, ps2 = 0.f, ps3 = 0.f;

    for (int tt = 0; tt < TCH/8; tt++) {
        int row = base + tt*8 + trow;
        size_t gi = (size_t)row*HIDN + hoff + col;
        float4 kv = *(const float4*)(g_EK + gi);
        kv.x = expf(kv.x); kv.y = expf(kv.y); kv.z = expf(kv.z); kv.w = expf(kv.w);
        *(float4*)(g_EK + gi) = kv;
        uint32_t h0, l0, h1, l1;
        split2(kv.x, kv.y, h0, l0);
        split2(kv.z, kv.w, h1, l1);
        uint2 hu; hu.x = h0; hu.y = h1;
        uint2 lu; lu.x = l0; lu.y = l1;
        *(uint2*)(g_EKhi + gi) = hu;
        *(uint2*)(g_EKlo + gi) = lu;
        ps0 += kv.x; ps1 += kv.y; ps2 += kv.z; ps3 += kv.w;
        *(float4*)&EKs[trow*132 + col] = kv;
        float4 vv = *(const float4*)(g_V + gi);
        *(float4*)&Vs[trow*132 + col] = vv;
        __syncthreads();
#pragma unroll
        for (int k = 0; k < 8; k++) MICRO_FMA(Vs, EKs, k);   // acc[dv][dk] = CcT
        __syncthreads();
    }
    red[trow*128 + col + 0] = ps0; red[trow*128 + col + 1] = ps1;
    red[trow*128 + col + 2] = ps2; red[trow*128 + col + 3] = ps3;
    __syncthreads();
    if (tid < DKK) {
        float s = 0.f;
#pragma unroll
        for (int r = 0; r < 8; r++) s += red[r*128 + tid];
        g_Asum[(bh*NCHUNK + c)*DKK + tid] = s;
    }
    size_t cb = ((size_t)(bh*NCHUNK + c))*DKK*DKK;
#pragma unroll
    for (int i = 0; i < 8; i++) {
        int dv = fragmap(i, ty);
        float4 s0 = make_float4(acc[i][0], acc[i][1], acc[i][2], acc[i][3]);
        float4 s1 = make_float4(acc[i][4], acc[i][5], acc[i][6], acc[i][7]);
        *(float4*)(g_CcT + cb + (size_t)dv*DKK + tx*4)      = s0;
        *(float4*)(g_CcT + cb + (size_t)dv*DKK + 64 + tx*4) = s1;
    }
}

__global__ void scan_asum() {
    int bh = blockIdx.x, dk = threadIdx.x;
    float run = 0.f;
    for (int c = 0; c < NCHUNK; c++) {
        int i = (bh*NCHUNK + c)*DKK + dk;
        float v = g_Asum[i]; g_Asum[i] = run; run += v;
    }
}
// exclusive prefix of CcT across chunks -> split bf16
__global__ void scan_cc() {
    int bh = blockIdx.y;
    int idx = blockIdx.x*256 + threadIdx.x;
    float run = 0.f;
    for (int c = 0; c < NCHUNK; c++) {
        size_t p = ((size_t)(bh*NCHUNK + c))*(DKK*DKK) + idx;
        float v = g_CcT[p];
        bf16 hh = __float2bfloat16_rn(run);
        bf16 ll = __float2bfloat16_rn(run - __bfloat162float(hh));
        g_CcThi[p] = hh; g_CcTlo[p] = ll;
        run += v;
    }
}

// Qhat = silu(q)/A_t * scale -> split bf16
__global__ void compute_qhat() {
    const int c = blockIdx.x, bh = blockIdx.y;
    const int b = bh >> 3, h = bh & 7;
    const int base = b*TT + c*TCH;
    const int dk = threadIdx.x;
    const float scale = 0.08838834764831845f;
    float run = g_Asum[(bh*NCHUNK + c)*DKK + dk];
    for (int t = 0; t < TCH; t++) {
        size_t gi = (size_t)(base + t)*HIDN + h*DKK + dk;
        run += g_EK[gi];
        float qh = g_Q[gi] / run * scale;
        bf16 hh = __float2bfloat16_rn(qh);
        bf16 ll = __float2bfloat16_rn(qh - __bfloat162float(hh));
        g_QHhi[gi] = hh; g_QHlo[gi] = ll;
    }
}

// generic 128x128 operand loader into hi/lo smem (two 16KB K-halves each)
__device__ __forceinline__ void load_op(uint32_t shi, uint32_t slo,
        const bf16* __restrict__ ghi, const bf16* __restrict__ glo,
        size_t rstride, int tid) {
#pragma unroll
    for (int t = 0; t < 8; t++) {
        int idx = t * 256 + tid;
        int r = idx >> 4;
        int c16 = idx & 15;
        uint32_t off = (uint32_t)((c16 >> 3) * 16384) + SMEM_SWZ((uint32_t)(r * 128 + (c16 & 7) * 16));
        CP_ASYNC16(shi + off, ghi + (size_t)r * rstride + c16 * 8);
        CP_ASYNC16(slo + off, glo + (size_t)r * rstride + c16 * 8);
    }
}

// ====== chunk_out (tensor core): O = tril(QH EK^T) V + QH Cc ======
#define CO2_SMEM (6*32768 + 1024)
__global__ __launch_bounds__(256, 1)
void chunk_out_tc() {
    extern __shared__ char dynsm[];
    char* smb = (char*)((((uintptr_t)dynsm) + 1023) & ~(uintptr_t)1023);
    const uint32_t sa = smem_u32(smb);
    const int c = blockIdx.x, bh = blockIdx.y;
    const int b = bh >> 3, h = bh & 7;
    const int tbase = b*TT + c*TCH;
    const int hoff = h*DKK;
    const int tid = threadIdx.x, wid = tid >> 5, l = tid & 31;
    const int warp_m = wid >> 1, warp_n = wid & 1;
    const int a_row = warp_m * 32 + (l & 15);
    const int a_kb  = (l >> 4) * 16;
    const int b_row = warp_n * 64 + (l & 7) + ((l >> 4) & 1) * 8;
    const int b_kb  = ((l >> 3) & 1) * 16;

    const uint32_t QHI = sa, QLO = sa + 32768;
    const uint32_t BHI = sa + 65536, BLO = sa + 98304;
    const uint32_t PHI = sa + 131072, PLO = sa + 163840;
    char* Pc_hi = smb + 131072;
    char* Pc_lo = smb + 163840;

    load_op(QHI, QLO, g_QHhi + (size_t)tbase*HIDN + hoff, g_QHlo + (size_t)tbase*HIDN + hoff, HIDN, tid);
    load_op(BHI, BLO, g_EKhi + (size_t)tbase*HIDN + hoff, g_EKlo + (size_t)tbase*HIDN + hoff, HIDN, tid);
    CP_COMMIT(); CP_WAIT0(); __syncthreads();

    float acc[2][8][4];
#pragma unroll
    for (int mf = 0; mf < 2; mf++)
#pragma unroll
        for (int nf = 0; nf < 8; nf++)
#pragma unroll
            for (int j = 0; j < 4; j++) acc[mf][nf][j] = 0.f;

    // stage 1: P = QH * EK^T
#pragma unroll
    for (int kc = 0; kc < 2; kc++)
        mma_block64(acc, QHI + kc*16384, QLO + kc*16384, BHI + kc*16384, BLO + kc*16384,
                    a_row, a_kb, b_row, b_kb);
    __syncthreads();

    load_op(BHI, BLO, g_CcThi + (size_t)(bh*NCHUNK + c)*(DKK*DKK),
                       g_CcTlo + (size_t)(bh*NCHUNK + c)*(DKK*DKK), DKK, tid);
    CP_COMMIT();

    // causal mask + store P to smem (split bf16)
#pragma unroll
    for (int mf = 0; mf < 2; mf++)
#pragma unroll
        for (int nf = 0; nf < 8; nf++) {
            int r0 = warp_m * 32 + mf * 16 + (l >> 2);
            int cc = warp_n * 64 + nf * 8 + (l & 3) * 2;
            float v0 = (cc     <= r0) ? acc[mf][nf][0] : 0.f;
            float v1 = (cc + 1 <= r0) ? acc[mf][nf][1] : 0.f;
            float v2 = (cc     <= r0 + 8) ? acc[mf][nf][2] : 0.f;
            float v3 = (cc + 1 <= r0 + 8) ? acc[mf][nf][3] : 0.f;
            uint32_t ch = (uint32_t)((cc >> 6) * 16384);
            uint32_t o0 = ch + SMEM_SWZ((uint32_t)(r0 * 128 + (cc & 63) * 2));
            uint32_t o1 = ch + SMEM_SWZ((uint32_t)((r0 + 8) * 128 + (cc & 63) * 2));
            uint32_t hh, ll;
            split2(v0, v1, hh, ll);
            *(uint32_t*)(Pc_hi + o0) = hh; *(uint32_t*)(Pc_lo + o0) = ll;
            split2(v2, v3, hh, ll);
            *(uint32_t*)(Pc_hi + o1) = hh; *(uint32_t*)(Pc_lo + o1) = ll;
        }
    CP_WAIT0(); __syncthreads();

    // stage 2b: O = QH * CcT^T
#pragma unroll
    for (int mf = 0; mf < 2; mf++)
#pragma unroll
        for (int nf = 0; nf < 8; nf++)
#pragma unroll
            for (int j = 0; j < 4; j++) acc[mf][nf][j] = 0.f;
#pragma unroll
    for (int kc = 0; kc < 2; kc++)
        mma_block64(acc, QHI + kc*16384, QLO + kc*16384, BHI + kc*16384, BLO + kc*16384,
                    a_row, a_kb, b_row, b_kb);
    __syncthreads();

    load_op(QHI, QLO, g_VThi + (size_t)bh*DKK*TT + c*TCH,
                       g_VTlo + (size_t)bh*DKK*TT + c*TCH, TT, tid);
    CP_COMMIT(); CP_WAIT0(); __syncthreads();

    // stage 2a: O += P * VT^T
#pragma unroll
    for (int kc = 0; kc < 2; kc++)
        mma_block64(acc, PHI + kc*16384, PLO + kc*16384, QHI + kc*16384, QLO + kc*16384,
                    a_row, a_kb, b_row, b_kb);

#pragma unroll
    for (int mf = 0; mf < 2; mf++)
#pragma unroll
        for (int nf = 0; nf < 8; nf++) {
            int r0 = warp_m * 32 + mf * 16 + (l >> 2);
            int cc = warp_n * 64 + nf * 8 + (l & 3) * 2;
            *(float2*)(g_O + (size_t)(tbase + r0) * HIDN + hoff + cc) =
                make_float2(acc[mf][nf][0], acc[mf][nf][1]);
            *(float2*)(g_O + (size_t)(tbase + r0 + 8) * HIDN + hoff + cc) =
                make_float2(acc[mf][nf][2], acc[mf][nf][3]);
        }
}

// epilogue: RMSNorm(o) * w * gate * sigmoid(gate) -> split bf16 U
__global__ __launch_bounds__(256)
void epilogue_k(const float* __restrict__ gnw) {
    __shared__ float red[256];
    const int n = blockIdx.x, tid = threadIdx.x;
    float4 ov = *((const float4*)(g_O + (size_t)n*HIDN) + tid);
    float ss = ov.x*ov.x + ov.y*ov.y + ov.z*ov.z + ov.w*ov.w;
    red[tid] = ss;
    __syncthreads();
    for (int s = 128; s > 0; s >>= 1) {
        if (tid < s) red[tid] += red[tid + s];
        __syncthreads();
    }
    float rms = rsqrtf(red[0] * (1.f/HIDN) + 1e-5f);
    float4 gv = *((const float4*)(g_gate + (size_t)n*HIDN) + tid);
    float4 wv = *((const float4*)gnw + tid);
    float4 u;
    u.x = ov.x*rms*wv.x * gv.x / (1.f + expf(-gv.x));
    u.y = ov.y*rms*wv.y * gv.y / (1.f + expf(-gv.y));
    u.z = ov.z*rms*wv.z * gv.z / (1.f + expf(-gv.z));
    u.w = ov.w*rms*wv.w * gv.w / (1.f + expf(-gv.w));
    size_t off = (size_t)n*HIDN + tid*4;
    store_pair_split(g_Uhi, g_Ulo, off, u.x, u.y);
    store_pair_split(g_Uhi, g_Ulo, off + 2, u.z, u.w);
}

extern "C" void kernel_launch(void* const* d_in, const int* in_sizes, int n_in,
                              void* d_out, int out_size) {
    const float* x   = (const float*)d_in[0];
    const float* Wq  = (const float*)d_in[1];
    const float* Wk  = (const float*)d_in[2];
    const float* Wv  = (const float*)d_in[3];
    const float* Wg1 = (const float*)d_in[4];
    const float* Wg2 = (const float*)d_in[5];
    const float* gnw = (const float*)d_in[6];
    const float* Wo  = (const float*)d_in[7];
    float* out = (float*)d_out;

    bf16 *xhi,*xlo,*wqh,*wql,*wkh,*wkl,*wvh,*wvl,*woh,*wol,*w1h,*w1l,*w2h,*w2l,*g1h,*g1l,*uh,*ul;
    float* gate;
    cudaGetSymbolAddress((void**)&xhi, g_xhi);  cudaGetSymbolAddress((void**)&xlo, g_xlo);
    cudaGetSymbolAddress((void**)&wqh, g_Wqhi); cudaGetSymbolAddress((void**)&wql, g_Wqlo);
    cudaGetSymbolAddress((void**)&wkh, g_Wkhi); cudaGetSymbolAddress((void**)&wkl, g_Wklo);
    cudaGetSymbolAddress((void**)&wvh, g_Wvhi); cudaGetSymbolAddress((void**)&wvl, g_Wvlo);
    cudaGetSymbolAddress((void**)&woh, g_Wohi); cudaGetSymbolAddress((void**)&wol, g_Wolo);
    cudaGetSymbolAddress((void**)&w1h, g_Wg1hi); cudaGetSymbolAddress((void**)&w1l, g_Wg1lo);
    cudaGetSymbolAddress((void**)&w2h, g_Wg2hi); cudaGetSymbolAddress((void**)&w2l, g_Wg2lo);
    cudaGetSymbolAddress((void**)&g1h, g_G1hi); cudaGetSymbolAddress((void**)&g1l, g_G1lo);
    cudaGetSymbolAddress((void**)&uh, g_Uhi);   cudaGetSymbolAddress((void**)&ul, g_Ulo);
    cudaGetSymbolAddress((void**)&gate, g_gate);

    cudaFuncSetAttribute(gemm_qkv, cudaFuncAttributeMaxDynamicSharedMemorySize, GEMM_SMEM);
    cudaFuncSetAttribute(gemm_wg1_split, cudaFuncAttributeMaxDynamicSharedMemorySize, GEMM_SMEM);
    cudaFuncSetAttribute(gemm_bf16<0,0>, cudaFuncAttributeMaxDynamicSharedMemorySize, GEMM_SMEM);
    cudaFuncSetAttribute(chunk_out_tc, cudaFuncAttributeMaxDynamicSharedMemorySize, CO2_SMEM);

    dim3 blk(256);
    convert_split<<<NROWS*HIDN/1024, blk>>>(x, xhi, xlo, NROWS*HIDN);
    convert_split<<<HIDN*HIDN/1024, blk>>>(Wq, wqh, wql, HIDN*HIDN);
    convert_split<<<HIDN*HIDN/1024, blk>>>(Wk, wkh, wkl, HIDN*HIDN);
    convert_split<<<HIDN*HIDN/1024, blk>>>(Wv, wvh, wvl, HIDN*HIDN);
    convert_split<<<128*HIDN/1024, blk>>>(Wg1, w1h, w1l, 128*HIDN);
    gemm_qkv<<<dim3(24,32), blk, GEMM_SMEM>>>();
    gemm_wg1_split<<<dim3(4,32), blk, GEMM_SMEM>>>();
    g1_reduce<<<NROWS*128/1024, blk>>>();
    convert_split<<<HIDN*128/1024, blk>>>(Wg2, w2h, w2l, HIDN*128);
    gemm_bf16<0,0><<<dim3(8,32), blk, GEMM_SMEM>>>(g1h, g1l, w2h, w2l, gate, nullptr, nullptr, HIDN, 128);
    convert_split<<<HIDN*HIDN/1024, blk>>>(Wo, woh, wol, HIDN*HIDN);
    chunk_stats<<<dim3(NCHUNK, NBH), blk>>>();
    scan_asum<<<NBH, DKK>>>();
    scan_cc<<<dim3(64, NBH), 256>>>();
    transpose_v<<<dim3(64, 4*NBH), blk>>>();
    compute_qhat<<<dim3(NCHUNK, NBH), DKK>>>();
    chunk_out_tc<<<dim3(NCHUNK, NBH), blk, CO2_SMEM>>>();
    epilogue_k<<<NROWS, blk>>>(gnw);
    gemm_bf16<0,0><<<dim3(8,32), blk, GEMM_SMEM>>>(uh, ul, woh, wol, out, nullptr, nullptr, HIDN, HIDN);
}

// round 8
// speedup vs baseline: 1.7385x; 1.2329x over previous
#include <cuda_runtime.h>
#include <cuda_bf16.h>
#include <cuda_fp16.h>
#include <cstdint>
#include <math.h>

// Problem dims
#define BB 2
#define TT 2048
#define HIDN 1024
#define NH 8
#define DKK 128
#define NROWS (BB*TT)      // 4096
#define TCH 128
#define NCHUNK (TT/TCH)    // 16
#define NBH (BB*NH)        // 16

#define SMEM_SWZ(off) ((off) ^ (((off) >> 3) & 0x70))
typedef __nv_bfloat16 bf16;

// -------- fp32 scratch --------
__device__ float g_Q[NROWS*HIDN];
__device__ float g_EK[NROWS*HIDN];     // raw k, then exp(k) in place
__device__ float g_V[NROWS*HIDN];
__device__ float g_gate[NROWS*HIDN];
__device__ float g_O[NROWS*HIDN];
__device__ float g_Asum[NBH*NCHUNK*DKK];
__device__ float g_CcT[NBH*NCHUNK*DKK*DKK];   // per-chunk (V^T EK) = Cc^T [dv][dk]
__device__ float g_G1part[4*NROWS*128];       // split-K partials for Wg1
// -------- fp16 scratch (projection path, 2-term split) --------
__device__ __half g_xh[NROWS*HIDN];
__device__ __half g_Wqh[HIDN*HIDN],  g_Wql[HIDN*HIDN];
__device__ __half g_Wkh[HIDN*HIDN],  g_Wkl[HIDN*HIDN];
__device__ __half g_Wvh[HIDN*HIDN],  g_Wvl[HIDN*HIDN];
__device__ __half g_Woh[HIDN*HIDN],  g_Wol[HIDN*HIDN];
__device__ __half g_Wg1h[128*HIDN],  g_Wg1l[128*HIDN];
__device__ __half g_Wg2h[HIDN*128],  g_Wg2l[HIDN*128];
__device__ __half g_G1h[NROWS*128];
__device__ __half g_Uh[NROWS*HIDN];
// -------- split-bf16 scratch (attention path, 3-term split) --------
__device__ bf16 g_EKhi[NROWS*HIDN], g_EKlo[NROWS*HIDN];   // exp(k), natural [t, dk]
__device__ bf16 g_QHhi[NROWS*HIDN], g_QHlo[NROWS*HIDN];   // qhat, natural [t, dk]
__device__ bf16 g_VThi[NBH*DKK*TT], g_VTlo[NBH*DKK*TT];   // [bh][dv][t]
__device__ bf16 g_CcThi[NBH*NCHUNK*DKK*DKK], g_CcTlo[NBH*NCHUNK*DKK*DKK]; // excl prefix

// ================= helpers =================
__device__ __forceinline__ uint32_t smem_u32(const void* p) {
    uint32_t a;
    asm("{ .reg .u64 t; cvta.to.shared.u64 t, %1; cvt.u32.u64 %0, t; }" : "=r"(a) : "l"(p));
    return a;
}
__device__ __forceinline__ void ldsm4(uint32_t* r, uint32_t addr) {
    asm volatile("ldmatrix.sync.aligned.m8n8.x4.shared.b16 {%0,%1,%2,%3}, [%4];"
        : "=r"(r[0]), "=r"(r[1]), "=r"(r[2]), "=r"(r[3]) : "r"(addr));
}
__device__ __forceinline__ void mma_bf16(float* d, const uint32_t* a, const uint32_t* b) {
    asm volatile("mma.sync.aligned.m16n8k16.row.col.f32.bf16.bf16.f32 "
        "{%0,%1,%2,%3}, {%4,%5,%6,%7}, {%8,%9}, {%0,%1,%2,%3};"
        : "+f"(d[0]), "+f"(d[1]), "+f"(d[2]), "+f"(d[3])
        : "r"(a[0]), "r"(a[1]), "r"(a[2]), "r"(a[3]), "r"(b[0]), "r"(b[1]));
}
__device__ __forceinline__ void mma_f16(float* d, const uint32_t* a, const uint32_t* b) {
    asm volatile("mma.sync.aligned.m16n8k16.row.col.f32.f16.f16.f32 "
        "{%0,%1,%2,%3}, {%4,%5,%6,%7}, {%8,%9}, {%0,%1,%2,%3};"
        : "+f"(d[0]), "+f"(d[1]), "+f"(d[2]), "+f"(d[3])
        : "r"(a[0]), "r"(a[1]), "r"(a[2]), "r"(a[3]), "r"(b[0]), "r"(b[1]));
}
#define CP_ASYNC16(dst, src) \
    asm volatile("cp.async.cg.shared.global [%0], [%1], 16;" :: "r"(dst), "l"(src) : "memory")
#define CP_COMMIT() asm volatile("cp.async.commit_group;" ::: "memory")
#define CP_WAIT2()  asm volatile("cp.async.wait_group 2;" ::: "memory")
#define CP_WAIT0()  asm volatile("cp.async.wait_group 0;" ::: "memory")

__device__ __forceinline__ void split2(float v0, float v1, uint32_t& h, uint32_t& lo) {
    bf16 h0 = __float2bfloat16_rn(v0), h1 = __float2bfloat16_rn(v1);
    bf16 l0 = __float2bfloat16_rn(v0 - __bfloat162float(h0));
    bf16 l1 = __float2bfloat16_rn(v1 - __bfloat162float(h1));
    __nv_bfloat162 hp = __halves2bfloat162(h0, h1);
    __nv_bfloat162 lp = __halves2bfloat162(l0, l1);
    h = *(uint32_t*)&hp; lo = *(uint32_t*)&lp;
}
__device__ __forceinline__ void split2h(float v0, float v1, uint32_t& h, uint32_t& lo) {
    __half h0 = __float2half_rn(v0), h1 = __float2half_rn(v1);
    __half l0 = __float2half_rn(v0 - __half2float(h0));
    __half l1 = __float2half_rn(v1 - __half2float(h1));
    __half2 hp = __halves2half2(h0, h1);
    __half2 lp = __halves2half2(l0, l1);
    h = *(uint32_t*)&hp; lo = *(uint32_t*)&lp;
}
__device__ __forceinline__ uint32_t pack2h(float v0, float v1) {
    __half2 hp = __halves2half2(__float2half_rn(v0), __float2half_rn(v1));
    return *(uint32_t*)&hp;
}
__device__ __forceinline__ void store_pair_split(bf16* Chi, bf16* Clo, size_t off,
                                                 float v0, float v1) {
    uint32_t h, lo; split2(v0, v1, h, lo);
    *(uint32_t*)(Chi + off) = h;
    *(uint32_t*)(Clo + off) = lo;
}

// shared 64-K-wide 3-term bf16 MMA block (attention path)
__device__ __forceinline__ void mma_block64(float acc[2][8][4],
        uint32_t sAhi, uint32_t sAlo, uint32_t sBhi, uint32_t sBlo,
        int a_row, int a_kb, int b_row, int b_kb) {
#pragma unroll
    for (int ks = 0; ks < 4; ks++) {
        const int koff = ks * 32;
        uint32_t Ah[2][4], Al[2][4], Bh[4][4], Bl[4][4];
#pragma unroll
        for (int mf = 0; mf < 2; mf++) {
            uint32_t ro = SMEM_SWZ((uint32_t)((a_row + mf * 16) * 128 + koff + a_kb));
            ldsm4(Ah[mf], sAhi + ro);
            ldsm4(Al[mf], sAlo + ro);
        }
#pragma unroll
        for (int nf2 = 0; nf2 < 4; nf2++) {
            uint32_t ro = SMEM_SWZ((uint32_t)((b_row + nf2 * 16) * 128 + koff + b_kb));
            ldsm4(Bh[nf2], sBhi + ro);
            ldsm4(Bl[nf2], sBlo + ro);
        }
#pragma unroll
        for (int mf = 0; mf < 2; mf++)
#pragma unroll
            for (int nf = 0; nf < 8; nf++) {
                const int nf2 = nf >> 1, ho = (nf & 1) * 2;
                mma_bf16(acc[mf][nf], Ah[mf], &Bh[nf2][ho]);
                mma_bf16(acc[mf][nf], Ah[mf], &Bl[nf2][ho]);
                mma_bf16(acc[mf][nf], Al[mf], &Bh[nf2][ho]);
            }
    }
}

// 64-K-wide 2-term fp16 MMA block (projection path: A hi-only, B hi+lo)
__device__ __forceinline__ void mma_block64_f16(float acc[2][8][4],
        uint32_t sA, uint32_t sBh, uint32_t sBl,
        int a_row, int a_kb, int b_row, int b_kb) {
#pragma unroll
    for (int ks = 0; ks < 4; ks++) {
        const int koff = ks * 32;
        uint32_t Ah[2][4], Bh[4][4], Bl[4][4];
#pragma unroll
        for (int mf = 0; mf < 2; mf++) {
            uint32_t ro = SMEM_SWZ((uint32_t)((a_row + mf * 16) * 128 + koff + a_kb));
            ldsm4(Ah[mf], sA + ro);
        }
#pragma unroll
        for (int nf2 = 0; nf2 < 4; nf2++) {
            uint32_t ro = SMEM_SWZ((uint32_t)((b_row + nf2 * 16) * 128 + koff + b_kb));
            ldsm4(Bh[nf2], sBh + ro);
            ldsm4(Bl[nf2], sBl + ro);
        }
#pragma unroll
        for (int mf = 0; mf < 2; mf++)
#pragma unroll
            for (int nf = 0; nf < 8; nf++) {
                const int nf2 = nf >> 1, ho = (nf & 1) * 2;
                mma_f16(acc[mf][nf], Ah[mf], &Bh[nf2][ho]);
                mma_f16(acc[mf][nf], Ah[mf], &Bl[nf2][ho]);
            }
    }
}

// ================ merged split conversion ================
// bx<4096: x (hi-only); then Wq/Wk/Wv/Wo (hi+lo, 1024 blocks each); Wg1, Wg2 (128 each)
__global__ __launch_bounds__(256)
void convert_all(const float* __restrict__ x,  const float* __restrict__ Wq,
                 const float* __restrict__ Wk, const float* __restrict__ Wv,
                 const float* __restrict__ Wo, const float* __restrict__ Wg1,
                 const float* __restrict__ Wg2) {
    int bx = blockIdx.x;
    const float* src; __half *hi, *lo; int lb; int full;
    if      (bx < 4096) { src = x;   hi = g_xh;   lo = nullptr; lb = bx;        full = 0; }
    else if (bx < 5120) { src = Wq;  hi = g_Wqh;  lo = g_Wql;   lb = bx - 4096; full = 1; }
    else if (bx < 6144) { src = Wk;  hi = g_Wkh;  lo = g_Wkl;   lb = bx - 5120; full = 1; }
    else if (bx < 7168) { src = Wv;  hi = g_Wvh;  lo = g_Wvl;   lb = bx - 6144; full = 1; }
    else if (bx < 8192) { src = Wo;  hi = g_Woh;  lo = g_Wol;   lb = bx - 7168; full = 1; }
    else if (bx < 8320) { src = Wg1; hi = g_Wg1h; lo = g_Wg1l;  lb = bx - 8192; full = 1; }
    else                { src = Wg2; hi = g_Wg2h; lo = g_Wg2l;  lb = bx - 8320; full = 1; }
    int i = (lb * 256 + threadIdx.x) * 4;
    float4 v = *(const float4*)(src + i);
    if (!full) {
        uint2 hu; hu.x = pack2h(v.x, v.y); hu.y = pack2h(v.z, v.w);
        *(uint2*)(hi + i) = hu;
    } else {
        uint32_t h0, l0, h1, l1;
        split2h(v.x, v.y, h0, l0);
        split2h(v.z, v.w, h1, l1);
        uint2 hu; hu.x = h0; hu.y = h1;
        uint2 lu; lu.x = l0; lu.y = l1;
        *(uint2*)(hi + i) = hu;
        *(uint2*)(lo + i) = lu;
    }
}

// ============ fp16 2-term cp.async GEMM: C[M,N] = A[M,K] B[N,K]^T ============
// stage: A[16K] Bhi[16K] Blo[16K]
#define F16_STG 49152
#define NSTAGE 3
#define GEMM_F16_SMEM (NSTAGE*F16_STG + 1024)

__device__ __forceinline__ void issue_stage_f16(uint32_t sa,
        const __half* __restrict__ A, const __half* __restrict__ Bh,
        const __half* __restrict__ Bl,
        int rowA, int rowB, int Kstride, int k0, int tid) {
#pragma unroll
    for (int t = 0; t < 12; t++) {
        const int tile = t >> 2;
        int idx = t * 256 + tid;
        int r = (idx >> 3) & 127;
        int c16 = idx & 7;
        const __half* base = (tile == 0) ? A : (tile == 1) ? Bh : Bl;
        int rowg = ((tile == 0) ? rowA : rowB) + r;
        const void* src = base + (size_t)rowg * Kstride + k0 + c16 * 8;
        uint32_t dst = sa + tile * 16384 + SMEM_SWZ((uint32_t)(r * 128 + c16 * 16));
        CP_ASYNC16(dst, src);
    }
}

__device__ __forceinline__ void gemm_core_f16(
        const __half* __restrict__ A, const __half* __restrict__ Bh,
        const __half* __restrict__ Bl, float* __restrict__ C,
        int N, int Kloop, int Kstride, int rowA, int rowB, int act) {
    extern __shared__ char dynsm[];
    char* tile = (char*)((((uintptr_t)dynsm) + 1023) & ~(uintptr_t)1023);
    const uint32_t sa0 = smem_u32(tile);
    const int tid = threadIdx.x;
    const int wid = tid >> 5, l = tid & 31;
    const int warp_m = wid >> 1, warp_n = wid & 1;

    float acc[2][8][4];
#pragma unroll
    for (int mf = 0; mf < 2; mf++)
#pragma unroll
        for (int nf = 0; nf < 8; nf++)
#pragma unroll
            for (int j = 0; j < 4; j++) acc[mf][nf][j] = 0.f;

    const int a_row = warp_m * 32 + (l & 15);
    const int a_kb  = (l >> 4) * 16;
    const int b_row = warp_n * 64 + (l & 7) + ((l >> 4) & 1) * 8;
    const int b_kb  = ((l >> 3) & 1) * 16;

    const int nk = Kloop >> 6;
#pragma unroll
    for (int s = 0; s < NSTAGE; s++) {
        if (s < nk) issue_stage_f16(sa0 + s * F16_STG, A, Bh, Bl, rowA, rowB, Kstride, s << 6, tid);
        CP_COMMIT();
    }
    int sidx = 0;
    for (int kb = 0; kb < nk; kb++) {
        CP_WAIT2();
        __syncthreads();
        const uint32_t st = sa0 + sidx * F16_STG;
        mma_block64_f16(acc, st, st + 16384, st + 32768, a_row, a_kb, b_row, b_kb);
        __syncthreads();
        if (kb + NSTAGE < nk)
            issue_stage_f16(sa0 + sidx * F16_STG, A, Bh, Bl, rowA, rowB, Kstride, (kb + NSTAGE) << 6, tid);
        CP_COMMIT();
        sidx = (sidx + 1 == NSTAGE) ? 0 : sidx + 1;
    }

#pragma unroll
    for (int mf = 0; mf < 2; mf++)
#pragma unroll
        for (int nf = 0; nf < 8; nf++) {
            int r0 = rowA + warp_m * 32 + mf * 16 + (l >> 2);
            int cc = rowB + warp_n * 64 + nf * 8 + (l & 3) * 2;
            float v0 = acc[mf][nf][0], v1 = acc[mf][nf][1];
            float v2 = acc[mf][nf][2], v3 = acc[mf][nf][3];
            if (act) {
                v0 = v0 / (1.f + expf(-v0));
                v1 = v1 / (1.f + expf(-v1));
                v2 = v2 / (1.f + expf(-v2));
                v3 = v3 / (1.f + expf(-v3));
            }
            *(float2*)(C + (size_t)r0 * N + cc)       = make_float2(v0, v1);
            *(float2*)(C + (size_t)(r0 + 8) * N + cc) = make_float2(v2, v3);
        }
}

template<int ACT>
__global__ __launch_bounds__(256, 1)
void gemm_f16(const __half* A, const __half* Bh, const __half* Bl,
              float* C, int N, int K) {
    gemm_core_f16(A, Bh, Bl, C, N, K, K, blockIdx.y * 128, blockIdx.x * 128, ACT);
}

// fused Q/K/V projection: grid (24, 32); which = bx>>3
__global__ __launch_bounds__(256, 1)
void gemm_qkv_f16() {
    const int which = blockIdx.x >> 3;
    const int colb = blockIdx.x & 7;
    const __half *Bh, *Bl;
    float* C;
    if (which == 0)      { Bh = g_Wqh; Bl = g_Wql; C = g_Q; }
    else if (which == 1) { Bh = g_Wkh; Bl = g_Wkl; C = g_EK; }
    else                 { Bh = g_Wvh; Bl = g_Wvl; C = g_V; }
    gemm_core_f16(g_xh, Bh, Bl, C, HIDN, HIDN, HIDN,
                  blockIdx.y * 128, colb * 128, which == 0);
}

// split-K Wg1: grid (4, 32)
__global__ __launch_bounds__(256, 1)
void gemm_wg1_f16() {
    const int ks = blockIdx.x;
    gemm_core_f16(g_xh + ks * 256, g_Wg1h + ks * 256, g_Wg1l + ks * 256,
                  g_G1part + (size_t)ks * NROWS * 128,
                  128, 256, HIDN, blockIdx.y * 128, 0, 0);
}

__global__ __launch_bounds__(256)
void g1_reduce() {
    int i = (blockIdx.x * 256 + threadIdx.x) * 4;   // over NROWS*128
    const int S = NROWS * 128;
    float4 a = *(float4*)(g_G1part + i);
    float4 b = *(float4*)(g_G1part + S + i);
    float4 c = *(float4*)(g_G1part + 2*S + i);
    float4 d = *(float4*)(g_G1part + 3*S + i);
    uint2 hu;
    hu.x = pack2h(a.x + b.x + c.x + d.x, a.y + b.y + c.y + d.y);
    hu.y = pack2h(a.z + b.z + c.z + d.z, a.w + b.w + c.w + d.w);
    *(uint2*)(g_G1h + i) = hu;
}

// ================ transpose V -> split bf16 VT[bh][dv][t] ================
__global__ __launch_bounds__(256)
void transpose_v() {
    __shared__ float tile[32][33];
    const int ttile = blockIdx.x;            // 0..63
    const int dvt = blockIdx.y & 3, bh = blockIdx.y >> 2;
    const int b = bh >> 3, h = bh & 7;
    const int t0 = ttile * 32, dv0 = dvt * 32;
    const int lx = threadIdx.x & 31, ly = threadIdx.x >> 5;
#pragma unroll
    for (int i = 0; i < 4; i++) {
        int r = ly + i * 8;
        tile[r][lx] = g_V[(size_t)(b * TT + t0 + r) * HIDN + h * DKK + dv0 + lx];
    }
    __syncthreads();
#pragma unroll
    for (int i = 0; i < 4; i++) {
        int r = ly + i * 8;
        float v = tile[lx][r];
        bf16 hh = __float2bfloat16_rn(v);
        bf16 ll = __float2bfloat16_rn(v - __bfloat162float(hh));
        size_t oa = ((size_t)bh * DKK + dv0 + r) * TT + t0 + lx;
        g_VThi[oa] = hh;
        g_VTlo[oa] = ll;
    }
}

// ================= attention kernels (unchanged round-7 path) ==================
#define MICRO_FMA(Aptr, Bptr, kk) do {                                    \
    float4 a0 = *(const float4*)&(Aptr)[(kk)*132 + ty*4];                 \
    float4 a1 = *(const float4*)&(Aptr)[(kk)*132 + 64 + ty*4];            \
    float4 b0 = *(const float4*)&(Bptr)[(kk)*132 + tx*4];                 \
    float4 b1 = *(const float4*)&(Bptr)[(kk)*132 + 64 + tx*4];            \
    float av[8] = {a0.x,a0.y,a0.z,a0.w,a1.x,a1.y,a1.z,a1.w};              \
    float bv[8] = {b0.x,b0.y,b0.z,b0.w,b1.x,b1.y,b1.z,b1.w};              \
    _Pragma("unroll") for (int ii=0; ii<8; ii++)                          \
      _Pragma("unroll") for (int jj=0; jj<8; jj++)                        \
        acc[ii][jj] += av[ii]*bv[jj];                                     \
} while(0)

__device__ __forceinline__ int fragmap(int idx, int t4) {
    return (idx < 4) ? (t4*4 + idx) : (64 + t4*4 + idx - 4);
}

// exp(k) in place (+split bf16 out), per-chunk colsum, CcT = V^T EK (fp32)
__global__ __launch_bounds__(256)
void chunk_stats() {
    const int c = blockIdx.x, bh = blockIdx.y;
    const int b = bh >> 3, h = bh & 7;
    const int base = b*TT + c*TCH;
    const int hoff = h*DKK;
    __shared__ float EKs[8*132];
    __shared__ float Vs[8*132];
    __shared__ float red[8*128];
    const int tid = threadIdx.x;
    const int tx = tid & 15, ty = tid >> 4;
    const int trow = tid >> 5;
    const int col = (tid & 31) << 2;
    float acc[8][8];
#pragma unroll
    for (int i = 0; i < 8; i++)
#pragma unroll
        for (int j = 0; j < 8; j++) acc[i][j] = 0.f;
    float ps0 = 0.f, ps1 = 0.f, ps2 = 0.f, ps3 = 0.f;

    for (int tt = 0; tt < TCH/8; tt++) {
        int row = base + tt*8 + trow;
        size_t gi = (size_t)row*HIDN + hoff + col;
        float4 kv = *(const float4*)(g_EK + gi);
        kv.x = expf(kv.x); kv.y = expf(kv.y); kv.z = expf(kv.z); kv.w = expf(kv.w);
        *(float4*)(g_EK + gi) = kv;
        uint32_t h0, l0, h1, l1;
        split2(kv.x, kv.y, h0, l0);
        split2(kv.z, kv.w, h1, l1);
        uint2 hu; hu.x = h0; hu.y = h1;
        uint2 lu; lu.x = l0; lu.y = l1;
        *(uint2*)(g_EKhi + gi) = hu;
        *(uint2*)(g_EKlo + gi) = lu;
        ps0 += kv.x; ps1 += kv.y; ps2 += kv.z; ps3 += kv.w;
        *(float4*)&EKs[trow*132 + col] = kv;
        float4 vv = *(const float4*)(g_V + gi);
        *(float4*)&Vs[trow*132 + col] = vv;
        __syncthreads();
#pragma unroll
        for (int k = 0; k < 8; k++) MICRO_FMA(Vs, EKs, k);   // acc[dv][dk] = CcT
        __syncthreads();
    }
    red[trow*128 + col + 0] = ps0; red[trow*128 + col + 1] = ps1;
    red[trow*128 + col + 2] = ps2; red[trow*128 + col + 3] = ps3;
    __syncthreads();
    if (tid < DKK) {
        float s = 0.f;
#pragma unroll
        for (int r = 0; r < 8; r++) s += red[r*128 + tid];
        g_Asum[(bh*NCHUNK + c)*DKK + tid] = s;
    }
    size_t cb = ((size_t)(bh*NCHUNK + c))*DKK*DKK;
#pragma unroll
    for (int i = 0; i < 8; i++) {
        int dv = fragmap(i, ty);
        float4 s0 = make_float4(acc[i][0], acc[i][1], acc[i][2], acc[i][3]);
        float4 s1 = make_float4(acc[i][4], acc[i][5], acc[i][6], acc[i][7]);
        *(float4*)(g_CcT + cb + (size_t)dv*DKK + tx*4)      = s0;
        *(float4*)(g_CcT + cb + (size_t)dv*DKK + 64 + tx*4) = s1;
    }
}

__global__ void scan_asum() {
    int bh = blockIdx.x, dk = threadIdx.x;
    float run = 0.f;
    for (int c = 0; c < NCHUNK; c++) {
        int i = (bh*NCHUNK + c)*DKK + dk;
        float v = g_Asum[i]; g_Asum[i] = run; run += v;
    }
}
__global__ void scan_cc() {
    int bh = blockIdx.y;
    int idx = blockIdx.x*256 + threadIdx.x;
    float run = 0.f;
    for (int c = 0; c < NCHUNK; c++) {
        size_t p = ((size_t)(bh*NCHUNK + c))*(DKK*DKK) + idx;
        float v = g_CcT[p];
        bf16 hh = __float2bfloat16_rn(run);
        bf16 ll = __float2bfloat16_rn(run - __bfloat162float(hh));
        g_CcThi[p] = hh; g_CcTlo[p] = ll;
        run += v;
    }
}

__global__ void compute_qhat() {
    const int c = blockIdx.x, bh = blockIdx.y;
    const int b = bh >> 3, h = bh & 7;
    const int base = b*TT + c*TCH;
    const int dk = threadIdx.x;
    const float scale = 0.08838834764831845f;
    float run = g_Asum[(bh*NCHUNK + c)*DKK + dk];
    for (int t = 0; t < TCH; t++) {
        size_t gi = (size_t)(base + t)*HIDN + h*DKK + dk;
        run += g_EK[gi];
        float qh = g_Q[gi] / run * scale;
        bf16 hh = __float2bfloat16_rn(qh);
        bf16 ll = __float2bfloat16_rn(qh - __bfloat162float(hh));
        g_QHhi[gi] = hh; g_QHlo[gi] = ll;
    }
}

// generic 128x128 operand loader into hi/lo smem (two 16KB K-halves each)
__device__ __forceinline__ void load_op(uint32_t shi, uint32_t slo,
        const bf16* __restrict__ ghi, const bf16* __restrict__ glo,
        size_t rstride, int tid) {
#pragma unroll
    for (int t = 0; t < 8; t++) {
        int idx = t * 256 + tid;
        int r = idx >> 4;
        int c16 = idx & 15;
        uint32_t off = (uint32_t)((c16 >> 3) * 16384) + SMEM_SWZ((uint32_t)(r * 128 + (c16 & 7) * 16));
        CP_ASYNC16(shi + off, ghi + (size_t)r * rstride + c16 * 8);
        CP_ASYNC16(slo + off, glo + (size_t)r * rstride + c16 * 8);
    }
}

// ====== chunk_out (tensor core): O = tril(QH EK^T) V + QH Cc ======
#define CO2_SMEM (6*32768 + 1024)
__global__ __launch_bounds__(256, 1)
void chunk_out_tc() {
    extern __shared__ char dynsm[];
    char* smb = (char*)((((uintptr_t)dynsm) + 1023) & ~(uintptr_t)1023);
    const uint32_t sa = smem_u32(smb);
    const int c = blockIdx.x, bh = blockIdx.y;
    const int b = bh >> 3, h = bh & 7;
    const int tbase = b*TT + c*TCH;
    const int hoff = h*DKK;
    const int tid = threadIdx.x, wid = tid >> 5, l = tid & 31;
    const int warp_m = wid >> 1, warp_n = wid & 1;
    const int a_row = warp_m * 32 + (l & 15);
    const int a_kb  = (l >> 4) * 16;
    const int b_row = warp_n * 64 + (l & 7) + ((l >> 4) & 1) * 8;
    const int b_kb  = ((l >> 3) & 1) * 16;

    const uint32_t QHI = sa, QLO = sa + 32768;
    const uint32_t BHI = sa + 65536, BLO = sa + 98304;
    const uint32_t PHI = sa + 131072, PLO = sa + 163840;
    char* Pc_hi = smb + 131072;
    char* Pc_lo = smb + 163840;

    load_op(QHI, QLO, g_QHhi + (size_t)tbase*HIDN + hoff, g_QHlo + (size_t)tbase*HIDN + hoff, HIDN, tid);
    load_op(BHI, BLO, g_EKhi + (size_t)tbase*HIDN + hoff, g_EKlo + (size_t)tbase*HIDN + hoff, HIDN, tid);
    CP_COMMIT(); CP_WAIT0(); __syncthreads();

    float acc[2][8][4];
#pragma unroll
    for (int mf = 0; mf < 2; mf++)
#pragma unroll
        for (int nf = 0; nf < 8; nf++)
#pragma unroll
            for (int j = 0; j < 4; j++) acc[mf][nf][j] = 0.f;

    // stage 1: P = QH * EK^T
#pragma unroll
    for (int kc = 0; kc < 2; kc++)
        mma_block64(acc, QHI + kc*16384, QLO + kc*16384, BHI + kc*16384, BLO + kc*16384,
                    a_row, a_kb, b_row, b_kb);
    __syncthreads();

    load_op(BHI, BLO, g_CcThi + (size_t)(bh*NCHUNK + c)*(DKK*DKK),
                       g_CcTlo + (size_t)(bh*NCHUNK + c)*(DKK*DKK), DKK, tid);
    CP_COMMIT();

    // causal mask + store P to smem (split bf16)
#pragma unroll
    for (int mf = 0; mf < 2; mf++)
#pragma unroll
        for (int nf = 0; nf < 8; nf++) {
            int r0 = warp_m * 32 + mf * 16 + (l >> 2);
            int cc = warp_n * 64 + nf * 8 + (l & 3) * 2;
            float v0 = (cc     <= r0) ? acc[mf][nf][0] : 0.f;
            float v1 = (cc + 1 <= r0) ? acc[mf][nf][1] : 0.f;
            float v2 = (cc     <= r0 + 8) ? acc[mf][nf][2] : 0.f;
            float v3 = (cc + 1 <= r0 + 8) ? acc[mf][nf][3] : 0.f;
            uint32_t ch = (uint32_t)((cc >> 6) * 16384);
            uint32_t o0 = ch + SMEM_SWZ((uint32_t)(r0 * 128 + (cc & 63) * 2));
            uint32_t o1 = ch + SMEM_SWZ((uint32_t)((r0 + 8) * 128 + (cc & 63) * 2));
            uint32_t hh, ll;
            split2(v0, v1, hh, ll);
            *(uint32_t*)(Pc_hi + o0) = hh; *(uint32_t*)(Pc_lo + o0) = ll;
            split2(v2, v3, hh, ll);
            *(uint32_t*)(Pc_hi + o1) = hh; *(uint32_t*)(Pc_lo + o1) = ll;
        }
    CP_WAIT0(); __syncthreads();

    // stage 2b: O = QH * CcT^T
#pragma unroll
    for (int mf = 0; mf < 2; mf++)
#pragma unroll
        for (int nf = 0; nf < 8; nf++)
#pragma unroll
            for (int j = 0; j < 4; j++) acc[mf][nf][j] = 0.f;
#pragma unroll
    for (int kc = 0; kc < 2; kc++)
        mma_block64(acc, QHI + kc*16384, QLO + kc*16384, BHI + kc*16384, BLO + kc*16384,
                    a_row, a_kb, b_row, b_kb);
    __syncthreads();

    load_op(QHI, QLO, g_VThi + (size_t)bh*DKK*TT + c*TCH,
                       g_VTlo + (size_t)bh*DKK*TT + c*TCH, TT, tid);
    CP_COMMIT(); CP_WAIT0(); __syncthreads();

    // stage 2a: O += P * VT^T
#pragma unroll
    for (int kc = 0; kc < 2; kc++)
        mma_block64(acc, PHI + kc*16384, PLO + kc*16384, QHI + kc*16384, QLO + kc*16384,
                    a_row, a_kb, b_row, b_kb);

#pragma unroll
    for (int mf = 0; mf < 2; mf++)
#pragma unroll
        for (int nf = 0; nf < 8; nf++) {
            int r0 = warp_m * 32 + mf * 16 + (l >> 2);
            int cc = warp_n * 64 + nf * 8 + (l & 3) * 2;
            *(float2*)(g_O + (size_t)(tbase + r0) * HIDN + hoff + cc) =
                make_float2(acc[mf][nf][0], acc[mf][nf][1]);
            *(float2*)(g_O + (size_t)(tbase + r0 + 8) * HIDN + hoff + cc) =
                make_float2(acc[mf][nf][2], acc[mf][nf][3]);
        }
}

// epilogue: RMSNorm(o) * w * gate * sigmoid(gate) -> fp16 U (hi only)
__global__ __launch_bounds__(256)
void epilogue_k(const float* __restrict__ gnw) {
    __shared__ float red[256];
    const int n = blockIdx.x, tid = threadIdx.x;
    float4 ov = *((const float4*)(g_O + (size_t)n*HIDN) + tid);
    float ss = ov.x*ov.x + ov.y*ov.y + ov.z*ov.z + ov.w*ov.w;
    red[tid] = ss;
    __syncthreads();
    for (int s = 128; s > 0; s >>= 1) {
        if (tid < s) red[tid] += red[tid + s];
        __syncthreads();
    }
    float rms = rsqrtf(red[0] * (1.f/HIDN) + 1e-5f);
    float4 gv = *((const float4*)(g_gate + (size_t)n*HIDN) + tid);
    float4 wv = *((const float4*)gnw + tid);
    float4 u;
    u.x = ov.x*rms*wv.x * gv.x / (1.f + expf(-gv.x));
    u.y = ov.y*rms*wv.y * gv.y / (1.f + expf(-gv.y));
    u.z = ov.z*rms*wv.z * gv.z / (1.f + expf(-gv.z));
    u.w = ov.w*rms*wv.w * gv.w / (1.f + expf(-gv.w));
    size_t off = (size_t)n*HIDN + tid*4;
    uint2 hu; hu.x = pack2h(u.x, u.y); hu.y = pack2h(u.z, u.w);
    *(uint2*)(g_Uh + off) = hu;
}

extern "C" void kernel_launch(void* const* d_in, const int* in_sizes, int n_in,
                              void* d_out, int out_size) {
    const float* x   = (const float*)d_in[0];
    const float* Wq  = (const float*)d_in[1];
    const float* Wk  = (const float*)d_in[2];
    const float* Wv  = (const float*)d_in[3];
    const float* Wg1 = (const float*)d_in[4];
    const float* Wg2 = (const float*)d_in[5];
    const float* gnw = (const float*)d_in[6];
    const float* Wo  = (const float*)d_in[7];
    float* out = (float*)d_out;

    __half *woh,*wol,*w2h,*w2l,*g1h,*uh;
    float* gate;
    cudaGetSymbolAddress((void**)&woh, g_Woh); cudaGetSymbolAddress((void**)&wol, g_Wol);
    cudaGetSymbolAddress((void**)&w2h, g_Wg2h); cudaGetSymbolAddress((void**)&w2l, g_Wg2l);
    cudaGetSymbolAddress((void**)&g1h, g_G1h);
    cudaGetSymbolAddress((void**)&uh, g_Uh);
    cudaGetSymbolAddress((void**)&gate, g_gate);

    cudaFuncSetAttribute(gemm_qkv_f16, cudaFuncAttributeMaxDynamicSharedMemorySize, GEMM_F16_SMEM);
    cudaFuncSetAttribute(gemm_wg1_f16, cudaFuncAttributeMaxDynamicSharedMemorySize, GEMM_F16_SMEM);
    cudaFuncSetAttribute(gemm_f16<0>, cudaFuncAttributeMaxDynamicSharedMemorySize, GEMM_F16_SMEM);
    cudaFuncSetAttribute(chunk_out_tc, cudaFuncAttributeMaxDynamicSharedMemorySize, CO2_SMEM);

    dim3 blk(256);
    convert_all<<<8448, blk>>>(x, Wq, Wk, Wv, Wo, Wg1, Wg2);
    gemm_qkv_f16<<<dim3(24,32), blk, GEMM_F16_SMEM>>>();
    gemm_wg1_f16<<<dim3(4,32), blk, GEMM_F16_SMEM>>>();
    g1_reduce<<<NROWS*128/1024, blk>>>();
    gemm_f16<0><<<dim3(8,32), blk, GEMM_F16_SMEM>>>(g1h, w2h, w2l, gate, HIDN, 128);
    chunk_stats<<<dim3(NCHUNK, NBH), blk>>>();
    scan_asum<<<NBH, DKK>>>();
    scan_cc<<<dim3(64, NBH), 256>>>();
    transpose_v<<<dim3(64, 4*NBH), blk>>>();
    compute_qhat<<<dim3(NCHUNK, NBH), DKK>>>();
    chunk_out_tc<<<dim3(NCHUNK, NBH), blk, CO2_SMEM>>>();
    epilogue_k<<<NROWS, blk>>>(gnw);
    gemm_f16<0><<<dim3(8,32), blk, GEMM_F16_SMEM>>>(uh, woh, wol, out, HIDN, HIDN);
}

// round 13
// speedup vs baseline: 2.0185x; 1.1611x over previous
#include <cuda_runtime.h>
#include <cuda_bf16.h>
#include <cuda_fp16.h>
#include <cstdint>
#include <math.h>

// Problem dims
#define BB 2
#define TT 2048
#define HIDN 1024
#define NH 8
#define DKK 128
#define NROWS (BB*TT)      // 4096
#define TCH 128
#define NCHUNK (TT/TCH)    // 16
#define NBH (BB*NH)        // 16

#define SMEM_SWZ(off) ((off) ^ (((off) >> 3) & 0x70))
typedef __nv_bfloat16 bf16;

// -------- fp32 scratch --------
__device__ float g_Q[NROWS*HIDN];
__device__ float g_EK[NROWS*HIDN];     // raw k (projection output)
__device__ float g_V[NROWS*HIDN];
__device__ float g_gate[NROWS*HIDN];
__device__ float g_O[NROWS*HIDN];
__device__ float g_Asum[NBH*NCHUNK*DKK];
__device__ float g_CcT[NBH*NCHUNK*DKK*DKK];   // per-chunk (V^T EK) = Cc^T [dv][dk]
__device__ float g_G1part[4*NROWS*128];       // split-K partials for Wg1
// -------- fp16 scratch (projection path, 2-term split) --------
__device__ __half g_xh[NROWS*HIDN];
__device__ __half g_Wqh[HIDN*HIDN],  g_Wql[HIDN*HIDN];
__device__ __half g_Wkh[HIDN*HIDN],  g_Wkl[HIDN*HIDN];
__device__ __half g_Wvh[HIDN*HIDN],  g_Wvl[HIDN*HIDN];
__device__ __half g_Woh[HIDN*HIDN],  g_Wol[HIDN*HIDN];
__device__ __half g_Wg1h[128*HIDN],  g_Wg1l[128*HIDN];
__device__ __half g_Wg2h[HIDN*128],  g_Wg2l[HIDN*128];
__device__ __half g_G1h[NROWS*128];
__device__ __half g_Uh[NROWS*HIDN];
// -------- split-bf16 scratch (attention path, 3-term split) --------
__device__ bf16 g_EKhi[NROWS*HIDN], g_EKlo[NROWS*HIDN];   // exp(k), natural [t, dk]
__device__ bf16 g_QHhi[NROWS*HIDN], g_QHlo[NROWS*HIDN];   // qhat, natural [t, dk]
__device__ bf16 g_VThi[NBH*DKK*TT], g_VTlo[NBH*DKK*TT];   // [bh][dv][t]
__device__ bf16 g_CcThi[NBH*NCHUNK*DKK*DKK], g_CcTlo[NBH*NCHUNK*DKK*DKK]; // excl prefix

// ================= helpers =================
__device__ __forceinline__ uint32_t smem_u32(const void* p) {
    uint32_t a;
    asm("{ .reg .u64 t; cvta.to.shared.u64 t, %1; cvt.u32.u64 %0, t; }" : "=r"(a) : "l"(p));
    return a;
}
__device__ __forceinline__ void ldsm4(uint32_t* r, uint32_t addr) {
    asm volatile("ldmatrix.sync.aligned.m8n8.x4.shared.b16 {%0,%1,%2,%3}, [%4];"
        : "=r"(r[0]), "=r"(r[1]), "=r"(r[2]), "=r"(r[3]) : "r"(addr));
}
__device__ __forceinline__ void mma_bf16(float* d, const uint32_t* a, const uint32_t* b) {
    asm volatile("mma.sync.aligned.m16n8k16.row.col.f32.bf16.bf16.f32 "
        "{%0,%1,%2,%3}, {%4,%5,%6,%7}, {%8,%9}, {%0,%1,%2,%3};"
        : "+f"(d[0]), "+f"(d[1]), "+f"(d[2]), "+f"(d[3])
        : "r"(a[0]), "r"(a[1]), "r"(a[2]), "r"(a[3]), "r"(b[0]), "r"(b[1]));
}
__device__ __forceinline__ void mma_f16(float* d, const uint32_t* a, const uint32_t* b) {
    asm volatile("mma.sync.aligned.m16n8k16.row.col.f32.f16.f16.f32 "
        "{%0,%1,%2,%3}, {%4,%5,%6,%7}, {%8,%9}, {%0,%1,%2,%3};"
        : "+f"(d[0]), "+f"(d[1]), "+f"(d[2]), "+f"(d[3])
        : "r"(a[0]), "r"(a[1]), "r"(a[2]), "r"(a[3]), "r"(b[0]), "r"(b[1]));
}
#define CP_ASYNC16(dst, src) \
    asm volatile("cp.async.cg.shared.global [%0], [%1], 16;" :: "r"(dst), "l"(src) : "memory")
#define CP_COMMIT() asm volatile("cp.async.commit_group;" ::: "memory")
#define CP_WAIT2()  asm volatile("cp.async.wait_group 2;" ::: "memory")
#define CP_WAIT0()  asm volatile("cp.async.wait_group 0;" ::: "memory")

__device__ __forceinline__ void split2(float v0, float v1, uint32_t& h, uint32_t& lo) {
    bf16 h0 = __float2bfloat16_rn(v0), h1 = __float2bfloat16_rn(v1);
    bf16 l0 = __float2bfloat16_rn(v0 - __bfloat162float(h0));
    bf16 l1 = __float2bfloat16_rn(v1 - __bfloat162float(h1));
    __nv_bfloat162 hp = __halves2bfloat162(h0, h1);
    __nv_bfloat162 lp = __halves2bfloat162(l0, l1);
    h = *(uint32_t*)&hp; lo = *(uint32_t*)&lp;
}
__device__ __forceinline__ void split2h(float v0, float v1, uint32_t& h, uint32_t& lo) {
    __half h0 = __float2half_rn(v0), h1 = __float2half_rn(v1);
    __half l0 = __float2half_rn(v0 - __half2float(h0));
    __half l1 = __float2half_rn(v1 - __half2float(h1));
    __half2 hp = __halves2half2(h0, h1);
    __half2 lp = __halves2half2(l0, l1);
    h = *(uint32_t*)&hp; lo = *(uint32_t*)&lp;
}
__device__ __forceinline__ uint32_t pack2h(float v0, float v1) {
    __half2 hp = __halves2half2(__float2half_rn(v0), __float2half_rn(v1));
    return *(uint32_t*)&hp;
}
__device__ __forceinline__ void store_pair_split(bf16* Chi, bf16* Clo, size_t off,
                                                 float v0, float v1) {
    uint32_t h, lo; split2(v0, v1, h, lo);
    *(uint32_t*)(Chi + off) = h;
    *(uint32_t*)(Clo + off) = lo;
}

// shared 64-K-wide 3-term bf16 MMA block (attention path)
__device__ __forceinline__ void mma_block64(float acc[2][8][4],
        uint32_t sAhi, uint32_t sAlo, uint32_t sBhi, uint32_t sBlo,
        int a_row, int a_kb, int b_row, int b_kb) {
#pragma unroll
    for (int ks = 0; ks < 4; ks++) {
        const int koff = ks * 32;
        uint32_t Ah[2][4], Al[2][4], Bh[4][4], Bl[4][4];
#pragma unroll
        for (int mf = 0; mf < 2; mf++) {
            uint32_t ro = SMEM_SWZ((uint32_t)((a_row + mf * 16) * 128 + koff + a_kb));
            ldsm4(Ah[mf], sAhi + ro);
            ldsm4(Al[mf], sAlo + ro);
        }
#pragma unroll
        for (int nf2 = 0; nf2 < 4; nf2++) {
            uint32_t ro = SMEM_SWZ((uint32_t)((b_row + nf2 * 16) * 128 + koff + b_kb));
            ldsm4(Bh[nf2], sBhi + ro);
            ldsm4(Bl[nf2], sBlo + ro);
        }
#pragma unroll
        for (int mf = 0; mf < 2; mf++)
#pragma unroll
            for (int nf = 0; nf < 8; nf++) {
                const int nf2 = nf >> 1, ho = (nf & 1) * 2;
                mma_bf16(acc[mf][nf], Ah[mf], &Bh[nf2][ho]);
                mma_bf16(acc[mf][nf], Ah[mf], &Bl[nf2][ho]);
                mma_bf16(acc[mf][nf], Al[mf], &Bh[nf2][ho]);
            }
    }
}

// 64-K-wide 2-term fp16 MMA block (projection path: A hi-only, B hi+lo)
__device__ __forceinline__ void mma_block64_f16(float acc[2][8][4],
        uint32_t sA, uint32_t sBh, uint32_t sBl,
        int a_row, int a_kb, int b_row, int b_kb) {
#pragma unroll
    for (int ks = 0; ks < 4; ks++) {
        const int koff = ks * 32;
        uint32_t Ah[2][4], Bh[4][4], Bl[4][4];
#pragma unroll
        for (int mf = 0; mf < 2; mf++) {
            uint32_t ro = SMEM_SWZ((uint32_t)((a_row + mf * 16) * 128 + koff + a_kb));
            ldsm4(Ah[mf], sA + ro);
        }
#pragma unroll
        for (int nf2 = 0; nf2 < 4; nf2++) {
            uint32_t ro = SMEM_SWZ((uint32_t)((b_row + nf2 * 16) * 128 + koff + b_kb));
            ldsm4(Bh[nf2], sBh + ro);
            ldsm4(Bl[nf2], sBl + ro);
        }
#pragma unroll
        for (int mf = 0; mf < 2; mf++)
#pragma unroll
            for (int nf = 0; nf < 8; nf++) {
                const int nf2 = nf >> 1, ho = (nf & 1) * 2;
                mma_f16(acc[mf][nf], Ah[mf], &Bh[nf2][ho]);
                mma_f16(acc[mf][nf], Ah[mf], &Bl[nf2][ho]);
            }
    }
}

// ================ merged split conversion ================
__global__ __launch_bounds__(256)
void convert_all(const float* __restrict__ x,  const float* __restrict__ Wq,
                 const float* __restrict__ Wk, const float* __restrict__ Wv,
                 const float* __restrict__ Wo, const float* __restrict__ Wg1,
                 const float* __restrict__ Wg2) {
    int bx = blockIdx.x;
    const float* src; __half *hi, *lo; int lb; int full;
    if      (bx < 4096) { src = x;   hi = g_xh;   lo = nullptr; lb = bx;        full = 0; }
    else if (bx < 5120) { src = Wq;  hi = g_Wqh;  lo = g_Wql;   lb = bx - 4096; full = 1; }
    else if (bx < 6144) { src = Wk;  hi = g_Wkh;  lo = g_Wkl;   lb = bx - 5120; full = 1; }
    else if (bx < 7168) { src = Wv;  hi = g_Wvh;  lo = g_Wvl;   lb = bx - 6144; full = 1; }
    else if (bx < 8192) { src = Wo;  hi = g_Woh;  lo = g_Wol;   lb = bx - 7168; full = 1; }
    else if (bx < 8320) { src = Wg1; hi = g_Wg1h; lo = g_Wg1l;  lb = bx - 8192; full = 1; }
    else                { src = Wg2; hi = g_Wg2h; lo = g_Wg2l;  lb = bx - 8320; full = 1; }
    int i = (lb * 256 + threadIdx.x) * 4;
    float4 v = *(const float4*)(src + i);
    if (!full) {
        uint2 hu; hu.x = pack2h(v.x, v.y); hu.y = pack2h(v.z, v.w);
        *(uint2*)(hi + i) = hu;
    } else {
        uint32_t h0, l0, h1, l1;
        split2h(v.x, v.y, h0, l0);
        split2h(v.z, v.w, h1, l1);
        uint2 hu; hu.x = h0; hu.y = h1;
        uint2 lu; lu.x = l0; lu.y = l1;
        *(uint2*)(hi + i) = hu;
        *(uint2*)(lo + i) = lu;
    }
}

// ============ fp16 2-term cp.async GEMM: C[M,N] = A[M,K] B[N,K]^T ============
#define F16_STG 49152
#define NSTAGE 3
#define GEMM_F16_SMEM (NSTAGE*F16_STG + 1024)

__device__ __forceinline__ void issue_stage_f16(uint32_t sa,
        const __half* __restrict__ A, const __half* __restrict__ Bh,
        const __half* __restrict__ Bl,
        int rowA, int rowB, int Kstride, int k0, int tid) {
#pragma unroll
    for (int t = 0; t < 12; t++) {
        const int tile = t >> 2;
        int idx = t * 256 + tid;
        int r = (idx >> 3) & 127;
        int c16 = idx & 7;
        const __half* base = (tile == 0) ? A : (tile == 1) ? Bh : Bl;
        int rowg = ((tile == 0) ? rowA : rowB) + r;
        const void* src = base + (size_t)rowg * Kstride + k0 + c16 * 8;
        uint32_t dst = sa + tile * 16384 + SMEM_SWZ((uint32_t)(r * 128 + c16 * 16));
        CP_ASYNC16(dst, src);
    }
}

__device__ __forceinline__ void gemm_core_f16(
        const __half* __restrict__ A, const __half* __restrict__ Bh,
        const __half* __restrict__ Bl, float* __restrict__ C,
        int N, int Kloop, int Kstride, int rowA, int rowB, int act) {
    extern __shared__ char dynsm[];
    char* tile = (char*)((((uintptr_t)dynsm) + 1023) & ~(uintptr_t)1023);
    const uint32_t sa0 = smem_u32(tile);
    const int tid = threadIdx.x;
    const int wid = tid >> 5, l = tid & 31;
    const int warp_m = wid >> 1, warp_n = wid & 1;

    float acc[2][8][4];
#pragma unroll
    for (int mf = 0; mf < 2; mf++)
#pragma unroll
        for (int nf = 0; nf < 8; nf++)
#pragma unroll
            for (int j = 0; j < 4; j++) acc[mf][nf][j] = 0.f;

    const int a_row = warp_m * 32 + (l & 15);
    const int a_kb  = (l >> 4) * 16;
    const int b_row = warp_n * 64 + (l & 7) + ((l >> 4) & 1) * 8;
    const int b_kb  = ((l >> 3) & 1) * 16;

    const int nk = Kloop >> 6;
#pragma unroll
    for (int s = 0; s < NSTAGE; s++) {
        if (s < nk) issue_stage_f16(sa0 + s * F16_STG, A, Bh, Bl, rowA, rowB, Kstride, s << 6, tid);
        CP_COMMIT();
    }
    int sidx = 0;
    for (int kb = 0; kb < nk; kb++) {
        CP_WAIT2();
        __syncthreads();
        const uint32_t st = sa0 + sidx * F16_STG;
        mma_block64_f16(acc, st, st + 16384, st + 32768, a_row, a_kb, b_row, b_kb);
        __syncthreads();
        if (kb + NSTAGE < nk)
            issue_stage_f16(sa0 + sidx * F16_STG, A, Bh, Bl, rowA, rowB, Kstride, (kb + NSTAGE) << 6, tid);
        CP_COMMIT();
        sidx = (sidx + 1 == NSTAGE) ? 0 : sidx + 1;
    }

#pragma unroll
    for (int mf = 0; mf < 2; mf++)
#pragma unroll
        for (int nf = 0; nf < 8; nf++) {
            int r0 = rowA + warp_m * 32 + mf * 16 + (l >> 2);
            int cc = rowB + warp_n * 64 + nf * 8 + (l & 3) * 2;
            float v0 = acc[mf][nf][0], v1 = acc[mf][nf][1];
            float v2 = acc[mf][nf][2], v3 = acc[mf][nf][3];
            if (act) {
                v0 = v0 / (1.f + expf(-v0));
                v1 = v1 / (1.f + expf(-v1));
                v2 = v2 / (1.f + expf(-v2));
                v3 = v3 / (1.f + expf(-v3));
            }
            *(float2*)(C + (size_t)r0 * N + cc)       = make_float2(v0, v1);
            *(float2*)(C + (size_t)(r0 + 8) * N + cc) = make_float2(v2, v3);
        }
}

template<int ACT>
__global__ __launch_bounds__(256, 1)
void gemm_f16(const __half* A, const __half* Bh, const __half* Bl,
              float* C, int N, int K) {
    gemm_core_f16(A, Bh, Bl, C, N, K, K, blockIdx.y * 128, blockIdx.x * 128, ACT);
}

// fused Q/K/V projection: grid (24, 32); which = bx>>3
__global__ __launch_bounds__(256, 1)
void gemm_qkv_f16() {
    const int which = blockIdx.x >> 3;
    const int colb = blockIdx.x & 7;
    const __half *Bh, *Bl;
    float* C;
    if (which == 0)      { Bh = g_Wqh; Bl = g_Wql; C = g_Q; }
    else if (which == 1) { Bh = g_Wkh; Bl = g_Wkl; C = g_EK; }
    else                 { Bh = g_Wvh; Bl = g_Wvl; C = g_V; }
    gemm_core_f16(g_xh, Bh, Bl, C, HIDN, HIDN, HIDN,
                  blockIdx.y * 128, colb * 128, which == 0);
}

// split-K Wg1: grid (4, 32)
__global__ __launch_bounds__(256, 1)
void gemm_wg1_f16() {
    const int ks = blockIdx.x;
    gemm_core_f16(g_xh + ks * 256, g_Wg1h + ks * 256, g_Wg1l + ks * 256,
                  g_G1part + (size_t)ks * NROWS * 128,
                  128, 256, HIDN, blockIdx.y * 128, 0, 0);
}

__global__ __launch_bounds__(256)
void g1_reduce() {
    int i = (blockIdx.x * 256 + threadIdx.x) * 4;   // over NROWS*128
    const int S = NROWS * 128;
    float4 a = *(float4*)(g_G1part + i);
    float4 b = *(float4*)(g_G1part + S + i);
    float4 c = *(float4*)(g_G1part + 2*S + i);
    float4 d = *(float4*)(g_G1part + 3*S + i);
    uint2 hu;
    hu.x = pack2h(a.x + b.x + c.x + d.x, a.y + b.y + c.y + d.y);
    hu.y = pack2h(a.z + b.z + c.z + d.z, a.w + b.w + c.w + d.w);
    *(uint2*)(g_G1h + i) = hu;
}

// ================ transpose V -> split bf16 VT[bh][dv][t] ================
__global__ __launch_bounds__(256)
void transpose_v() {
    __shared__ float tile[32][33];
    const int ttile = blockIdx.x;            // 0..63
    const int dvt = blockIdx.y & 3, bh = blockIdx.y >> 2;
    const int b = bh >> 3, h = bh & 7;
    const int t0 = ttile * 32, dv0 = dvt * 32;
    const int lx = threadIdx.x & 31, ly = threadIdx.x >> 5;
#pragma unroll
    for (int i = 0; i < 4; i++) {
        int r = ly + i * 8;
        tile[r][lx] = g_V[(size_t)(b * TT + t0 + r) * HIDN + h * DKK + dv0 + lx];
    }
    __syncthreads();
#pragma unroll
    for (int i = 0; i < 4; i++) {
        int r = ly + i * 8;
        float v = tile[lx][r];
        bf16 hh = __float2bfloat16_rn(v);
        bf16 ll = __float2bfloat16_rn(v - __bfloat162float(hh));
        size_t oa = ((size_t)bh * DKK + dv0 + r) * TT + t0 + lx;
        g_VThi[oa] = hh;
        g_VTlo[oa] = ll;
    }
}

// ================= attention kernels ==================
#define MICRO_FMA(Aptr, Bptr, kk) do {                                    \
    float4 a0 = *(const float4*)&(Aptr)[(kk)*132 + ty*4];                 \
    float4 a1 = *(const float4*)&(Aptr)[(kk)*132 + 64 + ty*4];            \
    float4 b0 = *(const float4*)&(Bptr)[(kk)*132 + tx*4];                 \
    float4 b1 = *(const float4*)&(Bptr)[(kk)*132 + 64 + tx*4];            \
    float av[8] = {a0.x,a0.y,a0.z,a0.w,a1.x,a1.y,a1.z,a1.w};              \
    float bv[8] = {b0.x,b0.y,b0.z,b0.w,b1.x,b1.y,b1.z,b1.w};              \
    _Pragma("unroll") for (int ii=0; ii<8; ii++)                          \
      _Pragma("unroll") for (int jj=0; jj<8; jj++)                        \
        acc[ii][jj] += av[ii]*bv[jj];                                     \
} while(0)

__device__ __forceinline__ int fragmap(int idx, int t4) {
    return (idx < 4) ? (t4*4 + idx) : (64 + t4*4 + idx - 4);
}

// exp(k) -> split bf16 out, per-chunk colsum, CcT = V^T EK (fp32)
__global__ __launch_bounds__(256)
void chunk_stats() {
    const int c = blockIdx.x, bh = blockIdx.y;
    const int b = bh >> 3, h = bh & 7;
    const int base = b*TT + c*TCH;
    const int hoff = h*DKK;
    __shared__ float EKs[8*132];
    __shared__ float Vs[8*132];
    __shared__ float red[8*128];
    const int tid = threadIdx.x;
    const int tx = tid & 15, ty = tid >> 4;
    const int trow = tid >> 5;
    const int col = (tid & 31) << 2;
    float acc[8][8];
#pragma unroll
    for (int i = 0; i < 8; i++)
#pragma unroll
        for (int j = 0; j < 8; j++) acc[i][j] = 0.f;
    float ps0 = 0.f, ps1 = 0.f, ps2 = 0.f, ps3 = 0.f;

    for (int tt = 0; tt < TCH/8; tt++) {
        int row = base + tt*8 + trow;
        size_t gi = (size_t)row*HIDN + hoff + col;
        float4 kv = *(const float4*)(g_EK + gi);
        kv.x = expf(kv.x); kv.y = expf(kv.y); kv.z = expf(kv.z); kv.w = expf(kv.w);
        uint32_t h0, l0, h1, l1;
        split2(kv.x, kv.y, h0, l0);
        split2(kv.z, kv.w, h1, l1);
        uint2 hu; hu.x = h0; hu.y = h1;
        uint2 lu; lu.x = l0; lu.y = l1;
        *(uint2*)(g_EKhi + gi) = hu;
        *(uint2*)(g_EKlo + gi) = lu;
        ps0 += kv.x; ps1 += kv.y; ps2 += kv.z; ps3 += kv.w;
        *(float4*)&EKs[trow*132 + col] = kv;
        float4 vv = *(const float4*)(g_V + gi);
        *(float4*)&Vs[trow*132 + col] = vv;
        __syncthreads();
#pragma unroll
        for (int k = 0; k < 8; k++) MICRO_FMA(Vs, EKs, k);   // acc[dv][dk] = CcT
        __syncthreads();
    }
    red[trow*128 + col + 0] = ps0; red[trow*128 + col + 1] = ps1;
    red[trow*128 + col + 2] = ps2; red[trow*128 + col + 3] = ps3;
    __syncthreads();
    if (tid < DKK) {
        float s = 0.f;
#pragma unroll
        for (int r = 0; r < 8; r++) s += red[r*128 + tid];
        g_Asum[(bh*NCHUNK + c)*DKK + tid] = s;
    }
    size_t cb = ((size_t)(bh*NCHUNK + c))*DKK*DKK;
#pragma unroll
    for (int i = 0; i < 8; i++) {
        int dv = fragmap(i, ty);
        float4 s0 = make_float4(acc[i][0], acc[i][1], acc[i][2], acc[i][3]);
        float4 s1 = make_float4(acc[i][4], acc[i][5], acc[i][6], acc[i][7]);
        *(float4*)(g_CcT + cb + (size_t)dv*DKK + tx*4)      = s0;
        *(float4*)(g_CcT + cb + (size_t)dv*DKK + 64 + tx*4) = s1;
    }
}

// exclusive prefix of Asum across chunks (loads hoisted -> MLP 16)
__global__ void scan_asum() {
    int bh = blockIdx.x, dk = threadIdx.x;
    float v[NCHUNK];
#pragma unroll
    for (int c = 0; c < NCHUNK; c++)
        v[c] = g_Asum[(bh*NCHUNK + c)*DKK + dk];
    float run = 0.f;
#pragma unroll
    for (int c = 0; c < NCHUNK; c++) {
        g_Asum[(bh*NCHUNK + c)*DKK + dk] = run;
        run += v[c];
    }
}
// exclusive prefix of CcT across chunks -> split bf16 (loads hoisted -> MLP 16)
__global__ void scan_cc() {
    int bh = blockIdx.y;
    int idx = blockIdx.x*256 + threadIdx.x;
    size_t base = (size_t)bh*NCHUNK*(DKK*DKK) + idx;
    float v[NCHUNK];
#pragma unroll
    for (int c = 0; c < NCHUNK; c++)
        v[c] = g_CcT[base + (size_t)c*(DKK*DKK)];
    float run = 0.f;
#pragma unroll
    for (int c = 0; c < NCHUNK; c++) {
        size_t p = base + (size_t)c*(DKK*DKK);
        bf16 hh = __float2bfloat16_rn(run);
        bf16 ll = __float2bfloat16_rn(run - __bfloat162float(hh));
        g_CcThi[p] = hh; g_CcTlo[p] = ll;
        run += v[c];
    }
}

// Qhat = silu(q)/A_t * scale -> split bf16 (8-deep prefetched; EK from hi+lo)
__global__ void compute_qhat() {
    const int c = blockIdx.x, bh = blockIdx.y;
    const int b = bh >> 3, h = bh & 7;
    const int base = b*TT + c*TCH;
    const int dk = threadIdx.x;
    const float scale = 0.08838834764831845f;
    float run = g_Asum[(bh*NCHUNK + c)*DKK + dk];
    const size_t g0 = (size_t)base*HIDN + h*DKK + dk;
    for (int tb = 0; tb < TCH; tb += 8) {
        float ek[8], qq[8];
#pragma unroll
        for (int i = 0; i < 8; i++) {
            size_t gi = g0 + (size_t)(tb + i)*HIDN;
            ek[i] = __bfloat162float(g_EKhi[gi]) + __bfloat162float(g_EKlo[gi]);
            qq[i] = g_Q[gi];
        }
#pragma unroll
        for (int i = 0; i < 8; i++) {
            run += ek[i];
            float qh = qq[i] / run * scale;
            size_t gi = g0 + (size_t)(tb + i)*HIDN;
            bf16 hh = __float2bfloat16_rn(qh);
            bf16 ll = __float2bfloat16_rn(qh - __bfloat162float(hh));
            g_QHhi[gi] = hh; g_QHlo[gi] = ll;
        }
    }
}

// generic 128x128 operand loader into hi/lo smem (two 16KB K-halves each)
__device__ __forceinline__ void load_op(uint32_t shi, uint32_t slo,
        const bf16* __restrict__ ghi, const bf16* __restrict__ glo,
        size_t rstride, int tid) {
#pragma unroll
    for (int t = 0; t < 8; t++) {
        int idx = t * 256 + tid;
        int r = idx >> 4;
        int c16 = idx & 15;
        uint32_t off = (uint32_t)((c16 >> 3) * 16384) + SMEM_SWZ((uint32_t)(r * 128 + (c16 & 7) * 16));
        CP_ASYNC16(shi + off, ghi + (size_t)r * rstride + c16 * 8);
        CP_ASYNC16(slo + off, glo + (size_t)r * rstride + c16 * 8);
    }
}

// ====== chunk_out (tensor core): O = tril(QH EK^T) V + QH Cc ======
#define CO2_SMEM (6*32768 + 1024)
__global__ __launch_bounds__(256, 1)
void chunk_out_tc() {
    extern __shared__ char dynsm[];
    char* smb = (char*)((((uintptr_t)dynsm) + 1023) & ~(uintptr_t)1023);
    const uint32_t sa = smem_u32(smb);
    const int c = blockIdx.x, bh = blockIdx.y;
    const int b = bh >> 3, h = bh & 7;
    const int tbase = b*TT + c*TCH;
    const int hoff = h*DKK;
    const int tid = threadIdx.x, wid = tid >> 5, l = tid & 31;
    const int warp_m = wid >> 1, warp_n = wid & 1;
    const int a_row = warp_m * 32 + (l & 15);
    const int a_kb  = (l >> 4) * 16;
    const int b_row = warp_n * 64 + (l & 7) + ((l >> 4) & 1) * 8;
    const int b_kb  = ((l >> 3) & 1) * 16;

    const uint32_t QHI = sa, QLO = sa + 32768;
    const uint32_t BHI = sa + 65536, BLO = sa + 98304;
    const uint32_t PHI = sa + 131072, PLO = sa + 163840;
    char* Pc_hi = smb + 131072;
    char* Pc_lo = smb + 163840;

    load_op(QHI, QLO, g_QHhi + (size_t)tbase*HIDN + hoff, g_QHlo + (size_t)tbase*HIDN + hoff, HIDN, tid);
    load_op(BHI, BLO, g_EKhi + (size_t)tbase*HIDN + hoff, g_EKlo + (size_t)tbase*HIDN + hoff, HIDN, tid);
    CP_COMMIT(); CP_WAIT0(); __syncthreads();

    float acc[2][8][4];
#pragma unroll
    for (int mf = 0; mf < 2; mf++)
#pragma unroll
        for (int nf = 0; nf < 8; nf++)
#pragma unroll
            for (int j = 0; j < 4; j++) acc[mf][nf][j] = 0.f;

    // stage 1: P = QH * EK^T
#pragma unroll
    for (int kc = 0; kc < 2; kc++)
        mma_block64(acc, QHI + kc*16384, QLO + kc*16384, BHI + kc*16384, BLO + kc*16384,
                    a_row, a_kb, b_row, b_kb);
    __syncthreads();

    load_op(BHI, BLO, g_CcThi + (size_t)(bh*NCHUNK + c)*(DKK*DKK),
                       g_CcTlo + (size_t)(bh*NCHUNK + c)*(DKK*DKK), DKK, tid);
    CP_COMMIT();

    // causal mask + store P to smem (split bf16)
#pragma unroll
    for (int mf = 0; mf < 2; mf++)
#pragma unroll
        for (int nf = 0; nf < 8; nf++) {
            int r0 = warp_m * 32 + mf * 16 + (l >> 2);
            int cc = warp_n * 64 + nf * 8 + (l & 3) * 2;
            float v0 = (cc     <= r0) ? acc[mf][nf][0] : 0.f;
            float v1 = (cc + 1 <= r0) ? acc[mf][nf][1] : 0.f;
            float v2 = (cc     <= r0 + 8) ? acc[mf][nf][2] : 0.f;
            float v3 = (cc + 1 <= r0 + 8) ? acc[mf][nf][3] : 0.f;
            uint32_t ch = (uint32_t)((cc >> 6) * 16384);
            uint32_t o0 = ch + SMEM_SWZ((uint32_t)(r0 * 128 + (cc & 63) * 2));
            uint32_t o1 = ch + SMEM_SWZ((uint32_t)((r0 + 8) * 128 + (cc & 63) * 2));
            uint32_t hh, ll;
            split2(v0, v1, hh, ll);
            *(uint32_t*)(Pc_hi + o0) = hh; *(uint32_t*)(Pc_lo + o0) = ll;
            split2(v2, v3, hh, ll);
            *(uint32_t*)(Pc_hi + o1) = hh; *(uint32_t*)(Pc_lo + o1) = ll;
        }
    CP_WAIT0(); __syncthreads();

    // stage 2b: O = QH * CcT^T
#pragma unroll
    for (int mf = 0; mf < 2; mf++)
#pragma unroll
        for (int nf = 0; nf < 8; nf++)
#pragma unroll
            for (int j = 0; j < 4; j++) acc[mf][nf][j] = 0.f;
#pragma unroll
    for (int kc = 0; kc < 2; kc++)
        mma_block64(acc, QHI + kc*16384, QLO + kc*16384, BHI + kc*16384, BLO + kc*16384,
                    a_row, a_kb, b_row, b_kb);
    __syncthreads();

    load_op(QHI, QLO, g_VThi + (size_t)bh*DKK*TT + c*TCH,
                       g_VTlo + (size_t)bh*DKK*TT + c*TCH, TT, tid);
    CP_COMMIT(); CP_WAIT0(); __syncthreads();

    // stage 2a: O += P * VT^T
#pragma unroll
    for (int kc = 0; kc < 2; kc++)
        mma_block64(acc, PHI + kc*16384, PLO + kc*16384, QHI + kc*16384, QLO + kc*16384,
                    a_row, a_kb, b_row, b_kb);

#pragma unroll
    for (int mf = 0; mf < 2; mf++)
#pragma unroll
        for (int nf = 0; nf < 8; nf++) {
            int r0 = warp_m * 32 + mf * 16 + (l >> 2);
            int cc = warp_n * 64 + nf * 8 + (l & 3) * 2;
            *(float2*)(g_O + (size_t)(tbase + r0) * HIDN + hoff + cc) =
                make_float2(acc[mf][nf][0], acc[mf][nf][1]);
            *(float2*)(g_O + (size_t)(tbase + r0 + 8) * HIDN + hoff + cc) =
                make_float2(acc[mf][nf][2], acc[mf][nf][3]);
        }
}

// epilogue: RMSNorm(o) * w * gate * sigmoid(gate) -> fp16 U (hi only)
__global__ __launch_bounds__(256)
void epilogue_k(const float* __restrict__ gnw) {
    __shared__ float red[256];
    const int n = blockIdx.x, tid = threadIdx.x;
    float4 ov = *((const float4*)(g_O + (size_t)n*HIDN) + tid);
    float ss = ov.x*ov.x + ov.y*ov.y + ov.z*ov.z + ov.w*ov.w;
    red[tid] = ss;
    __syncthreads();
    for (int s = 128; s > 0; s >>= 1) {
        if (tid < s) red[tid] += red[tid + s];
        __syncthreads();
    }
    float rms = rsqrtf(red[0] * (1.f/HIDN) + 1e-5f);
    float4 gv = *((const float4*)(g_gate + (size_t)n*HIDN) + tid);
    float4 wv = *((const float4*)gnw + tid);
    float4 u;
    u.x = ov.x*rms*wv.x * gv.x / (1.f + expf(-gv.x));
    u.y = ov.y*rms*wv.y * gv.y / (1.f + expf(-gv.y));
    u.z = ov.z*rms*wv.z * gv.z / (1.f + expf(-gv.z));
    u.w = ov.w*rms*wv.w * gv.w / (1.f + expf(-gv.w));
    size_t off = (size_t)n*HIDN + tid*4;
    uint2 hu; hu.x = pack2h(u.x, u.y); hu.y = pack2h(u.z, u.w);
    *(uint2*)(g_Uh + off) = hu;
}

extern "C" void kernel_launch(void* const* d_in, const int* in_sizes, int n_in,
                              void* d_out, int out_size) {
    const float* x   = (const float*)d_in[0];
    const float* Wq  = (const float*)d_in[1];
    const float* Wk  = (const float*)d_in[2];
    const float* Wv  = (const float*)d_in[3];
    const float* Wg1 = (const float*)d_in[4];
    const float* Wg2 = (const float*)d_in[5];
    const float* gnw = (const float*)d_in[6];
    const float* Wo  = (const float*)d_in[7];
    float* out = (float*)d_out;

    __half *woh,*wol,*w2h,*w2l,*g1h,*uh;
    float* gate;
    cudaGetSymbolAddress((void**)&woh, g_Woh); cudaGetSymbolAddress((void**)&wol, g_Wol);
    cudaGetSymbolAddress((void**)&w2h, g_Wg2h); cudaGetSymbolAddress((void**)&w2l, g_Wg2l);
    cudaGetSymbolAddress((void**)&g1h, g_G1h);
    cudaGetSymbolAddress((void**)&uh, g_Uh);
    cudaGetSymbolAddress((void**)&gate, g_gate);

    cudaFuncSetAttribute(gemm_qkv_f16, cudaFuncAttributeMaxDynamicSharedMemorySize, GEMM_F16_SMEM);
    cudaFuncSetAttribute(gemm_wg1_f16, cudaFuncAttributeMaxDynamicSharedMemorySize, GEMM_F16_SMEM);
    cudaFuncSetAttribute(gemm_f16<0>, cudaFuncAttributeMaxDynamicSharedMemorySize, GEMM_F16_SMEM);
    cudaFuncSetAttribute(chunk_out_tc, cudaFuncAttributeMaxDynamicSharedMemorySize, CO2_SMEM);

    dim3 blk(256);
    convert_all<<<8448, blk>>>(x, Wq, Wk, Wv, Wo, Wg1, Wg2);
    gemm_qkv_f16<<<dim3(24,32), blk, GEMM_F16_SMEM>>>();
    gemm_wg1_f16<<<dim3(4,32), blk, GEMM_F16_SMEM>>>();
    g1_reduce<<<NROWS*128/1024, blk>>>();
    gemm_f16<0><<<dim3(8,32), blk, GEMM_F16_SMEM>>>(g1h, w2h, w2l, gate, HIDN, 128);
    chunk_stats<<<dim3(NCHUNK, NBH), blk>>>();
    scan_asum<<<NBH, DKK>>>();
    scan_cc<<<dim3(64, NBH), 256>>>();
    transpose_v<<<dim3(64, 4*NBH), blk>>>();
    compute_qhat<<<dim3(NCHUNK, NBH), DKK>>>();
    chunk_out_tc<<<dim3(NCHUNK, NBH), blk, CO2_SMEM>>>();
    epilogue_k<<<NROWS, blk>>>(gnw);
    gemm_f16<0><<<dim3(8,32), blk, GEMM_F16_SMEM>>>(uh, woh, wol, out, HIDN, HIDN);
}

// round 16
// speedup vs baseline: 2.0570x; 1.0190x over previous
#include <cuda_runtime.h>
#include <cuda_bf16.h>
#include <cuda_fp16.h>
#include <cstdint>
#include <math.h>

// Problem dims
#define BB 2
#define TT 2048
#define HIDN 1024
#define NH 8
#define DKK 128
#define NROWS (BB*TT)      // 4096
#define TCH 128
#define NCHUNK (TT/TCH)    // 16
#define NBH (BB*NH)        // 16

#define SMEM_SWZ(off) ((off) ^ (((off) >> 3) & 0x70))
typedef __nv_bfloat16 bf16;

// -------- fp32 scratch --------
__device__ float g_Q[NROWS*HIDN];
__device__ float g_EK[NROWS*HIDN];     // raw k (projection output)
__device__ float g_V[NROWS*HIDN];
__device__ float g_gate[NROWS*HIDN];
__device__ float g_O[NROWS*HIDN];
__device__ float g_Asum[NBH*NCHUNK*DKK];
__device__ float g_CcT[NBH*NCHUNK*DKK*DKK];   // per-chunk (V^T EK) = Cc^T [dv][dk]
__device__ float g_G1part[4*NROWS*128];       // split-K partials for Wg1
// -------- fp16 scratch (projection path, 2-term split) --------
__device__ __half g_xh[NROWS*HIDN];
__device__ __half g_Wqh[HIDN*HIDN],  g_Wql[HIDN*HIDN];
__device__ __half g_Wkh[HIDN*HIDN],  g_Wkl[HIDN*HIDN];
__device__ __half g_Wvh[HIDN*HIDN],  g_Wvl[HIDN*HIDN];
__device__ __half g_Woh[HIDN*HIDN],  g_Wol[HIDN*HIDN];
__device__ __half g_Wg1h[128*HIDN],  g_Wg1l[128*HIDN];
__device__ __half g_Wg2h[HIDN*128],  g_Wg2l[HIDN*128];
__device__ __half g_G1h[NROWS*128];
__device__ __half g_Uh[NROWS*HIDN];
// -------- split-bf16 scratch (attention path, 3-term split) --------
__device__ bf16 g_EKhi[NROWS*HIDN], g_EKlo[NROWS*HIDN];   // exp(k), natural [t, dk]
__device__ bf16 g_QHhi[NROWS*HIDN], g_QHlo[NROWS*HIDN];   // qhat, natural [t, dk]
__device__ bf16 g_VThi[NBH*DKK*TT], g_VTlo[NBH*DKK*TT];   // [bh][dv][t]
__device__ bf16 g_CcThi[NBH*NCHUNK*DKK*DKK], g_CcTlo[NBH*NCHUNK*DKK*DKK]; // excl prefix

// ================= helpers =================
__device__ __forceinline__ uint32_t smem_u32(const void* p) {
    uint32_t a;
    asm("{ .reg .u64 t; cvta.to.shared.u64 t, %1; cvt.u32.u64 %0, t; }" : "=r"(a) : "l"(p));
    return a;
}
__device__ __forceinline__ void ldsm4(uint32_t* r, uint32_t addr) {
    asm volatile("ldmatrix.sync.aligned.m8n8.x4.shared.b16 {%0,%1,%2,%3}, [%4];"
        : "=r"(r[0]), "=r"(r[1]), "=r"(r[2]), "=r"(r[3]) : "r"(addr));
}
__device__ __forceinline__ void mma_bf16(float* d, const uint32_t* a, const uint32_t* b) {
    asm volatile("mma.sync.aligned.m16n8k16.row.col.f32.bf16.bf16.f32 "
        "{%0,%1,%2,%3}, {%4,%5,%6,%7}, {%8,%9}, {%0,%1,%2,%3};"
        : "+f"(d[0]), "+f"(d[1]), "+f"(d[2]), "+f"(d[3])
        : "r"(a[0]), "r"(a[1]), "r"(a[2]), "r"(a[3]), "r"(b[0]), "r"(b[1]));
}
__device__ __forceinline__ void mma_f16(float* d, const uint32_t* a, const uint32_t* b) {
    asm volatile("mma.sync.aligned.m16n8k16.row.col.f32.f16.f16.f32 "
        "{%0,%1,%2,%3}, {%4,%5,%6,%7}, {%8,%9}, {%0,%1,%2,%3};"
        : "+f"(d[0]), "+f"(d[1]), "+f"(d[2]), "+f"(d[3])
        : "r"(a[0]), "r"(a[1]), "r"(a[2]), "r"(a[3]), "r"(b[0]), "r"(b[1]));
}
#define CP_ASYNC16(dst, src) \
    asm volatile("cp.async.cg.shared.global [%0], [%1], 16;" :: "r"(dst), "l"(src) : "memory")
#define CP_COMMIT() asm volatile("cp.async.commit_group;" ::: "memory")
#define CP_WAIT1()  asm volatile("cp.async.wait_group 1;" ::: "memory")
#define CP_WAIT0()  asm volatile("cp.async.wait_group 0;" ::: "memory")

__device__ __forceinline__ void split2(float v0, float v1, uint32_t& h, uint32_t& lo) {
    bf16 h0 = __float2bfloat16_rn(v0), h1 = __float2bfloat16_rn(v1);
    bf16 l0 = __float2bfloat16_rn(v0 - __bfloat162float(h0));
    bf16 l1 = __float2bfloat16_rn(v1 - __bfloat162float(h1));
    __nv_bfloat162 hp = __halves2bfloat162(h0, h1);
    __nv_bfloat162 lp = __halves2bfloat162(l0, l1);
    h = *(uint32_t*)&hp; lo = *(uint32_t*)&lp;
}
__device__ __forceinline__ void split2h(float v0, float v1, uint32_t& h, uint32_t& lo) {
    __half h0 = __float2half_rn(v0), h1 = __float2half_rn(v1);
    __half l0 = __float2half_rn(v0 - __half2float(h0));
    __half l1 = __float2half_rn(v1 - __half2float(h1));
    __half2 hp = __halves2half2(h0, h1);
    __half2 lp = __halves2half2(l0, l1);
    h = *(uint32_t*)&hp; lo = *(uint32_t*)&lp;
}
__device__ __forceinline__ uint32_t pack2h(float v0, float v1) {
    __half2 hp = __halves2half2(__float2half_rn(v0), __float2half_rn(v1));
    return *(uint32_t*)&hp;
}
__device__ __forceinline__ void store_pair_split(bf16* Chi, bf16* Clo, size_t off,
                                                 float v0, float v1) {
    uint32_t h, lo; split2(v0, v1, h, lo);
    *(uint32_t*)(Chi + off) = h;
    *(uint32_t*)(Clo + off) = lo;
}

// shared 64-K-wide 3-term bf16 MMA block (attention path)
__device__ __forceinline__ void mma_block64(float acc[2][8][4],
        uint32_t sAhi, uint32_t sAlo, uint32_t sBhi, uint32_t sBlo,
        int a_row, int a_kb, int b_row, int b_kb) {
#pragma unroll
    for (int ks = 0; ks < 4; ks++) {
        const int koff = ks * 32;
        uint32_t Ah[2][4], Al[2][4], Bh[4][4], Bl[4][4];
#pragma unroll
        for (int mf = 0; mf < 2; mf++) {
            uint32_t ro = SMEM_SWZ((uint32_t)((a_row + mf * 16) * 128 + koff + a_kb));
            ldsm4(Ah[mf], sAhi + ro);
            ldsm4(Al[mf], sAlo + ro);
        }
#pragma unroll
        for (int nf2 = 0; nf2 < 4; nf2++) {
            uint32_t ro = SMEM_SWZ((uint32_t)((b_row + nf2 * 16) * 128 + koff + b_kb));
            ldsm4(Bh[nf2], sBhi + ro);
            ldsm4(Bl[nf2], sBlo + ro);
        }
#pragma unroll
        for (int mf = 0; mf < 2; mf++)
#pragma unroll
            for (int nf = 0; nf < 8; nf++) {
                const int nf2 = nf >> 1, ho = (nf & 1) * 2;
                mma_bf16(acc[mf][nf], Ah[mf], &Bh[nf2][ho]);
                mma_bf16(acc[mf][nf], Ah[mf], &Bl[nf2][ho]);
                mma_bf16(acc[mf][nf], Al[mf], &Bh[nf2][ho]);
            }
    }
}

// 64-K-wide 2-term fp16 MMA block (projection path: A hi-only, B hi+lo)
__device__ __forceinline__ void mma_block64_f16(float acc[2][8][4],
        uint32_t sA, uint32_t sBh, uint32_t sBl,
        int a_row, int a_kb, int b_row, int b_kb) {
#pragma unroll
    for (int ks = 0; ks < 4; ks++) {
        const int koff = ks * 32;
        uint32_t Ah[2][4], Bh[4][4], Bl[4][4];
#pragma unroll
        for (int mf = 0; mf < 2; mf++) {
            uint32_t ro = SMEM_SWZ((uint32_t)((a_row + mf * 16) * 128 + koff + a_kb));
            ldsm4(Ah[mf], sA + ro);
        }
#pragma unroll
        for (int nf2 = 0; nf2 < 4; nf2++) {
            uint32_t ro = SMEM_SWZ((uint32_t)((b_row + nf2 * 16) * 128 + koff + b_kb));
            ldsm4(Bh[nf2], sBh + ro);
            ldsm4(Bl[nf2], sBl + ro);
        }
#pragma unroll
        for (int mf = 0; mf < 2; mf++)
#pragma unroll
            for (int nf = 0; nf < 8; nf++) {
                const int nf2 = nf >> 1, ho = (nf & 1) * 2;
                mma_f16(acc[mf][nf], Ah[mf], &Bh[nf2][ho]);
                mma_f16(acc[mf][nf], Ah[mf], &Bl[nf2][ho]);
            }
    }
}

// ================ merged split conversion ================
__global__ __launch_bounds__(256)
void convert_all(const float* __restrict__ x,  const float* __restrict__ Wq,
                 const float* __restrict__ Wk, const float* __restrict__ Wv,
                 const float* __restrict__ Wo, const float* __restrict__ Wg1,
                 const float* __restrict__ Wg2) {
    int bx = blockIdx.x;
    const float* src; __half *hi, *lo; int lb; int full;
    if      (bx < 4096) { src = x;   hi = g_xh;   lo = nullptr; lb = bx;        full = 0; }
    else if (bx < 5120) { src = Wq;  hi = g_Wqh;  lo = g_Wql;   lb = bx - 4096; full = 1; }
    else if (bx < 6144) { src = Wk;  hi = g_Wkh;  lo = g_Wkl;   lb = bx - 5120; full = 1; }
    else if (bx < 7168) { src = Wv;  hi = g_Wvh;  lo = g_Wvl;   lb = bx - 6144; full = 1; }
    else if (bx < 8192) { src = Wo;  hi = g_Woh;  lo = g_Wol;   lb = bx - 7168; full = 1; }
    else if (bx < 8320) { src = Wg1; hi = g_Wg1h; lo = g_Wg1l;  lb = bx - 8192; full = 1; }
    else                { src = Wg2; hi = g_Wg2h; lo = g_Wg2l;  lb = bx - 8320; full = 1; }
    int i = (lb * 256 + threadIdx.x) * 4;
    float4 v = *(const float4*)(src + i);
    if (!full) {
        uint2 hu; hu.x = pack2h(v.x, v.y); hu.y = pack2h(v.z, v.w);
        *(uint2*)(hi + i) = hu;
    } else {
        uint32_t h0, l0, h1, l1;
        split2h(v.x, v.y, h0, l0);
        split2h(v.z, v.w, h1, l1);
        uint2 hu; hu.x = h0; hu.y = h1;
        uint2 lu; lu.x = l0; lu.y = l1;
        *(uint2*)(hi + i) = hu;
        *(uint2*)(lo + i) = lu;
    }
}

// ============ fp16 2-term cp.async GEMM: C[M,N] = A[M,K] B[N,K]^T ============
// 2 stages x 48KB => 97KB smem, 2 CTAs/SM for cross-CTA latency hiding
#define F16_STG 49152
#define NSTAGE 2
#define GEMM_F16_SMEM (NSTAGE*F16_STG + 1024)

__device__ __forceinline__ void issue_stage_f16(uint32_t sa,
        const __half* __restrict__ A, const __half* __restrict__ Bh,
        const __half* __restrict__ Bl,
        int rowA, int rowB, int Kstride, int k0, int tid) {
#pragma unroll
    for (int t = 0; t < 12; t++) {
        const int tile = t >> 2;
        int idx = t * 256 + tid;
        int r = (idx >> 3) & 127;
        int c16 = idx & 7;
        const __half* base = (tile == 0) ? A : (tile == 1) ? Bh : Bl;
        int rowg = ((tile == 0) ? rowA : rowB) + r;
        const void* src = base + (size_t)rowg * Kstride + k0 + c16 * 8;
        uint32_t dst = sa + tile * 16384 + SMEM_SWZ((uint32_t)(r * 128 + c16 * 16));
        CP_ASYNC16(dst, src);
    }
}

__device__ __forceinline__ void gemm_core_f16(
        const __half* __restrict__ A, const __half* __restrict__ Bh,
        const __half* __restrict__ Bl, float* __restrict__ C,
        int N, int Kloop, int Kstride, int rowA, int rowB, int act) {
    extern __shared__ char dynsm[];
    char* tile = (char*)((((uintptr_t)dynsm) + 1023) & ~(uintptr_t)1023);
    const uint32_t sa0 = smem_u32(tile);
    const int tid = threadIdx.x;
    const int wid = tid >> 5, l = tid & 31;
    const int warp_m = wid >> 1, warp_n = wid & 1;

    float acc[2][8][4];
#pragma unroll
    for (int mf = 0; mf < 2; mf++)
#pragma unroll
        for (int nf = 0; nf < 8; nf++)
#pragma unroll
            for (int j = 0; j < 4; j++) acc[mf][nf][j] = 0.f;

    const int a_row = warp_m * 32 + (l & 15);
    const int a_kb  = (l >> 4) * 16;
    const int b_row = warp_n * 64 + (l & 7) + ((l >> 4) & 1) * 8;
    const int b_kb  = ((l >> 3) & 1) * 16;

    const int nk = Kloop >> 6;
#pragma unroll
    for (int s = 0; s < NSTAGE; s++) {
        if (s < nk) issue_stage_f16(sa0 + s * F16_STG, A, Bh, Bl, rowA, rowB, Kstride, s << 6, tid);
        CP_COMMIT();
    }
    int sidx = 0;
    for (int kb = 0; kb < nk; kb++) {
        CP_WAIT1();
        __syncthreads();
        const uint32_t st = sa0 + sidx * F16_STG;
        mma_block64_f16(acc, st, st + 16384, st + 32768, a_row, a_kb, b_row, b_kb);
        __syncthreads();
        if (kb + NSTAGE < nk)
            issue_stage_f16(sa0 + sidx * F16_STG, A, Bh, Bl, rowA, rowB, Kstride, (kb + NSTAGE) << 6, tid);
        CP_COMMIT();
        sidx = (sidx + 1 == NSTAGE) ? 0 : sidx + 1;
    }

#pragma unroll
    for (int mf = 0; mf < 2; mf++)
#pragma unroll
        for (int nf = 0; nf < 8; nf++) {
            int r0 = rowA + warp_m * 32 + mf * 16 + (l >> 2);
            int cc = rowB + warp_n * 64 + nf * 8 + (l & 3) * 2;
            float v0 = acc[mf][nf][0], v1 = acc[mf][nf][1];
            float v2 = acc[mf][nf][2], v3 = acc[mf][nf][3];
            if (act) {
                v0 = v0 / (1.f + expf(-v0));
                v1 = v1 / (1.f + expf(-v1));
                v2 = v2 / (1.f + expf(-v2));
                v3 = v3 / (1.f + expf(-v3));
            }
            *(float2*)(C + (size_t)r0 * N + cc)       = make_float2(v0, v1);
            *(float2*)(C + (size_t)(r0 + 8) * N + cc) = make_float2(v2, v3);
        }
}

template<int ACT>
__global__ __launch_bounds__(256, 2)
void gemm_f16(const __half* A, const __half* Bh, const __half* Bl,
              float* C, int N, int K) {
    gemm_core_f16(A, Bh, Bl, C, N, K, K, blockIdx.y * 128, blockIdx.x * 128, ACT);
}

// fused Q/K/V projection: grid (24, 32); which = bx>>3
__global__ __launch_bounds__(256, 2)
void gemm_qkv_f16() {
    const int which = blockIdx.x >> 3;
    const int colb = blockIdx.x & 7;
    const __half *Bh, *Bl;
    float* C;
    if (which == 0)      { Bh = g_Wqh; Bl = g_Wql; C = g_Q; }
    else if (which == 1) { Bh = g_Wkh; Bl = g_Wkl; C = g_EK; }
    else                 { Bh = g_Wvh; Bl = g_Wvl; C = g_V; }
    gemm_core_f16(g_xh, Bh, Bl, C, HIDN, HIDN, HIDN,
                  blockIdx.y * 128, colb * 128, which == 0);
}

// split-K Wg1: grid (4, 32)
__global__ __launch_bounds__(256, 2)
void gemm_wg1_f16() {
    const int ks = blockIdx.x;
    gemm_core_f16(g_xh + ks * 256, g_Wg1h + ks * 256, g_Wg1l + ks * 256,
                  g_G1part + (size_t)ks * NROWS * 128,
                  128, 256, HIDN, blockIdx.y * 128, 0, 0);
}

__global__ __launch_bounds__(256)
void g1_reduce() {
    int i = (blockIdx.x * 256 + threadIdx.x) * 4;   // over NROWS*128
    const int S = NROWS * 128;
    float4 a = *(float4*)(g_G1part + i);
    float4 b = *(float4*)(g_G1part + S + i);
    float4 c = *(float4*)(g_G1part + 2*S + i);
    float4 d = *(float4*)(g_G1part + 3*S + i);
    uint2 hu;
    hu.x = pack2h(a.x + b.x + c.x + d.x, a.y + b.y + c.y + d.y);
    hu.y = pack2h(a.z + b.z + c.z + d.z, a.w + b.w + c.w + d.w);
    *(uint2*)(g_G1h + i) = hu;
}

// ================ transpose V -> split bf16 VT[bh][dv][t] ================
__global__ __launch_bounds__(256)
void transpose_v() {
    __shared__ float tile[32][33];
    const int ttile = blockIdx.x;            // 0..63
    const int dvt = blockIdx.y & 3, bh = blockIdx.y >> 2;
    const int b = bh >> 3, h = bh & 7;
    const int t0 = ttile * 32, dv0 = dvt * 32;
    const int lx = threadIdx.x & 31, ly = threadIdx.x >> 5;
#pragma unroll
    for (int i = 0; i < 4; i++) {
        int r = ly + i * 8;
        tile[r][lx] = g_V[(size_t)(b * TT + t0 + r) * HIDN + h * DKK + dv0 + lx];
    }
    __syncthreads();
#pragma unroll
    for (int i = 0; i < 4; i++) {
        int r = ly + i * 8;
        float v = tile[lx][r];
        bf16 hh = __float2bfloat16_rn(v);
        bf16 ll = __float2bfloat16_rn(v - __bfloat162float(hh));
        size_t oa = ((size_t)bh * DKK + dv0 + r) * TT + t0 + lx;
        g_VThi[oa] = hh;
        g_VTlo[oa] = ll;
    }
}

// ================= attention kernels ==================
#define MICRO_FMA(Aptr, Bptr, kk) do {                                    \
    float4 a0 = *(const float4*)&(Aptr)[(kk)*132 + ty*4];                 \
    float4 a1 = *(const float4*)&(Aptr)[(kk)*132 + 64 + ty*4];            \
    float4 b0 = *(const float4*)&(Bptr)[(kk)*132 + tx*4];                 \
    float4 b1 = *(const float4*)&(Bptr)[(kk)*132 + 64 + tx*4];            \
    float av[8] = {a0.x,a0.y,a0.z,a0.w,a1.x,a1.y,a1.z,a1.w};              \
    float bv[8] = {b0.x,b0.y,b0.z,b0.w,b1.x,b1.y,b1.z,b1.w};              \
    _Pragma("unroll") for (int ii=0; ii<8; ii++)                          \
      _Pragma("unroll") for (int jj=0; jj<8; jj++)                        \
        acc[ii][jj] += av[ii]*bv[jj];                                     \
} while(0)

__device__ __forceinline__ int fragmap(int idx, int t4) {
    return (idx < 4) ? (t4*4 + idx) : (64 + t4*4 + idx - 4);
}

// exp(k) -> split bf16 out, per-chunk colsum, CcT = V^T EK (fp32)
__global__ __launch_bounds__(256)
void chunk_stats() {
    const int c = blockIdx.x, bh = blockIdx.y;
    const int b = bh >> 3, h = bh & 7;
    const int base = b*TT + c*TCH;
    const int hoff = h*DKK;
    __shared__ float EKs[8*132];
    __shared__ float Vs[8*132];
    __shared__ float red[8*128];
    const int tid = threadIdx.x;
    const int tx = tid & 15, ty = tid >> 4;
    const int trow = tid >> 5;
    const int col = (tid & 31) << 2;
    float acc[8][8];
#pragma unroll
    for (int i = 0; i < 8; i++)
#pragma unroll
        for (int j = 0; j < 8; j++) acc[i][j] = 0.f;
    float ps0 = 0.f, ps1 = 0.f, ps2 = 0.f, ps3 = 0.f;

    for (int tt = 0; tt < TCH/8; tt++) {
        int row = base + tt*8 + trow;
        size_t gi = (size_t)row*HIDN + hoff + col;
        float4 kv = *(const float4*)(g_EK + gi);
        kv.x = expf(kv.x); kv.y = expf(kv.y); kv.z = expf(kv.z); kv.w = expf(kv.w);
        uint32_t h0, l0, h1, l1;
        split2(kv.x, kv.y, h0, l0);
        split2(kv.z, kv.w, h1, l1);
        uint2 hu; hu.x = h0; hu.y = h1;
        uint2 lu; lu.x = l0; lu.y = l1;
        *(uint2*)(g_EKhi + gi) = hu;
        *(uint2*)(g_EKlo + gi) = lu;
        ps0 += kv.x; ps1 += kv.y; ps2 += kv.z; ps3 += kv.w;
        *(float4*)&EKs[trow*132 + col] = kv;
        float4 vv = *(const float4*)(g_V + gi);
        *(float4*)&Vs[trow*132 + col] = vv;
        __syncthreads();
#pragma unroll
        for (int k = 0; k < 8; k++) MICRO_FMA(Vs, EKs, k);   // acc[dv][dk] = CcT
        __syncthreads();
    }
    red[trow*128 + col + 0] = ps0; red[trow*128 + col + 1] = ps1;
    red[trow*128 + col + 2] = ps2; red[trow*128 + col + 3] = ps3;
    __syncthreads();
    if (tid < DKK) {
        float s = 0.f;
#pragma unroll
        for (int r = 0; r < 8; r++) s += red[r*128 + tid];
        g_Asum[(bh*NCHUNK + c)*DKK + tid] = s;
    }
    size_t cb = ((size_t)(bh*NCHUNK + c))*DKK*DKK;
#pragma unroll
    for (int i = 0; i < 8; i++) {
        int dv = fragmap(i, ty);
        float4 s0 = make_float4(acc[i][0], acc[i][1], acc[i][2], acc[i][3]);
        float4 s1 = make_float4(acc[i][4], acc[i][5], acc[i][6], acc[i][7]);
        *(float4*)(g_CcT + cb + (size_t)dv*DKK + tx*4)      = s0;
        *(float4*)(g_CcT + cb + (size_t)dv*DKK + 64 + tx*4) = s1;
    }
}

// exclusive prefix of Asum across chunks (loads hoisted -> MLP 16)
__global__ void scan_asum() {
    int bh = blockIdx.x, dk = threadIdx.x;
    float v[NCHUNK];
#pragma unroll
    for (int c = 0; c < NCHUNK; c++)
        v[c] = g_Asum[(bh*NCHUNK + c)*DKK + dk];
    float run = 0.f;
#pragma unroll
    for (int c = 0; c < NCHUNK; c++) {
        g_Asum[(bh*NCHUNK + c)*DKK + dk] = run;
        run += v[c];
    }
}
// exclusive prefix of CcT across chunks -> split bf16 (loads hoisted -> MLP 16)
__global__ void scan_cc() {
    int bh = blockIdx.y;
    int idx = blockIdx.x*256 + threadIdx.x;
    size_t base = (size_t)bh*NCHUNK*(DKK*DKK) + idx;
    float v[NCHUNK];
#pragma unroll
    for (int c = 0; c < NCHUNK; c++)
        v[c] = g_CcT[base + (size_t)c*(DKK*DKK)];
    float run = 0.f;
#pragma unroll
    for (int c = 0; c < NCHUNK; c++) {
        size_t p = base + (size_t)c*(DKK*DKK);
        bf16 hh = __float2bfloat16_rn(run);
        bf16 ll = __float2bfloat16_rn(run - __bfloat162float(hh));
        g_CcThi[p] = hh; g_CcTlo[p] = ll;
        run += v[c];
    }
}

// Qhat = silu(q)/A_t * scale -> split bf16 (8-deep prefetched; EK from hi+lo)
__global__ void compute_qhat() {
    const int c = blockIdx.x, bh = blockIdx.y;
    const int b = bh >> 3, h = bh & 7;
    const int base = b*TT + c*TCH;
    const int dk = threadIdx.x;
    const float scale = 0.08838834764831845f;
    float run = g_Asum[(bh*NCHUNK + c)*DKK + dk];
    const size_t g0 = (size_t)base*HIDN + h*DKK + dk;
    for (int tb = 0; tb < TCH; tb += 8) {
        float ek[8], qq[8];
#pragma unroll
        for (int i = 0; i < 8; i++) {
            size_t gi = g0 + (size_t)(tb + i)*HIDN;
            ek[i] = __bfloat162float(g_EKhi[gi]) + __bfloat162float(g_EKlo[gi]);
            qq[i] = g_Q[gi];
        }
#pragma unroll
        for (int i = 0; i < 8; i++) {
            run += ek[i];
            float qh = qq[i] / run * scale;
            size_t gi = g0 + (size_t)(tb + i)*HIDN;
            bf16 hh = __float2bfloat16_rn(qh);
            bf16 ll = __float2bfloat16_rn(qh - __bfloat162float(hh));
            g_QHhi[gi] = hh; g_QHlo[gi] = ll;
        }
    }
}

// generic 128x128 operand loader into hi/lo smem (two 16KB K-halves each)
__device__ __forceinline__ void load_op(uint32_t shi, uint32_t slo,
        const bf16* __restrict__ ghi, const bf16* __restrict__ glo,
        size_t rstride, int tid) {
#pragma unroll
    for (int t = 0; t < 8; t++) {
        int idx = t * 256 + tid;
        int r = idx >> 4;
        int c16 = idx & 15;
        uint32_t off = (uint32_t)((c16 >> 3) * 16384) + SMEM_SWZ((uint32_t)(r * 128 + (c16 & 7) * 16));
        CP_ASYNC16(shi + off, ghi + (size_t)r * rstride + c16 * 8);
        CP_ASYNC16(slo + off, glo + (size_t)r * rstride + c16 * 8);
    }
}

// ====== chunk_out (tensor core): O = tril(QH EK^T) V + QH Cc ======
#define CO2_SMEM (6*32768 + 1024)
__global__ __launch_bounds__(256, 1)
void chunk_out_tc() {
    extern __shared__ char dynsm[];
    char* smb = (char*)((((uintptr_t)dynsm) + 1023) & ~(uintptr_t)1023);
    const uint32_t sa = smem_u32(smb);
    const int c = blockIdx.x, bh = blockIdx.y;
    const int b = bh >> 3, h = bh & 7;
    const int tbase = b*TT + c*TCH;
    const int hoff = h*DKK;
    const int tid = threadIdx.x, wid = tid >> 5, l = tid & 31;
    const int warp_m = wid >> 1, warp_n = wid & 1;
    const int a_row = warp_m * 32 + (l & 15);
    const int a_kb  = (l >> 4) * 16;
    const int b_row = warp_n * 64 + (l & 7) + ((l >> 4) & 1) * 8;
    const int b_kb  = ((l >> 3) & 1) * 16;

    const uint32_t QHI = sa, QLO = sa + 32768;
    const uint32_t BHI = sa + 65536, BLO = sa + 98304;
    const uint32_t PHI = sa + 131072, PLO = sa + 163840;
    char* Pc_hi = smb + 131072;
    char* Pc_lo = smb + 163840;

    load_op(QHI, QLO, g_QHhi + (size_t)tbase*HIDN + hoff, g_QHlo + (size_t)tbase*HIDN + hoff, HIDN, tid);
    load_op(BHI, BLO, g_EKhi + (size_t)tbase*HIDN + hoff, g_EKlo + (size_t)tbase*HIDN + hoff, HIDN, tid);
    CP_COMMIT(); CP_WAIT0(); __syncthreads();

    float acc[2][8][4];
#pragma unroll
    for (int mf = 0; mf < 2; mf++)
#pragma unroll
        for (int nf = 0; nf < 8; nf++)
#pragma unroll
            for (int j = 0; j < 4; j++) acc[mf][nf][j] = 0.f;

    // stage 1: P = QH * EK^T
#pragma unroll
    for (int kc = 0; kc < 2; kc++)
        mma_block64(acc, QHI + kc*16384, QLO + kc*16384, BHI + kc*16384, BLO + kc*16384,
                    a_row, a_kb, b_row, b_kb);
    __syncthreads();

    load_op(BHI, BLO, g_CcThi + (size_t)(bh*NCHUNK + c)*(DKK*DKK),
                       g_CcTlo + (size_t)(bh*NCHUNK + c)*(DKK*DKK), DKK, tid);
    CP_COMMIT();

    // causal mask + store P to smem (split bf16)
#pragma unroll
    for (int mf = 0; mf < 2; mf++)
#pragma unroll
        for (int nf = 0; nf < 8; nf++) {
            int r0 = warp_m * 32 + mf * 16 + (l >> 2);
            int cc = warp_n * 64 + nf * 8 + (l & 3) * 2;
            float v0 = (cc     <= r0) ? acc[mf][nf][0] : 0.f;
            float v1 = (cc + 1 <= r0) ? acc[mf][nf][1] : 0.f;
            float v2 = (cc     <= r0 + 8) ? acc[mf][nf][2] : 0.f;
            float v3 = (cc + 1 <= r0 + 8) ? acc[mf][nf][3] : 0.f;
            uint32_t ch = (uint32_t)((cc >> 6) * 16384);
            uint32_t o0 = ch + SMEM_SWZ((uint32_t)(r0 * 128 + (cc & 63) * 2));
            uint32_t o1 = ch + SMEM_SWZ((uint32_t)((r0 + 8) * 128 + (cc & 63) * 2));
            uint32_t hh, ll;
            split2(v0, v1, hh, ll);
            *(uint32_t*)(Pc_hi + o0) = hh; *(uint32_t*)(Pc_lo + o0) = ll;
            split2(v2, v3, hh, ll);
            *(uint32_t*)(Pc_hi + o1) = hh; *(uint32_t*)(Pc_lo + o1) = ll;
        }
    CP_WAIT0(); __syncthreads();

    // stage 2b: O = QH * CcT^T
#pragma unroll
    for (int mf = 0; mf < 2; mf++)
#pragma unroll
        for (int nf = 0; nf < 8; nf++)
#pragma unroll
            for (int j = 0; j < 4; j++) acc[mf][nf][j] = 0.f;
#pragma unroll
    for (int kc = 0; kc < 2; kc++)
        mma_block64(acc, QHI + kc*16384, QLO + kc*16384, BHI + kc*16384, BLO + kc*16384,
                    a_row, a_kb, b_row, b_kb);
    __syncthreads();

    load_op(QHI, QLO, g_VThi + (size_t)bh*DKK*TT + c*TCH,
                       g_VTlo + (size_t)bh*DKK*TT + c*TCH, TT, tid);
    CP_COMMIT(); CP_WAIT0(); __syncthreads();

    // stage 2a: O += P * VT^T
#pragma unroll
    for (int kc = 0; kc < 2; kc++)
        mma_block64(acc, PHI + kc*16384, PLO + kc*16384, QHI + kc*16384, QLO + kc*16384,
                    a_row, a_kb, b_row, b_kb);

#pragma unroll
    for (int mf = 0; mf < 2; mf++)
#pragma unroll
        for (int nf = 0; nf < 8; nf++) {
            int r0 = warp_m * 32 + mf * 16 + (l >> 2);
            int cc = warp_n * 64 + nf * 8 + (l & 3) * 2;
            *(float2*)(g_O + (size_t)(tbase + r0) * HIDN + hoff + cc) =
                make_float2(acc[mf][nf][0], acc[mf][nf][1]);
            *(float2*)(g_O + (size_t)(tbase + r0 + 8) * HIDN + hoff + cc) =
                make_float2(acc[mf][nf][2], acc[mf][nf][3]);
        }
}

// epilogue: RMSNorm(o) * w * gate * sigmoid(gate) -> fp16 U (hi only)
__global__ __launch_bounds__(256)
void epilogue_k(const float* __restrict__ gnw) {
    __shared__ float red[256];
    const int n = blockIdx.x, tid = threadIdx.x;
    float4 ov = *((const float4*)(g_O + (size_t)n*HIDN) + tid);
    float ss = ov.x*ov.x + ov.y*ov.y + ov.z*ov.z + ov.w*ov.w;
    red[tid] = ss;
    __syncthreads();
    for (int s = 128; s > 0; s >>= 1) {
        if (tid < s) red[tid] += red[tid + s];
        __syncthreads();
    }
    float rms = rsqrtf(red[0] * (1.f/HIDN) + 1e-5f);
    float4 gv = *((const float4*)(g_gate + (size_t)n*HIDN) + tid);
    float4 wv = *((const float4*)gnw + tid);
    float4 u;
    u.x = ov.x*rms*wv.x * gv.x / (1.f + expf(-gv.x));
    u.y = ov.y*rms*wv.y * gv.y / (1.f + expf(-gv.y));
    u.z = ov.z*rms*wv.z * gv.z / (1.f + expf(-gv.z));
    u.w = ov.w*rms*wv.w * gv.w / (1.f + expf(-gv.w));
    size_t off = (size_t)n*HIDN + tid*4;
    uint2 hu; hu.x = pack2h(u.x, u.y); hu.y = pack2h(u.z, u.w);
    *(uint2*)(g_Uh + off) = hu;
}

extern "C" void kernel_launch(void* const* d_in, const int* in_sizes, int n_in,
                              void* d_out, int out_size) {
    const float* x   = (const float*)d_in[0];
    const float* Wq  = (const float*)d_in[1];
    const float* Wk  = (const float*)d_in[2];
    const float* Wv  = (const float*)d_in[3];
    const float* Wg1 = (const float*)d_in[4];
    const float* Wg2 = (const float*)d_in[5];
    const float* gnw = (const float*)d_in[6];
    const float* Wo  = (const float*)d_in[7];
    float* out = (float*)d_out;

    __half *woh,*wol,*w2h,*w2l,*g1h,*uh;
    float* gate;
    cudaGetSymbolAddress((void**)&woh, g_Woh); cudaGetSymbolAddress((void**)&wol, g_Wol);
    cudaGetSymbolAddress((void**)&w2h, g_Wg2h); cudaGetSymbolAddress((void**)&w2l, g_Wg2l);
    cudaGetSymbolAddress((void**)&g1h, g_G1h);
    cudaGetSymbolAddress((void**)&uh, g_Uh);
    cudaGetSymbolAddress((void**)&gate, g_gate);

    cudaFuncSetAttribute(gemm_qkv_f16, cudaFuncAttributeMaxDynamicSharedMemorySize, GEMM_F16_SMEM);
    cudaFuncSetAttribute(gemm_wg1_f16, cudaFuncAttributeMaxDynamicSharedMemorySize, GEMM_F16_SMEM);
    cudaFuncSetAttribute(gemm_f16<0>, cudaFuncAttributeMaxDynamicSharedMemorySize, GEMM_F16_SMEM);
    cudaFuncSetAttribute(chunk_out_tc, cudaFuncAttributeMaxDynamicSharedMemorySize, CO2_SMEM);

    dim3 blk(256);
    convert_all<<<8448, blk>>>(x, Wq, Wk, Wv, Wo, Wg1, Wg2);
    gemm_qkv_f16<<<dim3(24,32), blk, GEMM_F16_SMEM>>>();
    gemm_wg1_f16<<<dim3(4,32), blk, GEMM_F16_SMEM>>>();
    g1_reduce<<<NROWS*128/1024, blk>>>();
    gemm_f16<0><<<dim3(8,32), blk, GEMM_F16_SMEM>>>(g1h, w2h, w2l, gate, HIDN, 128);
    chunk_stats<<<dim3(NCHUNK, NBH), blk>>>();
    scan_asum<<<NBH, DKK>>>();
    scan_cc<<<dim3(64, NBH), 256>>>();
    transpose_v<<<dim3(64, 4*NBH), blk>>>();
    compute_qhat<<<dim3(NCHUNK, NBH), DKK>>>();
    chunk_out_tc<<<dim3(NCHUNK, NBH), blk, CO2_SMEM>>>();
    epilogue_k<<<NROWS, blk>>>(gnw);
    gemm_f16<0><<<dim3(8,32), blk, GEMM_F16_SMEM>>>(uh, woh, wol, out, HIDN, HIDN);
}

// round 17
// speedup vs baseline: 2.1087x; 1.0252x over previous
#include <cuda_runtime.h>
#include <cuda_bf16.h>
#include <cuda_fp16.h>
#include <cstdint>
#include <math.h>

// Problem dims
#define BB 2
#define TT 2048
#define HIDN 1024
#define NH 8
#define DKK 128
#define NROWS (BB*TT)      // 4096
#define TCH 128
#define NCHUNK (TT/TCH)    // 16
#define NBH (BB*NH)        // 16

#define SMEM_SWZ(off) ((off) ^ (((off) >> 3) & 0x70))
typedef __nv_bfloat16 bf16;

// -------- fp32 scratch --------
__device__ float g_Q[NROWS*HIDN];
__device__ float g_EK[NROWS*HIDN];     // raw k (projection output)
__device__ float g_V[NROWS*HIDN];
__device__ float g_gate[NROWS*HIDN];
__device__ float g_O[NROWS*HIDN];
__device__ float g_Asum[NBH*NCHUNK*DKK];
__device__ float g_CcT[NBH*NCHUNK*DKK*DKK];   // per-chunk (V^T EK) = Cc^T [dv][dk]
__device__ float g_G1part[4*NROWS*128];       // split-K partials for Wg1
// -------- fp16 scratch (projection path, 2-term split) --------
__device__ __half g_xh[NROWS*HIDN];
__device__ __half g_Wqh[HIDN*HIDN],  g_Wql[HIDN*HIDN];
__device__ __half g_Wkh[HIDN*HIDN],  g_Wkl[HIDN*HIDN];
__device__ __half g_Wvh[HIDN*HIDN],  g_Wvl[HIDN*HIDN];
__device__ __half g_Woh[HIDN*HIDN],  g_Wol[HIDN*HIDN];
__device__ __half g_Wg1h[128*HIDN],  g_Wg1l[128*HIDN];
__device__ __half g_Wg2h[HIDN*128],  g_Wg2l[HIDN*128];
__device__ __half g_G1h[NROWS*128];
__device__ __half g_Uh[NROWS*HIDN];
// -------- split-bf16 scratch (attention path, 3-term split) --------
__device__ bf16 g_EKhi[NROWS*HIDN], g_EKlo[NROWS*HIDN];   // exp(k), natural [t, dk]
__device__ bf16 g_QHhi[NROWS*HIDN], g_QHlo[NROWS*HIDN];   // qhat, natural [t, dk]
__device__ bf16 g_VThi[NBH*DKK*TT], g_VTlo[NBH*DKK*TT];   // [bh][dv][t]
__device__ bf16 g_EKThi[NBH*DKK*TT], g_EKTlo[NBH*DKK*TT]; // [bh][dk][t]
__device__ bf16 g_CcThi[NBH*NCHUNK*DKK*DKK], g_CcTlo[NBH*NCHUNK*DKK*DKK]; // excl prefix

// ================= helpers =================
__device__ __forceinline__ uint32_t smem_u32(const void* p) {
    uint32_t a;
    asm("{ .reg .u64 t; cvta.to.shared.u64 t, %1; cvt.u32.u64 %0, t; }" : "=r"(a) : "l"(p));
    return a;
}
__device__ __forceinline__ void ldsm4(uint32_t* r, uint32_t addr) {
    asm volatile("ldmatrix.sync.aligned.m8n8.x4.shared.b16 {%0,%1,%2,%3}, [%4];"
        : "=r"(r[0]), "=r"(r[1]), "=r"(r[2]), "=r"(r[3]) : "r"(addr));
}
__device__ __forceinline__ void mma_bf16(float* d, const uint32_t* a, const uint32_t* b) {
    asm volatile("mma.sync.aligned.m16n8k16.row.col.f32.bf16.bf16.f32 "
        "{%0,%1,%2,%3}, {%4,%5,%6,%7}, {%8,%9}, {%0,%1,%2,%3};"
        : "+f"(d[0]), "+f"(d[1]), "+f"(d[2]), "+f"(d[3])
        : "r"(a[0]), "r"(a[1]), "r"(a[2]), "r"(a[3]), "r"(b[0]), "r"(b[1]));
}
__device__ __forceinline__ void mma_f16(float* d, const uint32_t* a, const uint32_t* b) {
    asm volatile("mma.sync.aligned.m16n8k16.row.col.f32.f16.f16.f32 "
        "{%0,%1,%2,%3}, {%4,%5,%6,%7}, {%8,%9}, {%0,%1,%2,%3};"
        : "+f"(d[0]), "+f"(d[1]), "+f"(d[2]), "+f"(d[3])
        : "r"(a[0]), "r"(a[1]), "r"(a[2]), "r"(a[3]), "r"(b[0]), "r"(b[1]));
}
#define CP_ASYNC16(dst, src) \
    asm volatile("cp.async.cg.shared.global [%0], [%1], 16;" :: "r"(dst), "l"(src) : "memory")
#define CP_COMMIT() asm volatile("cp.async.commit_group;" ::: "memory")
#define CP_WAIT1()  asm volatile("cp.async.wait_group 1;" ::: "memory")
#define CP_WAIT0()  asm volatile("cp.async.wait_group 0;" ::: "memory")

__device__ __forceinline__ void split2(float v0, float v1, uint32_t& h, uint32_t& lo) {
    bf16 h0 = __float2bfloat16_rn(v0), h1 = __float2bfloat16_rn(v1);
    bf16 l0 = __float2bfloat16_rn(v0 - __bfloat162float(h0));
    bf16 l1 = __float2bfloat16_rn(v1 - __bfloat162float(h1));
    __nv_bfloat162 hp = __halves2bfloat162(h0, h1);
    __nv_bfloat162 lp = __halves2bfloat162(l0, l1);
    h = *(uint32_t*)&hp; lo = *(uint32_t*)&lp;
}
__device__ __forceinline__ void split2h(float v0, float v1, uint32_t& h, uint32_t& lo) {
    __half h0 = __float2half_rn(v0), h1 = __float2half_rn(v1);
    __half l0 = __float2half_rn(v0 - __half2float(h0));
    __half l1 = __float2half_rn(v1 - __half2float(h1));
    __half2 hp = __halves2half2(h0, h1);
    __half2 lp = __halves2half2(l0, l1);
    h = *(uint32_t*)&hp; lo = *(uint32_t*)&lp;
}
__device__ __forceinline__ uint32_t pack2h(float v0, float v1) {
    __half2 hp = __halves2half2(__float2half_rn(v0), __float2half_rn(v1));
    return *(uint32_t*)&hp;
}
__device__ __forceinline__ void store_pair_split(bf16* Chi, bf16* Clo, size_t off,
                                                 float v0, float v1) {
    uint32_t h, lo; split2(v0, v1, h, lo);
    *(uint32_t*)(Chi + off) = h;
    *(uint32_t*)(Clo + off) = lo;
}

// shared 64-K-wide 3-term bf16 MMA block (attention path)
__device__ __forceinline__ void mma_block64(float acc[2][8][4],
        uint32_t sAhi, uint32_t sAlo, uint32_t sBhi, uint32_t sBlo,
        int a_row, int a_kb, int b_row, int b_kb) {
#pragma unroll
    for (int ks = 0; ks < 4; ks++) {
        const int koff = ks * 32;
        uint32_t Ah[2][4], Al[2][4], Bh[4][4], Bl[4][4];
#pragma unroll
        for (int mf = 0; mf < 2; mf++) {
            uint32_t ro = SMEM_SWZ((uint32_t)((a_row + mf * 16) * 128 + koff + a_kb));
            ldsm4(Ah[mf], sAhi + ro);
            ldsm4(Al[mf], sAlo + ro);
        }
#pragma unroll
        for (int nf2 = 0; nf2 < 4; nf2++) {
            uint32_t ro = SMEM_SWZ((uint32_t)((b_row + nf2 * 16) * 128 + koff + b_kb));
            ldsm4(Bh[nf2], sBhi + ro);
            ldsm4(Bl[nf2], sBlo + ro);
        }
#pragma unroll
        for (int mf = 0; mf < 2; mf++)
#pragma unroll
            for (int nf = 0; nf < 8; nf++) {
                const int nf2 = nf >> 1, ho = (nf & 1) * 2;
                mma_bf16(acc[mf][nf], Ah[mf], &Bh[nf2][ho]);
                mma_bf16(acc[mf][nf], Ah[mf], &Bl[nf2][ho]);
                mma_bf16(acc[mf][nf], Al[mf], &Bh[nf2][ho]);
            }
    }
}

// 64-K-wide 2-term fp16 MMA block (projection path: A hi-only, B hi+lo)
__device__ __forceinline__ void mma_block64_f16(float acc[2][8][4],
        uint32_t sA, uint32_t sBh, uint32_t sBl,
        int a_row, int a_kb, int b_row, int b_kb) {
#pragma unroll
    for (int ks = 0; ks < 4; ks++) {
        const int koff = ks * 32;
        uint32_t Ah[2][4], Bh[4][4], Bl[4][4];
#pragma unroll
        for (int mf = 0; mf < 2; mf++) {
            uint32_t ro = SMEM_SWZ((uint32_t)((a_row + mf * 16) * 128 + koff + a_kb));
            ldsm4(Ah[mf], sA + ro);
        }
#pragma unroll
        for (int nf2 = 0; nf2 < 4; nf2++) {
            uint32_t ro = SMEM_SWZ((uint32_t)((b_row + nf2 * 16) * 128 + koff + b_kb));
            ldsm4(Bh[nf2], sBh + ro);
            ldsm4(Bl[nf2], sBl + ro);
        }
#pragma unroll
        for (int mf = 0; mf < 2; mf++)
#pragma unroll
            for (int nf = 0; nf < 8; nf++) {
                const int nf2 = nf >> 1, ho = (nf & 1) * 2;
                mma_f16(acc[mf][nf], Ah[mf], &Bh[nf2][ho]);
                mma_f16(acc[mf][nf], Ah[mf], &Bl[nf2][ho]);
            }
    }
}

// ================ split conversions (3 kernels for ncu positioning) ================
__global__ __launch_bounds__(256)
void convert_x(const float* __restrict__ x) {
    int i = (blockIdx.x * 256 + threadIdx.x) * 4;
    float4 v = *(const float4*)(x + i);
    uint2 hu; hu.x = pack2h(v.x, v.y); hu.y = pack2h(v.z, v.w);
    *(uint2*)(g_xh + i) = hu;
}
__device__ __forceinline__ void conv_full(const float* src, __half* hi, __half* lo, int i) {
    float4 v = *(const float4*)(src + i);
    uint32_t h0, l0, h1, l1;
    split2h(v.x, v.y, h0, l0);
    split2h(v.z, v.w, h1, l1);
    uint2 hu; hu.x = h0; hu.y = h1;
    uint2 lu; lu.x = l0; lu.y = l1;
    *(uint2*)(hi + i) = hu;
    *(uint2*)(lo + i) = lu;
}
__global__ __launch_bounds__(256)
void convert_wqkv(const float* __restrict__ Wq, const float* __restrict__ Wk,
                  const float* __restrict__ Wv) {
    int bx = blockIdx.x;   // 3*1024
    const float* src; __half *hi, *lo; int lb;
    if      (bx < 1024) { src = Wq; hi = g_Wqh; lo = g_Wql; lb = bx; }
    else if (bx < 2048) { src = Wk; hi = g_Wkh; lo = g_Wkl; lb = bx - 1024; }
    else                { src = Wv; hi = g_Wvh; lo = g_Wvl; lb = bx - 2048; }
    conv_full(src, hi, lo, (lb * 256 + threadIdx.x) * 4);
}
__global__ __launch_bounds__(256)
void convert_rest(const float* __restrict__ Wo, const float* __restrict__ Wg1,
                  const float* __restrict__ Wg2) {
    int bx = blockIdx.x;   // 1024 + 128 + 128
    const float* src; __half *hi, *lo; int lb;
    if      (bx < 1024) { src = Wo;  hi = g_Woh;  lo = g_Wol;  lb = bx; }
    else if (bx < 1152) { src = Wg1; hi = g_Wg1h; lo = g_Wg1l; lb = bx - 1024; }
    else                { src = Wg2; hi = g_Wg2h; lo = g_Wg2l; lb = bx - 1152; }
    conv_full(src, hi, lo, (lb * 256 + threadIdx.x) * 4);
}

// ============ fp16 2-term cp.async GEMM: C[M,N] = A[M,K] B[N,K]^T ============
#define F16_STG 49152
#define NSTAGE 2
#define GEMM_F16_SMEM (NSTAGE*F16_STG + 1024)

__device__ __forceinline__ void issue_stage_f16(uint32_t sa,
        const __half* __restrict__ A, const __half* __restrict__ Bh,
        const __half* __restrict__ Bl,
        int rowA, int rowB, int Kstride, int k0, int tid) {
#pragma unroll
    for (int t = 0; t < 12; t++) {
        const int tile = t >> 2;
        int idx = t * 256 + tid;
        int r = (idx >> 3) & 127;
        int c16 = idx & 7;
        const __half* base = (tile == 0) ? A : (tile == 1) ? Bh : Bl;
        int rowg = ((tile == 0) ? rowA : rowB) + r;
        const void* src = base + (size_t)rowg * Kstride + k0 + c16 * 8;
        uint32_t dst = sa + tile * 16384 + SMEM_SWZ((uint32_t)(r * 128 + c16 * 16));
        CP_ASYNC16(dst, src);
    }
}

__device__ __forceinline__ void gemm_core_f16(
        const __half* __restrict__ A, const __half* __restrict__ Bh,
        const __half* __restrict__ Bl, float* __restrict__ C,
        int N, int Kloop, int Kstride, int rowA, int rowB, int act) {
    extern __shared__ char dynsm[];
    char* tile = (char*)((((uintptr_t)dynsm) + 1023) & ~(uintptr_t)1023);
    const uint32_t sa0 = smem_u32(tile);
    const int tid = threadIdx.x;
    const int wid = tid >> 5, l = tid & 31;
    const int warp_m = wid >> 1, warp_n = wid & 1;

    float acc[2][8][4];
#pragma unroll
    for (int mf = 0; mf < 2; mf++)
#pragma unroll
        for (int nf = 0; nf < 8; nf++)
#pragma unroll
            for (int j = 0; j < 4; j++) acc[mf][nf][j] = 0.f;

    const int a_row = warp_m * 32 + (l & 15);
    const int a_kb  = (l >> 4) * 16;
    const int b_row = warp_n * 64 + (l & 7) + ((l >> 4) & 1) * 8;
    const int b_kb  = ((l >> 3) & 1) * 16;

    const int nk = Kloop >> 6;
#pragma unroll
    for (int s = 0; s < NSTAGE; s++) {
        if (s < nk) issue_stage_f16(sa0 + s * F16_STG, A, Bh, Bl, rowA, rowB, Kstride, s << 6, tid);
        CP_COMMIT();
    }
    int sidx = 0;
    for (int kb = 0; kb < nk; kb++) {
        CP_WAIT1();
        __syncthreads();
        const uint32_t st = sa0 + sidx * F16_STG;
        mma_block64_f16(acc, st, st + 16384, st + 32768, a_row, a_kb, b_row, b_kb);
        __syncthreads();
        if (kb + NSTAGE < nk)
            issue_stage_f16(sa0 + sidx * F16_STG, A, Bh, Bl, rowA, rowB, Kstride, (kb + NSTAGE) << 6, tid);
        CP_COMMIT();
        sidx = (sidx + 1 == NSTAGE) ? 0 : sidx + 1;
    }

#pragma unroll
    for (int mf = 0; mf < 2; mf++)
#pragma unroll
        for (int nf = 0; nf < 8; nf++) {
            int r0 = rowA + warp_m * 32 + mf * 16 + (l >> 2);
            int cc = rowB + warp_n * 64 + nf * 8 + (l & 3) * 2;
            float v0 = acc[mf][nf][0], v1 = acc[mf][nf][1];
            float v2 = acc[mf][nf][2], v3 = acc[mf][nf][3];
            if (act) {
                v0 = v0 / (1.f + expf(-v0));
                v1 = v1 / (1.f + expf(-v1));
                v2 = v2 / (1.f + expf(-v2));
                v3 = v3 / (1.f + expf(-v3));
            }
            *(float2*)(C + (size_t)r0 * N + cc)       = make_float2(v0, v1);
            *(float2*)(C + (size_t)(r0 + 8) * N + cc) = make_float2(v2, v3);
        }
}

template<int ACT>
__global__ __launch_bounds__(256, 2)
void gemm_f16(const __half* A, const __half* Bh, const __half* Bl,
              float* C, int N, int K) {
    gemm_core_f16(A, Bh, Bl, C, N, K, K, blockIdx.y * 128, blockIdx.x * 128, ACT);
}

// fused Q/K/V projection: grid (24, 32); which = bx>>3
__global__ __launch_bounds__(256, 2)
void gemm_qkv_f16() {
    const int which = blockIdx.x >> 3;
    const int colb = blockIdx.x & 7;
    const __half *Bh, *Bl;
    float* C;
    if (which == 0)      { Bh = g_Wqh; Bl = g_Wql; C = g_Q; }
    else if (which == 1) { Bh = g_Wkh; Bl = g_Wkl; C = g_EK; }
    else                 { Bh = g_Wvh; Bl = g_Wvl; C = g_V; }
    gemm_core_f16(g_xh, Bh, Bl, C, HIDN, HIDN, HIDN,
                  blockIdx.y * 128, colb * 128, which == 0);
}

// split-K Wg1: grid (4, 32)
__global__ __launch_bounds__(256, 2)
void gemm_wg1_f16() {
    const int ks = blockIdx.x;
    gemm_core_f16(g_xh + ks * 256, g_Wg1h + ks * 256, g_Wg1l + ks * 256,
                  g_G1part + (size_t)ks * NROWS * 128,
                  128, 256, HIDN, blockIdx.y * 128, 0, 0);
}

__global__ __launch_bounds__(256)
void g1_reduce() {
    int i = (blockIdx.x * 256 + threadIdx.x) * 4;   // over NROWS*128
    const int S = NROWS * 128;
    float4 a = *(float4*)(g_G1part + i);
    float4 b = *(float4*)(g_G1part + S + i);
    float4 c = *(float4*)(g_G1part + 2*S + i);
    float4 d = *(float4*)(g_G1part + 3*S + i);
    uint2 hu;
    hu.x = pack2h(a.x + b.x + c.x + d.x, a.y + b.y + c.y + d.y);
    hu.y = pack2h(a.z + b.z + c.z + d.z, a.w + b.w + c.w + d.w);
    *(uint2*)(g_G1h + i) = hu;
}

// ====== transpose V and EK -> split bf16 [bh][d][t] planes ======
// grid (64, 128): y = sel*64 + (bh*4 + dvt); sel 0 => V, 1 => EK
__global__ __launch_bounds__(256)
void transpose_vek() {
    __shared__ float tile[32][33];
    const int ttile = blockIdx.x;            // 0..63
    const int sel = blockIdx.y >> 6;
    const int local = blockIdx.y & 63;
    const int dvt = local & 3, bh = local >> 2;
    const int b = bh >> 3, h = bh & 7;
    const int t0 = ttile * 32, dv0 = dvt * 32;
    const int lx = threadIdx.x & 31, ly = threadIdx.x >> 5;
#pragma unroll
    for (int i = 0; i < 4; i++) {
        int r = ly + i * 8;
        size_t gi = (size_t)(b * TT + t0 + r) * HIDN + h * DKK + dv0 + lx;
        float v;
        if (sel == 0) v = g_V[gi];
        else          v = __bfloat162float(g_EKhi[gi]) + __bfloat162float(g_EKlo[gi]);
        tile[r][lx] = v;
    }
    __syncthreads();
    bf16* dhi = (sel == 0) ? g_VThi : g_EKThi;
    bf16* dlo = (sel == 0) ? g_VTlo : g_EKTlo;
#pragma unroll
    for (int i = 0; i < 4; i++) {
        int r = ly + i * 8;
        float v = tile[lx][r];
        bf16 hh = __float2bfloat16_rn(v);
        bf16 ll = __float2bfloat16_rn(v - __bfloat162float(hh));
        size_t oa = ((size_t)bh * DKK + dv0 + r) * TT + t0 + lx;
        dhi[oa] = hh;
        dlo[oa] = ll;
    }
}

// ================= attention kernels ==================
// slim chunk_stats: exp(k) -> split bf16 + per-chunk colsum (no FFMA GEMM)
__global__ __launch_bounds__(256)
void chunk_stats() {
    const int c = blockIdx.x, bh = blockIdx.y;
    const int b = bh >> 3, h = bh & 7;
    const int base = b*TT + c*TCH;
    const int hoff = h*DKK;
    __shared__ float red[8*128];
    const int tid = threadIdx.x;
    const int trow = tid >> 5;
    const int col = (tid & 31) << 2;
    float ps0 = 0.f, ps1 = 0.f, ps2 = 0.f, ps3 = 0.f;
#pragma unroll 4
    for (int tt = 0; tt < TCH/8; tt++) {
        int row = base + tt*8 + trow;
        size_t gi = (size_t)row*HIDN + hoff + col;
        float4 kv = *(const float4*)(g_EK + gi);
        kv.x = expf(kv.x); kv.y = expf(kv.y); kv.z = expf(kv.z); kv.w = expf(kv.w);
        uint32_t h0, l0, h1, l1;
        split2(kv.x, kv.y, h0, l0);
        split2(kv.z, kv.w, h1, l1);
        uint2 hu; hu.x = h0; hu.y = h1;
        uint2 lu; lu.x = l0; lu.y = l1;
        *(uint2*)(g_EKhi + gi) = hu;
        *(uint2*)(g_EKlo + gi) = lu;
        ps0 += kv.x; ps1 += kv.y; ps2 += kv.z; ps3 += kv.w;
    }
    red[trow*128 + col + 0] = ps0; red[trow*128 + col + 1] = ps1;
    red[trow*128 + col + 2] = ps2; red[trow*128 + col + 3] = ps3;
    __syncthreads();
    if (tid < DKK) {
        float s = 0.f;
#pragma unroll
        for (int r = 0; r < 8; r++) s += red[r*128 + tid];
        g_Asum[(bh*NCHUNK + c)*DKK + tid] = s;
    }
}

// generic 128x128 operand loader into hi/lo smem (two 16KB K-halves each)
__device__ __forceinline__ void load_op(uint32_t shi, uint32_t slo,
        const bf16* __restrict__ ghi, const bf16* __restrict__ glo,
        size_t rstride, int tid) {
#pragma unroll
    for (int t = 0; t < 8; t++) {
        int idx = t * 256 + tid;
        int r = idx >> 4;
        int c16 = idx & 15;
        uint32_t off = (uint32_t)((c16 >> 3) * 16384) + SMEM_SWZ((uint32_t)(r * 128 + (c16 & 7) * 16));
        CP_ASYNC16(shi + off, ghi + (size_t)r * rstride + c16 * 8);
        CP_ASYNC16(slo + off, glo + (size_t)r * rstride + c16 * 8);
    }
}

// ====== chunk_cct_tc: CcT[dv][dk] = sum_t VT[dv,t] * EKT[dk,t] (fp32 out) ======
#define CCT_SMEM (4*32768 + 1024)
__global__ __launch_bounds__(256, 1)
void chunk_cct_tc() {
    extern __shared__ char dynsm[];
    char* smb = (char*)((((uintptr_t)dynsm) + 1023) & ~(uintptr_t)1023);
    const uint32_t sa = smem_u32(smb);
    const int c = blockIdx.x, bh = blockIdx.y;
    const int tid = threadIdx.x, wid = tid >> 5, l = tid & 31;
    const int warp_m = wid >> 1, warp_n = wid & 1;
    const int a_row = warp_m * 32 + (l & 15);
    const int a_kb  = (l >> 4) * 16;
    const int b_row = warp_n * 64 + (l & 7) + ((l >> 4) & 1) * 8;
    const int b_kb  = ((l >> 3) & 1) * 16;
    const uint32_t AHI = sa, ALO = sa + 32768, BHI = sa + 65536, BLO = sa + 98304;

    size_t vb = (size_t)bh * DKK * TT + c * TCH;
    load_op(AHI, ALO, g_VThi + vb, g_VTlo + vb, TT, tid);
    load_op(BHI, BLO, g_EKThi + vb, g_EKTlo + vb, TT, tid);
    CP_COMMIT(); CP_WAIT0(); __syncthreads();

    float acc[2][8][4];
#pragma unroll
    for (int mf = 0; mf < 2; mf++)
#pragma unroll
        for (int nf = 0; nf < 8; nf++)
#pragma unroll
            for (int j = 0; j < 4; j++) acc[mf][nf][j] = 0.f;
#pragma unroll
    for (int kc = 0; kc < 2; kc++)
        mma_block64(acc, AHI + kc*16384, ALO + kc*16384, BHI + kc*16384, BLO + kc*16384,
                    a_row, a_kb, b_row, b_kb);

    size_t cb = (size_t)(bh*NCHUNK + c) * DKK * DKK;
#pragma unroll
    for (int mf = 0; mf < 2; mf++)
#pragma unroll
        for (int nf = 0; nf < 8; nf++) {
            int r0 = warp_m * 32 + mf * 16 + (l >> 2);
            int cc = warp_n * 64 + nf * 8 + (l & 3) * 2;
            *(float2*)(g_CcT + cb + (size_t)r0 * DKK + cc) = make_float2(acc[mf][nf][0], acc[mf][nf][1]);
            *(float2*)(g_CcT + cb + (size_t)(r0+8) * DKK + cc) = make_float2(acc[mf][nf][2], acc[mf][nf][3]);
        }
}

// exclusive prefix of Asum across chunks (loads hoisted -> MLP 16)
__global__ void scan_asum() {
    int bh = blockIdx.x, dk = threadIdx.x;
    float v[NCHUNK];
#pragma unroll
    for (int c = 0; c < NCHUNK; c++)
        v[c] = g_Asum[(bh*NCHUNK + c)*DKK + dk];
    float run = 0.f;
#pragma unroll
    for (int c = 0; c < NCHUNK; c++) {
        g_Asum[(bh*NCHUNK + c)*DKK + dk] = run;
        run += v[c];
    }
}
// exclusive prefix of CcT across chunks -> split bf16 (loads hoisted -> MLP 16)
__global__ void scan_cc() {
    int bh = blockIdx.y;
    int idx = blockIdx.x*256 + threadIdx.x;
    size_t base = (size_t)bh*NCHUNK*(DKK*DKK) + idx;
    float v[NCHUNK];
#pragma unroll
    for (int c = 0; c < NCHUNK; c++)
        v[c] = g_CcT[base + (size_t)c*(DKK*DKK)];
    float run = 0.f;
#pragma unroll
    for (int c = 0; c < NCHUNK; c++) {
        size_t p = base + (size_t)c*(DKK*DKK);
        bf16 hh = __float2bfloat16_rn(run);
        bf16 ll = __float2bfloat16_rn(run - __bfloat162float(hh));
        g_CcThi[p] = hh; g_CcTlo[p] = ll;
        run += v[c];
    }
}

// Qhat = silu(q)/A_t * scale -> split bf16 (8-deep prefetched; EK from hi+lo)
__global__ void compute_qhat() {
    const int c = blockIdx.x, bh = blockIdx.y;
    const int b = bh >> 3, h = bh & 7;
    const int base = b*TT + c*TCH;
    const int dk = threadIdx.x;
    const float scale = 0.08838834764831845f;
    float run = g_Asum[(bh*NCHUNK + c)*DKK + dk];
    const size_t g0 = (size_t)base*HIDN + h*DKK + dk;
    for (int tb = 0; tb < TCH; tb += 8) {
        float ek[8], qq[8];
#pragma unroll
        for (int i = 0; i < 8; i++) {
            size_t gi = g0 + (size_t)(tb + i)*HIDN;
            ek[i] = __bfloat162float(g_EKhi[gi]) + __bfloat162float(g_EKlo[gi]);
            qq[i] = g_Q[gi];
        }
#pragma unroll
        for (int i = 0; i < 8; i++) {
            run += ek[i];
            float qh = qq[i] / run * scale;
            size_t gi = g0 + (size_t)(tb + i)*HIDN;
            bf16 hh = __float2bfloat16_rn(qh);
            bf16 ll = __float2bfloat16_rn(qh - __bfloat162float(hh));
            g_QHhi[gi] = hh; g_QHlo[gi] = ll;
        }
    }
}

// ====== chunk_out (tensor core): O = tril(QH EK^T) V + QH Cc ======
#define CO2_SMEM (6*32768 + 1024)
__global__ __launch_bounds__(256, 1)
void chunk_out_tc() {
    extern __shared__ char dynsm[];
    char* smb = (char*)((((uintptr_t)dynsm) + 1023) & ~(uintptr_t)1023);
    const uint32_t sa = smem_u32(smb);
    const int c = blockIdx.x, bh = blockIdx.y;
    const int b = bh >> 3, h = bh & 7;
    const int tbase = b*TT + c*TCH;
    const int hoff = h*DKK;
    const int tid = threadIdx.x, wid = tid >> 5, l = tid & 31;
    const int warp_m = wid >> 1, warp_n = wid & 1;
    const int a_row = warp_m * 32 + (l & 15);
    const int a_kb  = (l >> 4) * 16;
    const int b_row = warp_n * 64 + (l & 7) + ((l >> 4) & 1) * 8;
    const int b_kb  = ((l >> 3) & 1) * 16;

    const uint32_t QHI = sa, QLO = sa + 32768;
    const uint32_t BHI = sa + 65536, BLO = sa + 98304;
    const uint32_t PHI = sa + 131072, PLO = sa + 163840;
    char* Pc_hi = smb + 131072;
    char* Pc_lo = smb + 163840;

    load_op(QHI, QLO, g_QHhi + (size_t)tbase*HIDN + hoff, g_QHlo + (size_t)tbase*HIDN + hoff, HIDN, tid);
    load_op(BHI, BLO, g_EKhi + (size_t)tbase*HIDN + hoff, g_EKlo + (size_t)tbase*HIDN + hoff, HIDN, tid);
    CP_COMMIT(); CP_WAIT0(); __syncthreads();

    float acc[2][8][4];
#pragma unroll
    for (int mf = 0; mf < 2; mf++)
#pragma unroll
        for (int nf = 0; nf < 8; nf++)
#pragma unroll
            for (int j = 0; j < 4; j++) acc[mf][nf][j] = 0.f;

    // stage 1: P = QH * EK^T
#pragma unroll
    for (int kc = 0; kc < 2; kc++)
        mma_block64(acc, QHI + kc*16384, QLO + kc*16384, BHI + kc*16384, BLO + kc*16384,
                    a_row, a_kb, b_row, b_kb);
    __syncthreads();

    load_op(BHI, BLO, g_CcThi + (size_t)(bh*NCHUNK + c)*(DKK*DKK),
                       g_CcTlo + (size_t)(bh*NCHUNK + c)*(DKK*DKK), DKK, tid);
    CP_COMMIT();

    // causal mask + store P to smem (split bf16)
#pragma unroll
    for (int mf = 0; mf < 2; mf++)
#pragma unroll
        for (int nf = 0; nf < 8; nf++) {
            int r0 = warp_m * 32 + mf * 16 + (l >> 2);
            int cc = warp_n * 64 + nf * 8 + (l & 3) * 2;
            float v0 = (cc     <= r0) ? acc[mf][nf][0] : 0.f;
            float v1 = (cc + 1 <= r0) ? acc[mf][nf][1] : 0.f;
            float v2 = (cc     <= r0 + 8) ? acc[mf][nf][2] : 0.f;
            float v3 = (cc + 1 <= r0 + 8) ? acc[mf][nf][3] : 0.f;
            uint32_t ch = (uint32_t)((cc >> 6) * 16384);
            uint32_t o0 = ch + SMEM_SWZ((uint32_t)(r0 * 128 + (cc & 63) * 2));
            uint32_t o1 = ch + SMEM_SWZ((uint32_t)((r0 + 8) * 128 + (cc & 63) * 2));
            uint32_t hh, ll;
            split2(v0, v1, hh, ll);
            *(uint32_t*)(Pc_hi + o0) = hh; *(uint32_t*)(Pc_lo + o0) = ll;
            split2(v2, v3, hh, ll);
            *(uint32_t*)(Pc_hi + o1) = hh; *(uint32_t*)(Pc_lo + o1) = ll;
        }
    CP_WAIT0(); __syncthreads();

    // stage 2b: O = QH * CcT^T
#pragma unroll
    for (int mf = 0; mf < 2; mf++)
#pragma unroll
        for (int nf = 0; nf < 8; nf++)
#pragma unroll
            for (int j = 0; j < 4; j++) acc[mf][nf][j] = 0.f;
#pragma unroll
    for (int kc = 0; kc < 2; kc++)
        mma_block64(acc, QHI + kc*16384, QLO + kc*16384, BHI + kc*16384, BLO + kc*16384,
                    a_row, a_kb, b_row, b_kb);
    __syncthreads();

    load_op(QHI, QLO, g_VThi + (size_t)bh*DKK*TT + c*TCH,
                       g_VTlo + (size_t)bh*DKK*TT + c*TCH, TT, tid);
    CP_COMMIT(); CP_WAIT0(); __syncthreads();

    // stage 2a: O += P * VT^T
#pragma unroll
    for (int kc = 0; kc < 2; kc++)
        mma_block64(acc, PHI + kc*16384, PLO + kc*16384, QHI + kc*16384, QLO + kc*16384,
                    a_row, a_kb, b_row, b_kb);

#pragma unroll
    for (int mf = 0; mf < 2; mf++)
#pragma unroll
        for (int nf = 0; nf < 8; nf++) {
            int r0 = warp_m * 32 + mf * 16 + (l >> 2);
            int cc = warp_n * 64 + nf * 8 + (l & 3) * 2;
            *(float2*)(g_O + (size_t)(tbase + r0) * HIDN + hoff + cc) =
                make_float2(acc[mf][nf][0], acc[mf][nf][1]);
            *(float2*)(g_O + (size_t)(tbase + r0 + 8) * HIDN + hoff + cc) =
                make_float2(acc[mf][nf][2], acc[mf][nf][3]);
        }
}

// epilogue: RMSNorm(o) * w * gate * sigmoid(gate) -> fp16 U (hi only)
__global__ __launch_bounds__(256)
void epilogue_k(const float* __restrict__ gnw) {
    __shared__ float red[256];
    const int n = blockIdx.x, tid = threadIdx.x;
    float4 ov = *((const float4*)(g_O + (size_t)n*HIDN) + tid);
    float ss = ov.x*ov.x + ov.y*ov.y + ov.z*ov.z + ov.w*ov.w;
    red[tid] = ss;
    __syncthreads();
    for (int s = 128; s > 0; s >>= 1) {
        if (tid < s) red[tid] += red[tid + s];
        __syncthreads();
    }
    float rms = rsqrtf(red[0] * (1.f/HIDN) + 1e-5f);
    float4 gv = *((const float4*)(g_gate + (size_t)n*HIDN) + tid);
    float4 wv = *((const float4*)gnw + tid);
    float4 u;
    u.x = ov.x*rms*wv.x * gv.x / (1.f + expf(-gv.x));
    u.y = ov.y*rms*wv.y * gv.y / (1.f + expf(-gv.y));
    u.z = ov.z*rms*wv.z * gv.z / (1.f + expf(-gv.z));
    u.w = ov.w*rms*wv.w * gv.w / (1.f + expf(-gv.w));
    size_t off = (size_t)n*HIDN + tid*4;
    uint2 hu; hu.x = pack2h(u.x, u.y); hu.y = pack2h(u.z, u.w);
    *(uint2*)(g_Uh + off) = hu;
}

extern "C" void kernel_launch(void* const* d_in, const int* in_sizes, int n_in,
                              void* d_out, int out_size) {
    const float* x   = (const float*)d_in[0];
    const float* Wq  = (const float*)d_in[1];
    const float* Wk  = (const float*)d_in[2];
    const float* Wv  = (const float*)d_in[3];
    const float* Wg1 = (const float*)d_in[4];
    const float* Wg2 = (const float*)d_in[5];
    const float* gnw = (const float*)d_in[6];
    const float* Wo  = (const float*)d_in[7];
    float* out = (float*)d_out;

    __half *woh,*wol,*w2h,*w2l,*g1h,*uh;
    float* gate;
    cudaGetSymbolAddress((void**)&woh, g_Woh); cudaGetSymbolAddress((void**)&wol, g_Wol);
    cudaGetSymbolAddress((void**)&w2h, g_Wg2h); cudaGetSymbolAddress((void**)&w2l, g_Wg2l);
    cudaGetSymbolAddress((void**)&g1h, g_G1h);
    cudaGetSymbolAddress((void**)&uh, g_Uh);
    cudaGetSymbolAddress((void**)&gate, g_gate);

    cudaFuncSetAttribute(gemm_qkv_f16, cudaFuncAttributeMaxDynamicSharedMemorySize, GEMM_F16_SMEM);
    cudaFuncSetAttribute(gemm_wg1_f16, cudaFuncAttributeMaxDynamicSharedMemorySize, GEMM_F16_SMEM);
    cudaFuncSetAttribute(gemm_f16<0>, cudaFuncAttributeMaxDynamicSharedMemorySize, GEMM_F16_SMEM);
    cudaFuncSetAttribute(chunk_out_tc, cudaFuncAttributeMaxDynamicSharedMemorySize, CO2_SMEM);
    cudaFuncSetAttribute(chunk_cct_tc, cudaFuncAttributeMaxDynamicSharedMemorySize, CCT_SMEM);

    dim3 blk(256);
    convert_x<<<4096, blk>>>(x);                                              // 1
    convert_wqkv<<<3072, blk>>>(Wq, Wk, Wv);                                  // 2
    convert_rest<<<1280, blk>>>(Wo, Wg1, Wg2);                                // 3
    gemm_qkv_f16<<<dim3(24,32), blk, GEMM_F16_SMEM>>>();                      // 4 <- ncu target
    gemm_wg1_f16<<<dim3(4,32), blk, GEMM_F16_SMEM>>>();                       // 5
    g1_reduce<<<NROWS*128/1024, blk>>>();                                     // 6
    gemm_f16<0><<<dim3(8,32), blk, GEMM_F16_SMEM>>>(g1h, w2h, w2l, gate, HIDN, 128); // 7
    chunk_stats<<<dim3(NCHUNK, NBH), blk>>>();                                // 8
    transpose_vek<<<dim3(64, 128), blk>>>();                                  // 9
    chunk_cct_tc<<<dim3(NCHUNK, NBH), blk, CCT_SMEM>>>();                     // 10
    scan_asum<<<NBH, DKK>>>();                                                // 11
    scan_cc<<<dim3(64, NBH), 256>>>();                                        // 12
    compute_qhat<<<dim3(NCHUNK, NBH), DKK>>>();                               // 13
    chunk_out_tc<<<dim3(NCHUNK, NBH), blk, CO2_SMEM>>>();                     // 14
    epilogue_k<<<NROWS, blk>>>(gnw);                                          // 15
    gemm_f16<0><<<dim3(8,32), blk, GEMM_F16_SMEM>>>(uh, woh, wol, out, HIDN, HIDN); // 16
}